// round 9
// baseline (speedup 1.0000x reference)
#include <cuda_runtime.h>
#include <cuda_bf16.h>
#include <math.h>
#include <cstdint>

#define NN   50000
#define NE   800000
#define IND  128
#define HID  256
#define OUTD 40
#define NB   ((NN + 255) / 256)   // 196 scan blocks

// ---------------- scratch ----------------------------------------------------
__device__ int   g_is64;
__device__ int   g_counts[NN];
__device__ int   g_offsets[NN + 1];
__device__ int   g_cursor[NN];
__device__ int   g_esrc[NE];
__device__ float g_invc[NN];
__device__ int   g_bsum[NB];
__device__ int   g_done1 = 0;
__device__ int   g_done2 = 0;
__device__ __align__(16) __nv_bfloat16 g_w1hi[(size_t)HID * HID]; // W1^T hi [n][k]
__device__ __align__(16) __nv_bfloat16 g_w1lo[(size_t)HID * HID]; // W1^T lo [n][k]
__device__ __align__(16) __nv_bfloat16 g_hhi[(size_t)NN * HID];   // h hi [NN][256]
__device__ __align__(16) __nv_bfloat16 g_hlo[(size_t)NN * HID];   // h lo
__device__ __align__(16) __nv_bfloat16 g_w2hi[(size_t)80 * HID];  // W2^T hi [80][256]
__device__ __align__(16) __nv_bfloat16 g_w2lo[(size_t)80 * HID];  // W2^T lo
__device__ __align__(16) float g_p[(size_t)NN * OUTD];
__device__ __align__(16) float g_r[(size_t)NN * OUTD];

// ---------------- helpers ----------------------------------------------------
__device__ __forceinline__ uint32_t smem_u32(const void* p) {
    uint32_t a;
    asm("{ .reg .u64 t; cvta.to.shared.u64 t, %1; cvt.u32.u64 %0, t; }"
        : "=r"(a) : "l"(p));
    return a;
}

#define SW128(o) ((o) ^ (((o) >> 3) & 0x70))

#define LDSM4(R, ADDR)                                                           \
    asm volatile("ldmatrix.sync.aligned.m8n8.x4.shared.b16 {%0,%1,%2,%3}, [%4];" \
        : "=r"((R)[0]), "=r"((R)[1]), "=r"((R)[2]), "=r"((R)[3]) : "r"(ADDR))

__device__ __forceinline__ void mma16816(float* c, const uint32_t* a,
                                         uint32_t b0, uint32_t b1) {
    asm volatile(
        "mma.sync.aligned.m16n8k16.row.col.f32.bf16.bf16.f32 "
        "{%0,%1,%2,%3}, {%4,%5,%6,%7}, {%8,%9}, {%0,%1,%2,%3};"
        : "+f"(c[0]), "+f"(c[1]), "+f"(c[2]), "+f"(c[3])
        : "r"(a[0]), "r"(a[1]), "r"(a[2]), "r"(a[3]), "r"(b0), "r"(b1));
}

__device__ __forceinline__ void cp_async16(uint32_t dst, const void* src, int srcsz) {
    asm volatile("cp.async.cg.shared.global [%0], [%1], 16, %2;"
                 :: "r"(dst), "l"(src), "r"(srcsz) : "memory");
}
#define CP_COMMIT() asm volatile("cp.async.commit_group;" ::: "memory")
#define CP_WAIT1()  asm volatile("cp.async.wait_group 1;" ::: "memory")
#define CP_WAIT0()  asm volatile("cp.async.wait_group 0;" ::: "memory")

__device__ __forceinline__ int edge_at(const void* ei, int idx) {
    if (g_is64) return (int)((const long long*)ei)[idx];
    return ((const int*)ei)[idx];
}

// ---------------- bf16 split helpers -----------------------------------------
__device__ __forceinline__ void split4(float4 v, uint2& hi, uint2& lo) {
    __nv_bfloat16 h0 = __float2bfloat16(v.x);
    __nv_bfloat16 h1 = __float2bfloat16(v.y);
    __nv_bfloat16 h2 = __float2bfloat16(v.z);
    __nv_bfloat16 h3 = __float2bfloat16(v.w);
    __nv_bfloat16 l0 = __float2bfloat16(v.x - __bfloat162float(h0));
    __nv_bfloat16 l1 = __float2bfloat16(v.y - __bfloat162float(h1));
    __nv_bfloat16 l2 = __float2bfloat16(v.z - __bfloat162float(h2));
    __nv_bfloat16 l3 = __float2bfloat16(v.w - __bfloat162float(h3));
    hi.x = (uint32_t)__bfloat16_as_ushort(h0) | ((uint32_t)__bfloat16_as_ushort(h1) << 16);
    hi.y = (uint32_t)__bfloat16_as_ushort(h2) | ((uint32_t)__bfloat16_as_ushort(h3) << 16);
    lo.x = (uint32_t)__bfloat16_as_ushort(l0) | ((uint32_t)__bfloat16_as_ushort(l1) << 16);
    lo.y = (uint32_t)__bfloat16_as_ushort(l2) | ((uint32_t)__bfloat16_as_ushort(l3) << 16);
}

__device__ __forceinline__ void split2(float x, float y, uint32_t& hi, uint32_t& lo) {
    __nv_bfloat16 hx = __float2bfloat16(x), hy = __float2bfloat16(y);
    __nv_bfloat16 lx = __float2bfloat16(x - __bfloat162float(hx));
    __nv_bfloat16 ly = __float2bfloat16(y - __bfloat162float(hy));
    hi = (uint32_t)__bfloat16_as_ushort(hx) | ((uint32_t)__bfloat16_as_ushort(hy) << 16);
    lo = (uint32_t)__bfloat16_as_ushort(lx) | ((uint32_t)__bfloat16_as_ushort(ly) << 16);
}

// ---------------- k_init: detect (block 0) + zero counts ---------------------
__global__ void k_init(const int* __restrict__ ei32) {
    int b = blockIdx.x;
    int tid = threadIdx.x;
    if (b == 0) {
        __shared__ int bad;
        if (tid == 0) bad = 0;
        __syncthreads();
        if (ei32[2 * tid + 1] != 0) atomicOr(&bad, 1);
        __syncthreads();
        if (tid == 0) g_is64 = bad ? 0 : 1;
    } else {
        int i = (b - 1) * 256 + tid;
        if (i < NN) g_counts[i] = 0;
    }
}

// ---------------- k_count_prep: edge count ∥ W1/W2 bf16-split ----------------
#define CPB_COUNT 3125
#define CPB_W1    (CPB_COUNT + 256)
#define CPB_W2    (CPB_W1 + 80)

__global__ void k_count_prep(const void* __restrict__ ei,
                             const float* __restrict__ W1l, const float* __restrict__ W1r,
                             const float* __restrict__ W2l, const float* __restrict__ W2r) {
    int b = blockIdx.x;
    int tid = threadIdx.x;
    if (b < CPB_COUNT) {
        int e = b * 256 + tid;
        if (e < NE) atomicAdd(&g_counts[edge_at(ei, NE + e)], 1);
    } else if (b < CPB_W1) {
        int idx = (b - CPB_COUNT) * 256 + tid;
        int n = idx >> 8, k = idx & 255;
        float w = (k < 128) ? W1l[(size_t)k * 256 + n]
                            : W1r[(size_t)(k - 128) * 256 + n];
        __nv_bfloat16 h = __float2bfloat16(w);
        __nv_bfloat16 l = __float2bfloat16(w - __bfloat162float(h));
        g_w1hi[(size_t)n * 256 + k] = h;
        g_w1lo[(size_t)n * 256 + k] = l;
    } else {
        int idx = (b - CPB_W1) * 256 + tid;
        int n = idx >> 8, k = idx & 255;
        float w = (n < 40) ? W2l[(size_t)k * 40 + n]
                           : W2r[(size_t)k * 40 + (n - 40)];
        __nv_bfloat16 h = __float2bfloat16(w);
        __nv_bfloat16 l = __float2bfloat16(w - __bfloat162float(h));
        g_w2hi[(size_t)n * 256 + k] = h;
        g_w2lo[(size_t)n * 256 + k] = l;
    }
}

// ---------------- k_scan: fused hierarchical scan ----------------------------
__device__ __forceinline__ int block_excl_scan(int c, int t) {
    int lane = t & 31, w = t >> 5;
    int v = c;
#pragma unroll
    for (int off = 1; off < 32; off <<= 1) {
        int n = __shfl_up_sync(0xffffffffu, v, off);
        if (lane >= off) v += n;
    }
    __shared__ int ws[8];
    if (lane == 31) ws[w] = v;
    __syncthreads();
    if (w == 0 && lane < 8) {
        int s = ws[lane];
#pragma unroll
        for (int off = 1; off < 8; off <<= 1) {
            int n = __shfl_up_sync(0x000000ffu, s, off);
            if (lane >= off) s += n;
        }
        ws[lane] = s;
    }
    __syncthreads();
    return v - c + (w > 0 ? ws[w - 1] : 0);
}

__global__ void k_scan() {
    int b = blockIdx.x, tid = threadIdx.x;
    int i = b * 256 + tid;
    int c = (i < NN) ? g_counts[i] : 0;
    int e = block_excl_scan(c, tid);

    if (tid == 255) {
        g_bsum[b] = e + c;
        __threadfence();
        atomicAdd(&g_done1, 1);
    }
    if (tid == 0) {
        while (*(volatile int*)&g_done1 < NB) {}
    }
    __syncthreads();
    __threadfence();

    int v = (tid < b) ? g_bsum[tid] : 0;
    int lane = tid & 31, w = tid >> 5;
#pragma unroll
    for (int off = 16; off; off >>= 1) v += __shfl_xor_sync(0xffffffffu, v, off);
    __shared__ int rs[8];
    if (lane == 0) rs[w] = v;
    __syncthreads();
    __shared__ int pre;
    if (tid == 0) {
        int s = 0;
#pragma unroll
        for (int k = 0; k < 8; k++) s += rs[k];
        pre = s;
    }
    __syncthreads();

    if (i < NN) {
        int off = pre + e;
        g_offsets[i] = off;
        g_cursor[i]  = off;
        g_invc[i]    = 1.0f / (float)(c > 1 ? c : 1);
    }
    if (b == NB - 1 && tid == 255) g_offsets[NN] = NE;

    if (tid == 0) {
        int t2 = atomicAdd(&g_done2, 1);
        if (t2 == NB - 1) { g_done1 = 0; g_done2 = 0; }
    }
}

__global__ void k_scatter(const void* __restrict__ ei) {
    int e = blockIdx.x * blockDim.x + threadIdx.x;
    if (e < NE) {
        int s = edge_at(ei, e);
        int d = edge_at(ei, NE + e);
        g_esrc[atomicAdd(&g_cursor[d], 1)] = s;
    }
}

// ---------------- FUSED agg1 + GEMM1 -----------------------------------------
// Tile 128 rows x 256 n, 512 threads, grid 391.
// Phase 1: warp-per-row CSR gather -> A=[agg|x] bf16-split in swizzled smem.
// Phase 2: 3-pass mma.sync over 4 K-chunks, B (W1^T) single-buffered.
// smem: A_hi 64KB (4 chunks x 16KB) | A_lo 64KB | B_hi 32KB | B_lo 32KB = 192KB
#define FA_HI 0
#define FA_LO 65536
#define FB_HI 131072
#define FB_LO 163840
#define DYN_SMEMF 196608

__global__ void __launch_bounds__(512, 1) k_fused1(const float* __restrict__ x,
                                                   const float* __restrict__ b1) {
    extern __shared__ char dsm[];
    int tid = threadIdx.x;
    int wid = tid >> 5;          // 0..15
    int lane = tid & 31;
    int bm = blockIdx.x * 128;
    uint32_t dynb = smem_u32(dsm);

    // ---- phase 1: aggregate 8 rows per warp ----
    const float4* __restrict__ x4 = (const float4*)x;
    int k0 = lane * 4;                         // 0..124
    int cA = k0 >> 6;                          // agg chunk 0/1
    int kin = (k0 & 63) * 2;                   // byte offset within chunk row
#pragma unroll 1
    for (int r8 = 0; r8 < 8; r8++) {
        int row = wid * 8 + r8;
        int grow = bm + row;
        float4 acc = make_float4(0.f, 0.f, 0.f, 0.f);
        float4 xv  = make_float4(0.f, 0.f, 0.f, 0.f);
        if (grow < NN) {
            int beg = g_offsets[grow], end = g_offsets[grow + 1];
            int e = beg;
            for (; e + 1 < end; e += 2) {
                int s0 = g_esrc[e];
                int s1 = g_esrc[e + 1];
                float4 v0 = x4[(size_t)s0 * 32 + lane];
                float4 v1 = x4[(size_t)s1 * 32 + lane];
                acc.x += v0.x + v1.x; acc.y += v0.y + v1.y;
                acc.z += v0.z + v1.z; acc.w += v0.w + v1.w;
            }
            if (e < end) {
                float4 v0 = x4[(size_t)g_esrc[e] * 32 + lane];
                acc.x += v0.x; acc.y += v0.y; acc.z += v0.z; acc.w += v0.w;
            }
            float iv = g_invc[grow];
            acc.x *= iv; acc.y *= iv; acc.z *= iv; acc.w *= iv;
            xv = x4[(size_t)grow * 32 + lane];
        }
        uint2 hi, lo;
        split4(acc, hi, lo);
        int soA = cA * 16384 + SW128(row * 128 + kin);
        *(uint2*)(dsm + FA_HI + soA) = hi;
        *(uint2*)(dsm + FA_LO + soA) = lo;
        split4(xv, hi, lo);
        int soX = (2 + cA) * 16384 + SW128(row * 128 + kin);
        *(uint2*)(dsm + FA_HI + soX) = hi;
        *(uint2*)(dsm + FA_LO + soX) = lo;
    }
    __syncthreads();

    // ---- phase 2: GEMM ----
    int warp_m = (wid & 3) * 32;
    int warp_n = (wid >> 2) * 64;

    uint32_t offA[2][4], offB[4][4];
    {
        int mat = lane >> 3, rr = lane & 7;
#pragma unroll
        for (int i = 0; i < 2; i++)
#pragma unroll
            for (int j = 0; j < 4; j++) {
                int row = warp_m + i * 16 + ((mat & 1) << 3) + rr;
                int kb  = j * 16 + ((mat >> 1) << 3);
                offA[i][j] = SW128(row * 128 + kb * 2);
            }
#pragma unroll
        for (int q = 0; q < 4; q++)
#pragma unroll
            for (int j = 0; j < 4; j++) {
                int n  = warp_n + q * 16 + ((mat & 2) << 2) + rr;
                int kb = j * 16 + ((mat & 1) << 3);
                offB[q][j] = SW128(n * 128 + kb * 2);
            }
    }

    float acc[2][8][4];
#pragma unroll
    for (int i = 0; i < 2; i++)
#pragma unroll
        for (int jn = 0; jn < 8; jn++)
#pragma unroll
            for (int t = 0; t < 4; t++) acc[i][jn][t] = 0.f;

    for (int kc = 0; kc < 4; kc++) {
        // stage B chunk (256 n-rows x 64 k): 2048 x 16B segs / 512 thr = 4 iters
#pragma unroll
        for (int it = 0; it < 4; it++) {
            int idx = tid + it * 512;
            int row = idx >> 3, seg = idx & 7;
            size_t boff = ((size_t)row * 256 + kc * 64 + seg * 8) * 2;
            int so = SW128(row * 128 + seg * 16);
            cp_async16(dynb + FB_HI + so, (const char*)g_w1hi + boff, 16);
            cp_async16(dynb + FB_LO + so, (const char*)g_w1lo + boff, 16);
        }
        CP_COMMIT();
        CP_WAIT0();
        __syncthreads();

        uint32_t aoff = kc * 16384;
#pragma unroll
        for (int j = 0; j < 4; j++) {
            uint32_t ah[2][4], al[2][4];
#pragma unroll
            for (int i = 0; i < 2; i++) {
                LDSM4(ah[i], dynb + FA_HI + aoff + offA[i][j]);
                LDSM4(al[i], dynb + FA_LO + aoff + offA[i][j]);
            }
#pragma unroll
            for (int q = 0; q < 4; q++) {
                uint32_t bh[4], bl[4];
                LDSM4(bh, dynb + FB_HI + offB[q][j]);
                LDSM4(bl, dynb + FB_LO + offB[q][j]);
#pragma unroll
                for (int i = 0; i < 2; i++)
#pragma unroll
                    for (int hsel = 0; hsel < 2; hsel++) {
                        int jn = q * 2 + hsel;
                        uint32_t b0 = bh[hsel * 2], b1v = bh[hsel * 2 + 1];
                        uint32_t c0v = bl[hsel * 2], c1v = bl[hsel * 2 + 1];
                        mma16816(acc[i][jn], ah[i], b0, b1v);
                        mma16816(acc[i][jn], ah[i], c0v, c1v);
                        mma16816(acc[i][jn], al[i], b0, b1v);
                    }
            }
        }
        __syncthreads();
    }

    // epilogue: bias + relu -> bf16 hi/lo h
    int r0 = bm + warp_m + (lane >> 2);
    int c0 = warp_n + 2 * (lane & 3);
#pragma unroll
    for (int i = 0; i < 2; i++) {
        int row = r0 + i * 16;
#pragma unroll
        for (int jn = 0; jn < 8; jn++) {
            int col = c0 + jn * 8;
            float bx = b1[col], by = b1[col + 1];
            if (row < NN) {
                float vx = acc[i][jn][0] + bx; vx = vx > 0.f ? vx : 0.f;
                float vy = acc[i][jn][1] + by; vy = vy > 0.f ? vy : 0.f;
                uint32_t hi, lo;
                split2(vx, vy, hi, lo);
                *(uint32_t*)&g_hhi[(size_t)row * 256 + col] = hi;
                *(uint32_t*)&g_hlo[(size_t)row * 256 + col] = lo;
            }
            if (row + 8 < NN) {
                float vx = acc[i][jn][2] + bx; vx = vx > 0.f ? vx : 0.f;
                float vy = acc[i][jn][3] + by; vy = vy > 0.f ? vy : 0.f;
                uint32_t hi, lo;
                split2(vx, vy, hi, lo);
                *(uint32_t*)&g_hhi[(size_t)(row + 8) * 256 + col] = hi;
                *(uint32_t*)&g_hlo[(size_t)(row + 8) * 256 + col] = lo;
            }
        }
    }
}

// ---------------- GEMM2 via mma.sync (cp.async pipe) -------------------------
#define G2A_H 0
#define G2A_L 16384
#define G2B_H 32768
#define G2B_L 43008
#define BUF2 53248
#define DYN_SMEM2 (2 * BUF2)

__global__ void __launch_bounds__(256, 1) k_gemm2_mma(const float* __restrict__ b2) {
    extern __shared__ char dsm[];
    int tid = threadIdx.x;
    int wid = tid >> 5;
    int lane = tid & 31;
    int bm = blockIdx.x * 128;
    uint32_t dynb = smem_u32(dsm);

    int warp_m = wid * 16;

    uint32_t offA[4], offB[5][4];
    {
        int mat = lane >> 3, rr = lane & 7;
#pragma unroll
        for (int j = 0; j < 4; j++) {
            int row = warp_m + ((mat & 1) << 3) + rr;
            int kb  = j * 16 + ((mat >> 1) << 3);
            offA[j] = SW128(row * 128 + kb * 2);
        }
#pragma unroll
        for (int q = 0; q < 5; q++)
#pragma unroll
            for (int j = 0; j < 4; j++) {
                int n  = q * 16 + ((mat & 2) << 2) + rr;
                int kb = j * 16 + ((mat & 1) << 3);
                offB[q][j] = SW128(n * 128 + kb * 2);
            }
    }

    float acc[10][4];
#pragma unroll
    for (int jn = 0; jn < 10; jn++)
#pragma unroll
        for (int t = 0; t < 4; t++) acc[jn][t] = 0.f;

#define STAGE2(K0, BUFO) do {                                                      \
    _Pragma("unroll")                                                              \
    for (int it = 0; it < 4; it++) {                                               \
        int idx = tid + it * 256;                                                  \
        int row = idx >> 3, seg = idx & 7;                                         \
        int grow = bm + row;                                                       \
        int cl = grow < NN ? grow : (NN - 1);                                      \
        int sz = grow < NN ? 16 : 0;                                               \
        size_t boff = ((size_t)cl * 256 + (K0) + seg * 8) * 2;                     \
        int so = SW128(row * 128 + seg * 16);                                      \
        cp_async16(dynb + (BUFO) + G2A_H + so, (const char*)g_hhi + boff, sz);     \
        cp_async16(dynb + (BUFO) + G2A_L + so, (const char*)g_hlo + boff, sz);     \
    }                                                                              \
    _Pragma("unroll")                                                              \
    for (int it = 0; it < 3; it++) {                                               \
        int idx = tid + it * 256;                                                  \
        if (idx < 640) {                                                           \
            int row = idx >> 3, seg = idx & 7;                                     \
            size_t boff = ((size_t)row * 256 + (K0) + seg * 8) * 2;                \
            int so = SW128(row * 128 + seg * 16);                                  \
            cp_async16(dynb + (BUFO) + G2B_H + so, (const char*)g_w2hi + boff, 16);\
            cp_async16(dynb + (BUFO) + G2B_L + so, (const char*)g_w2lo + boff, 16);\
        }                                                                          \
    }                                                                              \
} while (0)

    STAGE2(0, 0);     CP_COMMIT();
    STAGE2(64, BUF2); CP_COMMIT();

    for (int kc = 0; kc < 4; kc++) {
        uint32_t bufo = (kc & 1) ? BUF2 : 0;
        CP_WAIT1();
        __syncthreads();
#pragma unroll
        for (int j = 0; j < 4; j++) {
            uint32_t ah[4], al[4], bh[5][4], bl[5][4];
            LDSM4(ah, dynb + bufo + G2A_H + offA[j]);
            LDSM4(al, dynb + bufo + G2A_L + offA[j]);
#pragma unroll
            for (int q = 0; q < 5; q++) {
                LDSM4(bh[q], dynb + bufo + G2B_H + offB[q][j]);
                LDSM4(bl[q], dynb + bufo + G2B_L + offB[q][j]);
            }
#pragma unroll
            for (int jn = 0; jn < 10; jn++) {
                int q = jn >> 1, hsel = (jn & 1) * 2;
                uint32_t bh0 = bh[q][hsel], bh1 = bh[q][hsel + 1];
                uint32_t bl0 = bl[q][hsel], bl1 = bl[q][hsel + 1];
                mma16816(acc[jn], ah, bh0, bh1);
                mma16816(acc[jn], ah, bl0, bl1);
                mma16816(acc[jn], al, bh0, bh1);
            }
        }
        __syncthreads();
        if (kc < 2) STAGE2((kc + 2) * 64, bufo);
        CP_COMMIT();
    }
#undef STAGE2

    int r0 = bm + warp_m + (lane >> 2);
    int c0 = 2 * (lane & 3);
#pragma unroll
    for (int jn = 0; jn < 10; jn++) {
        int col = c0 + jn * 8;
#pragma unroll
        for (int half = 0; half < 2; half++) {
            int row = r0 + half * 8;
            if (row < NN) {
                float vx = acc[jn][half * 2 + 0];
                float vy = acc[jn][half * 2 + 1];
                if (col < 40) {
                    float2 v = make_float2(vx, vy);
                    *(float2*)&g_p[(size_t)row * 40 + col] = v;
                } else {
                    float2 v = make_float2(vx + b2[col - 40], vy + b2[col - 39]);
                    *(float2*)&g_r[(size_t)row * 40 + (col - 40)] = v;
                }
            }
        }
    }
}

// ---------------- layer-2 aggregation + log_softmax --------------------------
__global__ void k_agg2_lsm(float* __restrict__ out) {
    int warp = (blockIdx.x * blockDim.x + threadIdx.x) >> 5;
    if (warp >= NN) return;
    int lane = threadIdx.x & 31;
    int beg = g_offsets[warp], end = g_offsets[warp + 1];
    bool h1 = lane < 8;
    float a0 = 0.f, a1 = 0.f;
    for (int e = beg; e < end; e++) {
        int s = g_esrc[e];
        const float* ps = g_p + (size_t)s * 40;
        a0 += ps[lane];
        if (h1) a1 += ps[32 + lane];
    }
    float iv = g_invc[warp];
    float v0 = a0 * iv + g_r[(size_t)warp * 40 + lane];
    float v1 = h1 ? (a1 * iv + g_r[(size_t)warp * 40 + 32 + lane]) : -3.0e38f;

    float m = fmaxf(v0, v1);
#pragma unroll
    for (int off = 16; off; off >>= 1)
        m = fmaxf(m, __shfl_xor_sync(0xffffffffu, m, off));
    float ssum = expf(v0 - m) + (h1 ? expf(v1 - m) : 0.f);
#pragma unroll
    for (int off = 16; off; off >>= 1)
        ssum += __shfl_xor_sync(0xffffffffu, ssum, off);
    float lse = m + logf(ssum);

    out[(size_t)warp * 40 + lane] = v0 - lse;
    if (h1) out[(size_t)warp * 40 + 32 + lane] = v1 - lse;
}

// ---------------- launch -----------------------------------------------------
extern "C" void kernel_launch(void* const* d_in, const int* in_sizes, int n_in,
                              void* d_out, int out_size) {
    const float* x   = (const float*)d_in[0];
    const void*  ei  = d_in[1];
    const float* W1l = (const float*)d_in[2];
    const float* W1r = (const float*)d_in[3];
    const float* b1  = (const float*)d_in[4];
    const float* W2l = (const float*)d_in[5];
    const float* W2r = (const float*)d_in[6];
    const float* b2  = (const float*)d_in[7];
    float* out = (float*)d_out;

    cudaFuncSetAttribute(k_fused1, cudaFuncAttributeMaxDynamicSharedMemorySize,
                         DYN_SMEMF);
    cudaFuncSetAttribute(k_gemm2_mma, cudaFuncAttributeMaxDynamicSharedMemorySize,
                         DYN_SMEM2);

    k_init<<<1 + NB, 256>>>((const int*)ei);
    k_count_prep<<<CPB_W2, 256>>>(ei, W1l, W1r, W2l, W2r);
    k_scan<<<NB, 256>>>();
    k_scatter<<<(NE + 255) / 256, 256>>>(ei);
    k_fused1<<<(NN + 127) / 128, 512, DYN_SMEMF>>>(x, b1);
    k_gemm2_mma<<<(NN + 127) / 128, 256, DYN_SMEM2>>>(b2);
    k_agg2_lsm<<<(NN + 7) / 8, 256>>>(out);
}

// round 10
// speedup vs baseline: 1.0624x; 1.0624x over previous
#include <cuda_runtime.h>
#include <cuda_bf16.h>
#include <math.h>
#include <cstdint>

#define NN   50000
#define NE   800000
#define IND  128
#define HID  256
#define OUTD 40
#define NB   ((NN + 255) / 256)   // 196 scan blocks
#define ROWS_H1 25088             // 196 gemm1 tiles; h2 = 195 tiles

// ---------------- scratch ----------------------------------------------------
__device__ int   g_is64;
__device__ int   g_counts[NN];
__device__ int   g_offsets[NN + 1];
__device__ int   g_cursor[NN];
__device__ int   g_esrc[NE];
__device__ float g_invc[NN];
__device__ int   g_bsum[NB];
__device__ int   g_done1 = 0;
__device__ int   g_done2 = 0;
__device__ __align__(16) __nv_bfloat16 g_a_hi[(size_t)NN * HID];  // [agg|x] hi
__device__ __align__(16) __nv_bfloat16 g_a_lo[(size_t)NN * HID];  // [agg|x] lo
__device__ __align__(16) __nv_bfloat16 g_w1hi[(size_t)HID * HID]; // W1^T hi [n][k]
__device__ __align__(16) __nv_bfloat16 g_w1lo[(size_t)HID * HID]; // W1^T lo [n][k]
__device__ __align__(16) __nv_bfloat16 g_hhi[(size_t)NN * HID];   // h hi [NN][256]
__device__ __align__(16) __nv_bfloat16 g_hlo[(size_t)NN * HID];   // h lo
__device__ __align__(16) __nv_bfloat16 g_w2hi[(size_t)80 * HID];  // W2^T hi [80][256]
__device__ __align__(16) __nv_bfloat16 g_w2lo[(size_t)80 * HID];  // W2^T lo
__device__ __align__(16) float g_p[(size_t)NN * OUTD];
__device__ __align__(16) float g_r[(size_t)NN * OUTD];

// ---------------- helpers ----------------------------------------------------
__device__ __forceinline__ uint32_t smem_u32(const void* p) {
    uint32_t a;
    asm("{ .reg .u64 t; cvta.to.shared.u64 t, %1; cvt.u32.u64 %0, t; }"
        : "=r"(a) : "l"(p));
    return a;
}

#define SW128(o) ((o) ^ (((o) >> 3) & 0x70))

#define LDSM4(R, ADDR)                                                           \
    asm volatile("ldmatrix.sync.aligned.m8n8.x4.shared.b16 {%0,%1,%2,%3}, [%4];" \
        : "=r"((R)[0]), "=r"((R)[1]), "=r"((R)[2]), "=r"((R)[3]) : "r"(ADDR))

__device__ __forceinline__ void mma16816(float* c, const uint32_t* a,
                                         uint32_t b0, uint32_t b1) {
    asm volatile(
        "mma.sync.aligned.m16n8k16.row.col.f32.bf16.bf16.f32 "
        "{%0,%1,%2,%3}, {%4,%5,%6,%7}, {%8,%9}, {%0,%1,%2,%3};"
        : "+f"(c[0]), "+f"(c[1]), "+f"(c[2]), "+f"(c[3])
        : "r"(a[0]), "r"(a[1]), "r"(a[2]), "r"(a[3]), "r"(b0), "r"(b1));
}

__device__ __forceinline__ void cp_async16(uint32_t dst, const void* src, int srcsz) {
    asm volatile("cp.async.cg.shared.global [%0], [%1], 16, %2;"
                 :: "r"(dst), "l"(src), "r"(srcsz) : "memory");
}
#define CP_COMMIT() asm volatile("cp.async.commit_group;" ::: "memory")
#define CP_WAIT1()  asm volatile("cp.async.wait_group 1;" ::: "memory")

__device__ __forceinline__ int edge_at(const void* ei, int idx) {
    if (g_is64) return (int)((const long long*)ei)[idx];
    return ((const int*)ei)[idx];
}

// ---------------- bf16 split helpers -----------------------------------------
__device__ __forceinline__ void split4(float4 v, uint2& hi, uint2& lo) {
    __nv_bfloat16 h0 = __float2bfloat16(v.x);
    __nv_bfloat16 h1 = __float2bfloat16(v.y);
    __nv_bfloat16 h2 = __float2bfloat16(v.z);
    __nv_bfloat16 h3 = __float2bfloat16(v.w);
    __nv_bfloat16 l0 = __float2bfloat16(v.x - __bfloat162float(h0));
    __nv_bfloat16 l1 = __float2bfloat16(v.y - __bfloat162float(h1));
    __nv_bfloat16 l2 = __float2bfloat16(v.z - __bfloat162float(h2));
    __nv_bfloat16 l3 = __float2bfloat16(v.w - __bfloat162float(h3));
    hi.x = (uint32_t)__bfloat16_as_ushort(h0) | ((uint32_t)__bfloat16_as_ushort(h1) << 16);
    hi.y = (uint32_t)__bfloat16_as_ushort(h2) | ((uint32_t)__bfloat16_as_ushort(h3) << 16);
    lo.x = (uint32_t)__bfloat16_as_ushort(l0) | ((uint32_t)__bfloat16_as_ushort(l1) << 16);
    lo.y = (uint32_t)__bfloat16_as_ushort(l2) | ((uint32_t)__bfloat16_as_ushort(l3) << 16);
}

__device__ __forceinline__ void split2(float x, float y, uint32_t& hi, uint32_t& lo) {
    __nv_bfloat16 hx = __float2bfloat16(x), hy = __float2bfloat16(y);
    __nv_bfloat16 lx = __float2bfloat16(x - __bfloat162float(hx));
    __nv_bfloat16 ly = __float2bfloat16(y - __bfloat162float(hy));
    hi = (uint32_t)__bfloat16_as_ushort(hx) | ((uint32_t)__bfloat16_as_ushort(hy) << 16);
    lo = (uint32_t)__bfloat16_as_ushort(lx) | ((uint32_t)__bfloat16_as_ushort(ly) << 16);
}

// ---------------- k_init: detect (block 0) + zero counts ---------------------
__global__ void k_init(const int* __restrict__ ei32) {
    int b = blockIdx.x;
    int tid = threadIdx.x;
    if (b == 0) {
        __shared__ int bad;
        if (tid == 0) bad = 0;
        __syncthreads();
        if (ei32[2 * tid + 1] != 0) atomicOr(&bad, 1);
        __syncthreads();
        if (tid == 0) g_is64 = bad ? 0 : 1;
    } else {
        int i = (b - 1) * 256 + tid;
        if (i < NN) g_counts[i] = 0;
    }
}

// ---------------- k_count_prep: edge count ∥ W1/W2/x bf16-split --------------
#define CPB_COUNT 3125
#define CPB_W1    (CPB_COUNT + 256)
#define CPB_W2    (CPB_W1 + 80)
#define CPB_X     (CPB_W2 + 6250)

__global__ void k_count_prep(const void* __restrict__ ei,
                             const float* __restrict__ W1l, const float* __restrict__ W1r,
                             const float* __restrict__ W2l, const float* __restrict__ W2r,
                             const float* __restrict__ x) {
    int b = blockIdx.x;
    int tid = threadIdx.x;
    if (b < CPB_COUNT) {
        int e = b * 256 + tid;
        if (e < NE) atomicAdd(&g_counts[edge_at(ei, NE + e)], 1);
    } else if (b < CPB_W1) {
        int idx = (b - CPB_COUNT) * 256 + tid;
        int n = idx >> 8, k = idx & 255;
        float w = (k < 128) ? W1l[(size_t)k * 256 + n]
                            : W1r[(size_t)(k - 128) * 256 + n];
        __nv_bfloat16 h = __float2bfloat16(w);
        __nv_bfloat16 l = __float2bfloat16(w - __bfloat162float(h));
        g_w1hi[(size_t)n * 256 + k] = h;
        g_w1lo[(size_t)n * 256 + k] = l;
    } else if (b < CPB_W2) {
        int idx = (b - CPB_W1) * 256 + tid;
        int n = idx >> 8, k = idx & 255;
        float w = (n < 40) ? W2l[(size_t)k * 40 + n]
                           : W2r[(size_t)k * 40 + (n - 40)];
        __nv_bfloat16 h = __float2bfloat16(w);
        __nv_bfloat16 l = __float2bfloat16(w - __bfloat162float(h));
        g_w2hi[(size_t)n * 256 + k] = h;
        g_w2lo[(size_t)n * 256 + k] = l;
    } else {
        int idx = (b - CPB_W2) * 256 + tid;
        if (idx >= NN * 32) return;
        int row = idx >> 5, c4 = idx & 31;
        float4 v = ((const float4*)x)[(size_t)row * 32 + c4];
        uint2 hi, lo;
        split4(v, hi, lo);
        *(uint2*)&g_a_hi[(size_t)row * 256 + 128 + c4 * 4] = hi;
        *(uint2*)&g_a_lo[(size_t)row * 256 + 128 + c4 * 4] = lo;
    }
}

// ---------------- k_scan: fused hierarchical scan ----------------------------
__device__ __forceinline__ int block_excl_scan(int c, int t) {
    int lane = t & 31, w = t >> 5;
    int v = c;
#pragma unroll
    for (int off = 1; off < 32; off <<= 1) {
        int n = __shfl_up_sync(0xffffffffu, v, off);
        if (lane >= off) v += n;
    }
    __shared__ int ws[8];
    if (lane == 31) ws[w] = v;
    __syncthreads();
    if (w == 0 && lane < 8) {
        int s = ws[lane];
#pragma unroll
        for (int off = 1; off < 8; off <<= 1) {
            int n = __shfl_up_sync(0x000000ffu, s, off);
            if (lane >= off) s += n;
        }
        ws[lane] = s;
    }
    __syncthreads();
    return v - c + (w > 0 ? ws[w - 1] : 0);
}

__global__ void k_scan() {
    int b = blockIdx.x, tid = threadIdx.x;
    int i = b * 256 + tid;
    int c = (i < NN) ? g_counts[i] : 0;
    int e = block_excl_scan(c, tid);

    if (tid == 255) {
        g_bsum[b] = e + c;
        __threadfence();
        atomicAdd(&g_done1, 1);
    }
    if (tid == 0) {
        while (*(volatile int*)&g_done1 < NB) {}
    }
    __syncthreads();
    __threadfence();

    int v = (tid < b) ? g_bsum[tid] : 0;
    int lane = tid & 31, w = tid >> 5;
#pragma unroll
    for (int off = 16; off; off >>= 1) v += __shfl_xor_sync(0xffffffffu, v, off);
    __shared__ int rs[8];
    if (lane == 0) rs[w] = v;
    __syncthreads();
    __shared__ int pre;
    if (tid == 0) {
        int s = 0;
#pragma unroll
        for (int k = 0; k < 8; k++) s += rs[k];
        pre = s;
    }
    __syncthreads();

    if (i < NN) {
        int off = pre + e;
        g_offsets[i] = off;
        g_cursor[i]  = off;
        g_invc[i]    = 1.0f / (float)(c > 1 ? c : 1);
    }
    if (b == NB - 1 && tid == 255) g_offsets[NN] = NE;

    if (tid == 0) {
        int t2 = atomicAdd(&g_done2, 1);
        if (t2 == NB - 1) { g_done1 = 0; g_done2 = 0; }
    }
}

__global__ void k_scatter(const void* __restrict__ ei) {
    int e = blockIdx.x * blockDim.x + threadIdx.x;
    if (e < NE) {
        int s = edge_at(ei, e);
        int d = edge_at(ei, NE + e);
        g_esrc[atomicAdd(&g_cursor[d], 1)] = s;
    }
}

// ---------------- layer-1 aggregation (node range [n0, n1)) ------------------
__global__ void k_agg1(const float* __restrict__ x, int n0, int n1) {
    int warp = n0 + ((blockIdx.x * blockDim.x + threadIdx.x) >> 5);
    if (warp >= n1) return;
    int lane = threadIdx.x & 31;
    int beg = g_offsets[warp], end = g_offsets[warp + 1];
    const float4* __restrict__ x4 = (const float4*)x;
    float4 acc = make_float4(0.f, 0.f, 0.f, 0.f);
    int e = beg;
    for (; e + 1 < end; e += 2) {
        int s0 = g_esrc[e];
        int s1 = g_esrc[e + 1];
        float4 v0 = x4[(size_t)s0 * 32 + lane];
        float4 v1 = x4[(size_t)s1 * 32 + lane];
        acc.x += v0.x + v1.x; acc.y += v0.y + v1.y;
        acc.z += v0.z + v1.z; acc.w += v0.w + v1.w;
    }
    if (e < end) {
        int s0 = g_esrc[e];
        float4 v0 = x4[(size_t)s0 * 32 + lane];
        acc.x += v0.x; acc.y += v0.y; acc.z += v0.z; acc.w += v0.w;
    }
    float iv = g_invc[warp];
    float4 o = make_float4(acc.x * iv, acc.y * iv, acc.z * iv, acc.w * iv);
    uint2 hi, lo;
    split4(o, hi, lo);
    *(uint2*)&g_a_hi[(size_t)warp * 256 + lane * 4] = hi;
    *(uint2*)&g_a_lo[(size_t)warp * 256 + lane * 4] = lo;
}

// ---------------- GEMM1 via mma.sync (bf16 3-pass split, cp.async pipe) ------
#define GA_H 0
#define GA_L 16384
#define GB_H 32768
#define GB_L 49152
#define BUF1 65536
#define DYN_SMEM1 (2 * BUF1)

__global__ void __launch_bounds__(256, 1) k_gemm1_mma(const float* __restrict__ b1,
                                                      int tile0) {
    extern __shared__ char dsm[];
    int tid = threadIdx.x;
    int wid = tid >> 5;
    int lane = tid & 31;
    int bm = (blockIdx.x + tile0) * 128;
    int bn = blockIdx.y * 128;
    uint32_t dynb = smem_u32(dsm);

    int warp_m = (wid & 3) * 32;
    int warp_n = (wid >> 2) * 64;

    uint32_t offA[2][4], offB[4][4];
    {
        int mat = lane >> 3, rr = lane & 7;
#pragma unroll
        for (int i = 0; i < 2; i++)
#pragma unroll
            for (int j = 0; j < 4; j++) {
                int row = warp_m + i * 16 + ((mat & 1) << 3) + rr;
                int kb  = j * 16 + ((mat >> 1) << 3);
                offA[i][j] = SW128(row * 128 + kb * 2);
            }
#pragma unroll
        for (int q = 0; q < 4; q++)
#pragma unroll
            for (int j = 0; j < 4; j++) {
                int n  = warp_n + q * 16 + ((mat & 2) << 2) + rr;
                int kb = j * 16 + ((mat & 1) << 3);
                offB[q][j] = SW128(n * 128 + kb * 2);
            }
    }

    float acc[2][8][4];
#pragma unroll
    for (int i = 0; i < 2; i++)
#pragma unroll
        for (int jn = 0; jn < 8; jn++)
#pragma unroll
            for (int t = 0; t < 4; t++) acc[i][jn][t] = 0.f;

#define STAGE1(K0, BUFO) do {                                                      \
    _Pragma("unroll")                                                              \
    for (int it = 0; it < 4; it++) {                                               \
        int idx = tid + it * 256;                                                  \
        int row = idx >> 3, seg = idx & 7;                                         \
        int grow = bm + row;                                                       \
        int cl = grow < NN ? grow : (NN - 1);                                      \
        int sz = grow < NN ? 16 : 0;                                               \
        size_t boff = ((size_t)cl * 256 + (K0) + seg * 8) * 2;                     \
        int so = SW128(row * 128 + seg * 16);                                      \
        cp_async16(dynb + (BUFO) + GA_H + so, (const char*)g_a_hi + boff, sz);     \
        cp_async16(dynb + (BUFO) + GA_L + so, (const char*)g_a_lo + boff, sz);     \
    }                                                                              \
    _Pragma("unroll")                                                              \
    for (int it = 0; it < 4; it++) {                                               \
        int idx = tid + it * 256;                                                  \
        int row = idx >> 3, seg = idx & 7;                                         \
        size_t boff = ((size_t)(bn + row) * 256 + (K0) + seg * 8) * 2;             \
        int so = SW128(row * 128 + seg * 16);                                      \
        cp_async16(dynb + (BUFO) + GB_H + so, (const char*)g_w1hi + boff, 16);     \
        cp_async16(dynb + (BUFO) + GB_L + so, (const char*)g_w1lo + boff, 16);     \
    }                                                                              \
} while (0)

    STAGE1(0, 0);     CP_COMMIT();
    STAGE1(64, BUF1); CP_COMMIT();

    for (int kc = 0; kc < 4; kc++) {
        uint32_t bufo = (kc & 1) ? BUF1 : 0;
        CP_WAIT1();
        __syncthreads();
#pragma unroll
        for (int j = 0; j < 4; j++) {
            uint32_t ah[2][4], al[2][4], bh[4][4], bl[4][4];
#pragma unroll
            for (int i = 0; i < 2; i++) {
                LDSM4(ah[i], dynb + bufo + GA_H + offA[i][j]);
                LDSM4(al[i], dynb + bufo + GA_L + offA[i][j]);
            }
#pragma unroll
            for (int q = 0; q < 4; q++) {
                LDSM4(bh[q], dynb + bufo + GB_H + offB[q][j]);
                LDSM4(bl[q], dynb + bufo + GB_L + offB[q][j]);
            }
#pragma unroll
            for (int i = 0; i < 2; i++)
#pragma unroll
                for (int jn = 0; jn < 8; jn++) {
                    int q = jn >> 1, hsel = (jn & 1) * 2;
                    uint32_t bh0 = bh[q][hsel], bh1 = bh[q][hsel + 1];
                    uint32_t bl0 = bl[q][hsel], bl1 = bl[q][hsel + 1];
                    mma16816(acc[i][jn], ah[i], bh0, bh1);
                    mma16816(acc[i][jn], ah[i], bl0, bl1);
                    mma16816(acc[i][jn], al[i], bh0, bh1);
                }
        }
        __syncthreads();
        if (kc < 2) STAGE1((kc + 2) * 64, bufo);
        CP_COMMIT();
    }
#undef STAGE1

    int r0 = bm + warp_m + (lane >> 2);
    int c0 = bn + warp_n + 2 * (lane & 3);
#pragma unroll
    for (int i = 0; i < 2; i++) {
        int row = r0 + i * 16;
#pragma unroll
        for (int jn = 0; jn < 8; jn++) {
            int col = c0 + jn * 8;
            float bx = b1[col], by = b1[col + 1];
            if (row < NN) {
                float vx = acc[i][jn][0] + bx; vx = vx > 0.f ? vx : 0.f;
                float vy = acc[i][jn][1] + by; vy = vy > 0.f ? vy : 0.f;
                uint32_t hi, lo;
                split2(vx, vy, hi, lo);
                *(uint32_t*)&g_hhi[(size_t)row * 256 + col] = hi;
                *(uint32_t*)&g_hlo[(size_t)row * 256 + col] = lo;
            }
            if (row + 8 < NN) {
                float vx = acc[i][jn][2] + bx; vx = vx > 0.f ? vx : 0.f;
                float vy = acc[i][jn][3] + by; vy = vy > 0.f ? vy : 0.f;
                uint32_t hi, lo;
                split2(vx, vy, hi, lo);
                *(uint32_t*)&g_hhi[(size_t)(row + 8) * 256 + col] = hi;
                *(uint32_t*)&g_hlo[(size_t)(row + 8) * 256 + col] = lo;
            }
        }
    }
}

// ---------------- GEMM2 via mma.sync (cp.async pipe) -------------------------
#define G2A_H 0
#define G2A_L 16384
#define G2B_H 32768
#define G2B_L 43008
#define BUF2 53248
#define DYN_SMEM2 (2 * BUF2)

__global__ void __launch_bounds__(256, 1) k_gemm2_mma(const float* __restrict__ b2) {
    extern __shared__ char dsm[];
    int tid = threadIdx.x;
    int wid = tid >> 5;
    int lane = tid & 31;
    int bm = blockIdx.x * 128;
    uint32_t dynb = smem_u32(dsm);

    int warp_m = wid * 16;

    uint32_t offA[4], offB[5][4];
    {
        int mat = lane >> 3, rr = lane & 7;
#pragma unroll
        for (int j = 0; j < 4; j++) {
            int row = warp_m + ((mat & 1) << 3) + rr;
            int kb  = j * 16 + ((mat >> 1) << 3);
            offA[j] = SW128(row * 128 + kb * 2);
        }
#pragma unroll
        for (int q = 0; q < 5; q++)
#pragma unroll
            for (int j = 0; j < 4; j++) {
                int n  = q * 16 + ((mat & 2) << 2) + rr;
                int kb = j * 16 + ((mat & 1) << 3);
                offB[q][j] = SW128(n * 128 + kb * 2);
            }
    }

    float acc[10][4];
#pragma unroll
    for (int jn = 0; jn < 10; jn++)
#pragma unroll
        for (int t = 0; t < 4; t++) acc[jn][t] = 0.f;

#define STAGE2(K0, BUFO) do {                                                      \
    _Pragma("unroll")                                                              \
    for (int it = 0; it < 4; it++) {                                               \
        int idx = tid + it * 256;                                                  \
        int row = idx >> 3, seg = idx & 7;                                         \
        int grow = bm + row;                                                       \
        int cl = grow < NN ? grow : (NN - 1);                                      \
        int sz = grow < NN ? 16 : 0;                                               \
        size_t boff = ((size_t)cl * 256 + (K0) + seg * 8) * 2;                     \
        int so = SW128(row * 128 + seg * 16);                                      \
        cp_async16(dynb + (BUFO) + G2A_H + so, (const char*)g_hhi + boff, sz);     \
        cp_async16(dynb + (BUFO) + G2A_L + so, (const char*)g_hlo + boff, sz);     \
    }                                                                              \
    _Pragma("unroll")                                                              \
    for (int it = 0; it < 3; it++) {                                               \
        int idx = tid + it * 256;                                                  \
        if (idx < 640) {                                                           \
            int row = idx >> 3, seg = idx & 7;                                     \
            size_t boff = ((size_t)row * 256 + (K0) + seg * 8) * 2;                \
            int so = SW128(row * 128 + seg * 16);                                  \
            cp_async16(dynb + (BUFO) + G2B_H + so, (const char*)g_w2hi + boff, 16);\
            cp_async16(dynb + (BUFO) + G2B_L + so, (const char*)g_w2lo + boff, 16);\
        }                                                                          \
    }                                                                              \
} while (0)

    STAGE2(0, 0);     CP_COMMIT();
    STAGE2(64, BUF2); CP_COMMIT();

    for (int kc = 0; kc < 4; kc++) {
        uint32_t bufo = (kc & 1) ? BUF2 : 0;
        CP_WAIT1();
        __syncthreads();
#pragma unroll
        for (int j = 0; j < 4; j++) {
            uint32_t ah[4], al[4], bh[5][4], bl[5][4];
            LDSM4(ah, dynb + bufo + G2A_H + offA[j]);
            LDSM4(al, dynb + bufo + G2A_L + offA[j]);
#pragma unroll
            for (int q = 0; q < 5; q++) {
                LDSM4(bh[q], dynb + bufo + G2B_H + offB[q][j]);
                LDSM4(bl[q], dynb + bufo + G2B_L + offB[q][j]);
            }
#pragma unroll
            for (int jn = 0; jn < 10; jn++) {
                int q = jn >> 1, hsel = (jn & 1) * 2;
                uint32_t bh0 = bh[q][hsel], bh1 = bh[q][hsel + 1];
                uint32_t bl0 = bl[q][hsel], bl1 = bl[q][hsel + 1];
                mma16816(acc[jn], ah, bh0, bh1);
                mma16816(acc[jn], ah, bl0, bl1);
                mma16816(acc[jn], al, bh0, bh1);
            }
        }
        __syncthreads();
        if (kc < 2) STAGE2((kc + 2) * 64, bufo);
        CP_COMMIT();
    }
#undef STAGE2

    int r0 = bm + warp_m + (lane >> 2);
    int c0 = 2 * (lane & 3);
#pragma unroll
    for (int jn = 0; jn < 10; jn++) {
        int col = c0 + jn * 8;
#pragma unroll
        for (int half = 0; half < 2; half++) {
            int row = r0 + half * 8;
            if (row < NN) {
                float vx = acc[jn][half * 2 + 0];
                float vy = acc[jn][half * 2 + 1];
                if (col < 40) {
                    float2 v = make_float2(vx, vy);
                    *(float2*)&g_p[(size_t)row * 40 + col] = v;
                } else {
                    float2 v = make_float2(vx + b2[col - 40], vy + b2[col - 39]);
                    *(float2*)&g_r[(size_t)row * 40 + (col - 40)] = v;
                }
            }
        }
    }
}

// ---------------- layer-2 aggregation + log_softmax --------------------------
__global__ void k_agg2_lsm(float* __restrict__ out) {
    int warp = (blockIdx.x * blockDim.x + threadIdx.x) >> 5;
    if (warp >= NN) return;
    int lane = threadIdx.x & 31;
    int beg = g_offsets[warp], end = g_offsets[warp + 1];
    bool h1 = lane < 8;
    float a0 = 0.f, a1 = 0.f;
    for (int e = beg; e < end; e++) {
        int s = g_esrc[e];
        const float* ps = g_p + (size_t)s * 40;
        a0 += ps[lane];
        if (h1) a1 += ps[32 + lane];
    }
    float iv = g_invc[warp];
    float v0 = a0 * iv + g_r[(size_t)warp * 40 + lane];
    float v1 = h1 ? (a1 * iv + g_r[(size_t)warp * 40 + 32 + lane]) : -3.0e38f;

    float m = fmaxf(v0, v1);
#pragma unroll
    for (int off = 16; off; off >>= 1)
        m = fmaxf(m, __shfl_xor_sync(0xffffffffu, m, off));
    float ssum = expf(v0 - m) + (h1 ? expf(v1 - m) : 0.f);
#pragma unroll
    for (int off = 16; off; off >>= 1)
        ssum += __shfl_xor_sync(0xffffffffu, ssum, off);
    float lse = m + logf(ssum);

    out[(size_t)warp * 40 + lane] = v0 - lse;
    if (h1) out[(size_t)warp * 40 + 32 + lane] = v1 - lse;
}

// ---------------- launch -----------------------------------------------------
extern "C" void kernel_launch(void* const* d_in, const int* in_sizes, int n_in,
                              void* d_out, int out_size) {
    const float* x   = (const float*)d_in[0];
    const void*  ei  = d_in[1];
    const float* W1l = (const float*)d_in[2];
    const float* W1r = (const float*)d_in[3];
    const float* b1  = (const float*)d_in[4];
    const float* W2l = (const float*)d_in[5];
    const float* W2r = (const float*)d_in[6];
    const float* b2  = (const float*)d_in[7];
    float* out = (float*)d_out;

    // one-time resource setup (first call is the uncaptured correctness run)
    static cudaStream_t s2 = nullptr;
    static cudaEvent_t evA = nullptr, evB = nullptr;
    if (s2 == nullptr) {
        cudaStreamCreateWithFlags(&s2, cudaStreamNonBlocking);
        cudaEventCreateWithFlags(&evA, cudaEventDisableTiming);
        cudaEventCreateWithFlags(&evB, cudaEventDisableTiming);
        cudaFuncSetAttribute(k_gemm1_mma, cudaFuncAttributeMaxDynamicSharedMemorySize,
                             DYN_SMEM1);
        cudaFuncSetAttribute(k_gemm2_mma, cudaFuncAttributeMaxDynamicSharedMemorySize,
                             DYN_SMEM2);
    }

    k_init<<<1 + NB, 256>>>((const int*)ei);
    k_count_prep<<<CPB_X, 256>>>(ei, W1l, W1r, W2l, W2r, x);
    k_scan<<<NB, 256>>>();
    k_scatter<<<(NE + 255) / 256, 256>>>(ei);

    // agg1 first half on main stream
    k_agg1<<<(ROWS_H1 + 7) / 8, 256>>>(x, 0, ROWS_H1);
    cudaEventRecord(evA, 0);

    // agg1 second half on side stream (concurrent with gemm1_h1)
    cudaStreamWaitEvent(s2, evA, 0);
    k_agg1<<<((NN - ROWS_H1) + 7) / 8, 256, 0, s2>>>(x, ROWS_H1, NN);
    cudaEventRecord(evB, s2);

    // gemm1 first half (depends on agg h1 only)
    dim3 g1a(ROWS_H1 / 128, 2);
    k_gemm1_mma<<<g1a, 256, DYN_SMEM1>>>(b1, 0);

    // gemm1 second half after agg h2 completes
    cudaStreamWaitEvent(0, evB, 0);
    dim3 g1b((NN - ROWS_H1 + 127) / 128, 2);
    k_gemm1_mma<<<g1b, 256, DYN_SMEM1>>>(b1, ROWS_H1 / 128);

    k_gemm2_mma<<<(NN + 127) / 128, 256, DYN_SMEM2>>>(b2);
    k_agg2_lsm<<<(NN + 7) / 8, 256>>>(out);
}

// round 11
// speedup vs baseline: 1.0751x; 1.0120x over previous
#include <cuda_runtime.h>
#include <cuda_bf16.h>
#include <math.h>
#include <cstdint>

#define NN   50000
#define NE   800000
#define IND  128
#define HID  256
#define OUTD 40
#define NB   ((NN + 255) / 256)   // 196 scan blocks

// ---------------- scratch ----------------------------------------------------
__device__ int   g_is64;
__device__ int   g_counts[NN];
__device__ int   g_offsets[NN + 1];
__device__ int   g_rank[NE];
__device__ int   g_esrc[NE];
__device__ float g_invc[NN];
__device__ int   g_bsum[NB];
__device__ int   g_done1 = 0;
__device__ int   g_done2 = 0;
__device__ __align__(16) __nv_bfloat16 g_a_hi[(size_t)NN * HID];  // [agg|x] hi
__device__ __align__(16) __nv_bfloat16 g_a_lo[(size_t)NN * HID];  // [agg|x] lo
__device__ __align__(16) __nv_bfloat16 g_w1hi[(size_t)HID * HID]; // W1^T hi [n][k]
__device__ __align__(16) __nv_bfloat16 g_w1lo[(size_t)HID * HID]; // W1^T lo [n][k]
__device__ __align__(16) __nv_bfloat16 g_hhi[(size_t)NN * HID];   // h hi [NN][256]
__device__ __align__(16) __nv_bfloat16 g_hlo[(size_t)NN * HID];   // h lo
__device__ __align__(16) __nv_bfloat16 g_w2hi[(size_t)80 * HID];  // W2^T hi [80][256]
__device__ __align__(16) __nv_bfloat16 g_w2lo[(size_t)80 * HID];  // W2^T lo
__device__ __align__(16) float g_p[(size_t)NN * OUTD];
__device__ __align__(16) float g_r[(size_t)NN * OUTD];

// ---------------- helpers ----------------------------------------------------
__device__ __forceinline__ uint32_t smem_u32(const void* p) {
    uint32_t a;
    asm("{ .reg .u64 t; cvta.to.shared.u64 t, %1; cvt.u32.u64 %0, t; }"
        : "=r"(a) : "l"(p));
    return a;
}

#define SW128(o) ((o) ^ (((o) >> 3) & 0x70))

#define LDSM4(R, ADDR)                                                           \
    asm volatile("ldmatrix.sync.aligned.m8n8.x4.shared.b16 {%0,%1,%2,%3}, [%4];" \
        : "=r"((R)[0]), "=r"((R)[1]), "=r"((R)[2]), "=r"((R)[3]) : "r"(ADDR))

__device__ __forceinline__ void mma16816(float* c, const uint32_t* a,
                                         uint32_t b0, uint32_t b1) {
    asm volatile(
        "mma.sync.aligned.m16n8k16.row.col.f32.bf16.bf16.f32 "
        "{%0,%1,%2,%3}, {%4,%5,%6,%7}, {%8,%9}, {%0,%1,%2,%3};"
        : "+f"(c[0]), "+f"(c[1]), "+f"(c[2]), "+f"(c[3])
        : "r"(a[0]), "r"(a[1]), "r"(a[2]), "r"(a[3]), "r"(b0), "r"(b1));
}

__device__ __forceinline__ void cp_async16(uint32_t dst, const void* src, int srcsz) {
    asm volatile("cp.async.cg.shared.global [%0], [%1], 16, %2;"
                 :: "r"(dst), "l"(src), "r"(srcsz) : "memory");
}
#define CP_COMMIT() asm volatile("cp.async.commit_group;" ::: "memory")
#define CP_WAIT1()  asm volatile("cp.async.wait_group 1;" ::: "memory")

__device__ __forceinline__ int edge_at(const void* ei, int idx) {
    if (g_is64) return (int)((const long long*)ei)[idx];
    return ((const int*)ei)[idx];
}

// ---------------- bf16 split helpers -----------------------------------------
__device__ __forceinline__ void split4(float4 v, uint2& hi, uint2& lo) {
    __nv_bfloat16 h0 = __float2bfloat16(v.x);
    __nv_bfloat16 h1 = __float2bfloat16(v.y);
    __nv_bfloat16 h2 = __float2bfloat16(v.z);
    __nv_bfloat16 h3 = __float2bfloat16(v.w);
    __nv_bfloat16 l0 = __float2bfloat16(v.x - __bfloat162float(h0));
    __nv_bfloat16 l1 = __float2bfloat16(v.y - __bfloat162float(h1));
    __nv_bfloat16 l2 = __float2bfloat16(v.z - __bfloat162float(h2));
    __nv_bfloat16 l3 = __float2bfloat16(v.w - __bfloat162float(h3));
    hi.x = (uint32_t)__bfloat16_as_ushort(h0) | ((uint32_t)__bfloat16_as_ushort(h1) << 16);
    hi.y = (uint32_t)__bfloat16_as_ushort(h2) | ((uint32_t)__bfloat16_as_ushort(h3) << 16);
    lo.x = (uint32_t)__bfloat16_as_ushort(l0) | ((uint32_t)__bfloat16_as_ushort(l1) << 16);
    lo.y = (uint32_t)__bfloat16_as_ushort(l2) | ((uint32_t)__bfloat16_as_ushort(l3) << 16);
}

__device__ __forceinline__ void split2(float x, float y, uint32_t& hi, uint32_t& lo) {
    __nv_bfloat16 hx = __float2bfloat16(x), hy = __float2bfloat16(y);
    __nv_bfloat16 lx = __float2bfloat16(x - __bfloat162float(hx));
    __nv_bfloat16 ly = __float2bfloat16(y - __bfloat162float(hy));
    hi = (uint32_t)__bfloat16_as_ushort(hx) | ((uint32_t)__bfloat16_as_ushort(hy) << 16);
    lo = (uint32_t)__bfloat16_as_ushort(lx) | ((uint32_t)__bfloat16_as_ushort(ly) << 16);
}

// ---------------- k_init: detect (block 0) + zero counts ---------------------
__global__ void k_init(const int* __restrict__ ei32) {
    int b = blockIdx.x;
    int tid = threadIdx.x;
    if (b == 0) {
        __shared__ int bad;
        if (tid == 0) bad = 0;
        __syncthreads();
        if (ei32[2 * tid + 1] != 0) atomicOr(&bad, 1);
        __syncthreads();
        if (tid == 0) g_is64 = bad ? 0 : 1;
    } else {
        int i = (b - 1) * 256 + tid;
        if (i < NN) g_counts[i] = 0;
    }
}

// ---------------- k_count_prep: edge count+rank ∥ W1/W2/x bf16-split ---------
#define CPB_COUNT 3125
#define CPB_W1    (CPB_COUNT + 256)
#define CPB_W2    (CPB_W1 + 80)
#define CPB_X     (CPB_W2 + 6250)

__global__ void k_count_prep(const void* __restrict__ ei,
                             const float* __restrict__ W1l, const float* __restrict__ W1r,
                             const float* __restrict__ W2l, const float* __restrict__ W2r,
                             const float* __restrict__ x) {
    int b = blockIdx.x;
    int tid = threadIdx.x;
    if (b < CPB_COUNT) {
        int e = b * 256 + tid;
        if (e < NE) {
            int d = edge_at(ei, NE + e);
            g_rank[e] = atomicAdd(&g_counts[d], 1);
        }
    } else if (b < CPB_W1) {
        int idx = (b - CPB_COUNT) * 256 + tid;
        int n = idx >> 8, k = idx & 255;
        float w = (k < 128) ? W1l[(size_t)k * 256 + n]
                            : W1r[(size_t)(k - 128) * 256 + n];
        __nv_bfloat16 h = __float2bfloat16(w);
        __nv_bfloat16 l = __float2bfloat16(w - __bfloat162float(h));
        g_w1hi[(size_t)n * 256 + k] = h;
        g_w1lo[(size_t)n * 256 + k] = l;
    } else if (b < CPB_W2) {
        int idx = (b - CPB_W1) * 256 + tid;
        int n = idx >> 8, k = idx & 255;
        float w = (n < 40) ? W2l[(size_t)k * 40 + n]
                           : W2r[(size_t)k * 40 + (n - 40)];
        __nv_bfloat16 h = __float2bfloat16(w);
        __nv_bfloat16 l = __float2bfloat16(w - __bfloat162float(h));
        g_w2hi[(size_t)n * 256 + k] = h;
        g_w2lo[(size_t)n * 256 + k] = l;
    } else {
        int idx = (b - CPB_W2) * 256 + tid;
        if (idx >= NN * 32) return;
        int row = idx >> 5, c4 = idx & 31;
        float4 v = ((const float4*)x)[(size_t)row * 32 + c4];
        uint2 hi, lo;
        split4(v, hi, lo);
        *(uint2*)&g_a_hi[(size_t)row * 256 + 128 + c4 * 4] = hi;
        *(uint2*)&g_a_lo[(size_t)row * 256 + 128 + c4 * 4] = lo;
    }
}

// ---------------- k_scan: fused hierarchical scan ----------------------------
__device__ __forceinline__ int block_excl_scan(int c, int t) {
    int lane = t & 31, w = t >> 5;
    int v = c;
#pragma unroll
    for (int off = 1; off < 32; off <<= 1) {
        int n = __shfl_up_sync(0xffffffffu, v, off);
        if (lane >= off) v += n;
    }
    __shared__ int ws[8];
    if (lane == 31) ws[w] = v;
    __syncthreads();
    if (w == 0 && lane < 8) {
        int s = ws[lane];
#pragma unroll
        for (int off = 1; off < 8; off <<= 1) {
            int n = __shfl_up_sync(0x000000ffu, s, off);
            if (lane >= off) s += n;
        }
        ws[lane] = s;
    }
    __syncthreads();
    return v - c + (w > 0 ? ws[w - 1] : 0);
}

__global__ void k_scan() {
    int b = blockIdx.x, tid = threadIdx.x;
    int i = b * 256 + tid;
    int c = (i < NN) ? g_counts[i] : 0;
    int e = block_excl_scan(c, tid);

    if (tid == 255) {
        g_bsum[b] = e + c;
        __threadfence();
        atomicAdd(&g_done1, 1);
    }
    if (tid == 0) {
        while (*(volatile int*)&g_done1 < NB) {}
    }
    __syncthreads();
    __threadfence();

    int v = (tid < b) ? g_bsum[tid] : 0;
    int lane = tid & 31, w = tid >> 5;
#pragma unroll
    for (int off = 16; off; off >>= 1) v += __shfl_xor_sync(0xffffffffu, v, off);
    __shared__ int rs[8];
    if (lane == 0) rs[w] = v;
    __syncthreads();
    __shared__ int pre;
    if (tid == 0) {
        int s = 0;
#pragma unroll
        for (int k = 0; k < 8; k++) s += rs[k];
        pre = s;
    }
    __syncthreads();

    if (i < NN) {
        g_offsets[i] = pre + e;
        g_invc[i]    = 1.0f / (float)(c > 1 ? c : 1);
    }
    if (b == NB - 1 && tid == 255) g_offsets[NN] = NE;

    if (tid == 0) {
        int t2 = atomicAdd(&g_done2, 1);
        if (t2 == NB - 1) { g_done1 = 0; g_done2 = 0; }
    }
}

// ---------------- k_scatter: atomic-free via precomputed rank ----------------
__global__ void k_scatter(const void* __restrict__ ei) {
    int e = blockIdx.x * blockDim.x + threadIdx.x;
    if (e < NE) {
        int s = edge_at(ei, e);
        int d = edge_at(ei, NE + e);
        g_esrc[g_offsets[d] + g_rank[e]] = s;
    }
}

// ---------------- layer-1 aggregation (bf16 hi/lo cols 0..127) ---------------
__global__ void k_agg1(const float* __restrict__ x) {
    int warp = (blockIdx.x * blockDim.x + threadIdx.x) >> 5;
    if (warp >= NN) return;
    int lane = threadIdx.x & 31;
    int beg = g_offsets[warp], end = g_offsets[warp + 1];
    const float4* __restrict__ x4 = (const float4*)x;
    float4 acc = make_float4(0.f, 0.f, 0.f, 0.f);
    int e = beg;
    for (; e + 1 < end; e += 2) {
        int s0 = g_esrc[e];
        int s1 = g_esrc[e + 1];
        float4 v0 = x4[(size_t)s0 * 32 + lane];
        float4 v1 = x4[(size_t)s1 * 32 + lane];
        acc.x += v0.x + v1.x; acc.y += v0.y + v1.y;
        acc.z += v0.z + v1.z; acc.w += v0.w + v1.w;
    }
    if (e < end) {
        int s0 = g_esrc[e];
        float4 v0 = x4[(size_t)s0 * 32 + lane];
        acc.x += v0.x; acc.y += v0.y; acc.z += v0.z; acc.w += v0.w;
    }
    float iv = g_invc[warp];
    float4 o = make_float4(acc.x * iv, acc.y * iv, acc.z * iv, acc.w * iv);
    uint2 hi, lo;
    split4(o, hi, lo);
    *(uint2*)&g_a_hi[(size_t)warp * 256 + lane * 4] = hi;
    *(uint2*)&g_a_lo[(size_t)warp * 256 + lane * 4] = lo;
}

// ---------------- GEMM1 via mma.sync (bf16 3-pass split, cp.async pipe) ------
#define GA_H 0
#define GA_L 16384
#define GB_H 32768
#define GB_L 49152
#define BUF1 65536
#define DYN_SMEM1 (2 * BUF1)

__global__ void __launch_bounds__(256, 1) k_gemm1_mma(const float* __restrict__ b1) {
    extern __shared__ char dsm[];
    int tid = threadIdx.x;
    int wid = tid >> 5;
    int lane = tid & 31;
    int bm = blockIdx.x * 128;
    int bn = blockIdx.y * 128;
    uint32_t dynb = smem_u32(dsm);

    int warp_m = (wid & 3) * 32;
    int warp_n = (wid >> 2) * 64;

    uint32_t offA[2][4], offB[4][4];
    {
        int mat = lane >> 3, rr = lane & 7;
#pragma unroll
        for (int i = 0; i < 2; i++)
#pragma unroll
            for (int j = 0; j < 4; j++) {
                int row = warp_m + i * 16 + ((mat & 1) << 3) + rr;
                int kb  = j * 16 + ((mat >> 1) << 3);
                offA[i][j] = SW128(row * 128 + kb * 2);
            }
#pragma unroll
        for (int q = 0; q < 4; q++)
#pragma unroll
            for (int j = 0; j < 4; j++) {
                int n  = warp_n + q * 16 + ((mat & 2) << 2) + rr;
                int kb = j * 16 + ((mat & 1) << 3);
                offB[q][j] = SW128(n * 128 + kb * 2);
            }
    }

    float acc[2][8][4];
#pragma unroll
    for (int i = 0; i < 2; i++)
#pragma unroll
        for (int jn = 0; jn < 8; jn++)
#pragma unroll
            for (int t = 0; t < 4; t++) acc[i][jn][t] = 0.f;

#define STAGE1(K0, BUFO) do {                                                      \
    _Pragma("unroll")                                                              \
    for (int it = 0; it < 4; it++) {                                               \
        int idx = tid + it * 256;                                                  \
        int row = idx >> 3, seg = idx & 7;                                         \
        int grow = bm + row;                                                       \
        int cl = grow < NN ? grow : (NN - 1);                                      \
        int sz = grow < NN ? 16 : 0;                                               \
        size_t boff = ((size_t)cl * 256 + (K0) + seg * 8) * 2;                     \
        int so = SW128(row * 128 + seg * 16);                                      \
        cp_async16(dynb + (BUFO) + GA_H + so, (const char*)g_a_hi + boff, sz);     \
        cp_async16(dynb + (BUFO) + GA_L + so, (const char*)g_a_lo + boff, sz);     \
    }                                                                              \
    _Pragma("unroll")                                                              \
    for (int it = 0; it < 4; it++) {                                               \
        int idx = tid + it * 256;                                                  \
        int row = idx >> 3, seg = idx & 7;                                         \
        size_t boff = ((size_t)(bn + row) * 256 + (K0) + seg * 8) * 2;             \
        int so = SW128(row * 128 + seg * 16);                                      \
        cp_async16(dynb + (BUFO) + GB_H + so, (const char*)g_w1hi + boff, 16);     \
        cp_async16(dynb + (BUFO) + GB_L + so, (const char*)g_w1lo + boff, 16);     \
    }                                                                              \
} while (0)

    STAGE1(0, 0);     CP_COMMIT();
    STAGE1(64, BUF1); CP_COMMIT();

    for (int kc = 0; kc < 4; kc++) {
        uint32_t bufo = (kc & 1) ? BUF1 : 0;
        CP_WAIT1();
        __syncthreads();
#pragma unroll
        for (int j = 0; j < 4; j++) {
            uint32_t ah[2][4], al[2][4], bh[4][4], bl[4][4];
#pragma unroll
            for (int i = 0; i < 2; i++) {
                LDSM4(ah[i], dynb + bufo + GA_H + offA[i][j]);
                LDSM4(al[i], dynb + bufo + GA_L + offA[i][j]);
            }
#pragma unroll
            for (int q = 0; q < 4; q++) {
                LDSM4(bh[q], dynb + bufo + GB_H + offB[q][j]);
                LDSM4(bl[q], dynb + bufo + GB_L + offB[q][j]);
            }
#pragma unroll
            for (int i = 0; i < 2; i++)
#pragma unroll
                for (int jn = 0; jn < 8; jn++) {
                    int q = jn >> 1, hsel = (jn & 1) * 2;
                    uint32_t bh0 = bh[q][hsel], bh1 = bh[q][hsel + 1];
                    uint32_t bl0 = bl[q][hsel], bl1 = bl[q][hsel + 1];
                    mma16816(acc[i][jn], ah[i], bh0, bh1);
                    mma16816(acc[i][jn], ah[i], bl0, bl1);
                    mma16816(acc[i][jn], al[i], bh0, bh1);
                }
        }
        __syncthreads();
        if (kc < 2) STAGE1((kc + 2) * 64, bufo);
        CP_COMMIT();
    }
#undef STAGE1

    int r0 = bm + warp_m + (lane >> 2);
    int c0 = bn + warp_n + 2 * (lane & 3);
#pragma unroll
    for (int i = 0; i < 2; i++) {
        int row = r0 + i * 16;
#pragma unroll
        for (int jn = 0; jn < 8; jn++) {
            int col = c0 + jn * 8;
            float bx = b1[col], by = b1[col + 1];
            if (row < NN) {
                float vx = acc[i][jn][0] + bx; vx = vx > 0.f ? vx : 0.f;
                float vy = acc[i][jn][1] + by; vy = vy > 0.f ? vy : 0.f;
                uint32_t hi, lo;
                split2(vx, vy, hi, lo);
                *(uint32_t*)&g_hhi[(size_t)row * 256 + col] = hi;
                *(uint32_t*)&g_hlo[(size_t)row * 256 + col] = lo;
            }
            if (row + 8 < NN) {
                float vx = acc[i][jn][2] + bx; vx = vx > 0.f ? vx : 0.f;
                float vy = acc[i][jn][3] + by; vy = vy > 0.f ? vy : 0.f;
                uint32_t hi, lo;
                split2(vx, vy, hi, lo);
                *(uint32_t*)&g_hhi[(size_t)(row + 8) * 256 + col] = hi;
                *(uint32_t*)&g_hlo[(size_t)(row + 8) * 256 + col] = lo;
            }
        }
    }
}

// ---------------- GEMM2 via mma.sync (cp.async pipe) -------------------------
#define G2A_H 0
#define G2A_L 16384
#define G2B_H 32768
#define G2B_L 43008
#define BUF2 53248
#define DYN_SMEM2 (2 * BUF2)

__global__ void __launch_bounds__(256, 1) k_gemm2_mma(const float* __restrict__ b2) {
    extern __shared__ char dsm[];
    int tid = threadIdx.x;
    int wid = tid >> 5;
    int lane = tid & 31;
    int bm = blockIdx.x * 128;
    uint32_t dynb = smem_u32(dsm);

    int warp_m = wid * 16;

    uint32_t offA[4], offB[5][4];
    {
        int mat = lane >> 3, rr = lane & 7;
#pragma unroll
        for (int j = 0; j < 4; j++) {
            int row = warp_m + ((mat & 1) << 3) + rr;
            int kb  = j * 16 + ((mat >> 1) << 3);
            offA[j] = SW128(row * 128 + kb * 2);
        }
#pragma unroll
        for (int q = 0; q < 5; q++)
#pragma unroll
            for (int j = 0; j < 4; j++) {
                int n  = q * 16 + ((mat & 2) << 2) + rr;
                int kb = j * 16 + ((mat & 1) << 3);
                offB[q][j] = SW128(n * 128 + kb * 2);
            }
    }

    float acc[10][4];
#pragma unroll
    for (int jn = 0; jn < 10; jn++)
#pragma unroll
        for (int t = 0; t < 4; t++) acc[jn][t] = 0.f;

#define STAGE2(K0, BUFO) do {                                                      \
    _Pragma("unroll")                                                              \
    for (int it = 0; it < 4; it++) {                                               \
        int idx = tid + it * 256;                                                  \
        int row = idx >> 3, seg = idx & 7;                                         \
        int grow = bm + row;                                                       \
        int cl = grow < NN ? grow : (NN - 1);                                      \
        int sz = grow < NN ? 16 : 0;                                               \
        size_t boff = ((size_t)cl * 256 + (K0) + seg * 8) * 2;                     \
        int so = SW128(row * 128 + seg * 16);                                      \
        cp_async16(dynb + (BUFO) + G2A_H + so, (const char*)g_hhi + boff, sz);     \
        cp_async16(dynb + (BUFO) + G2A_L + so, (const char*)g_hlo + boff, sz);     \
    }                                                                              \
    _Pragma("unroll")                                                              \
    for (int it = 0; it < 3; it++) {                                               \
        int idx = tid + it * 256;                                                  \
        if (idx < 640) {                                                           \
            int row = idx >> 3, seg = idx & 7;                                     \
            size_t boff = ((size_t)row * 256 + (K0) + seg * 8) * 2;                \
            int so = SW128(row * 128 + seg * 16);                                  \
            cp_async16(dynb + (BUFO) + G2B_H + so, (const char*)g_w2hi + boff, 16);\
            cp_async16(dynb + (BUFO) + G2B_L + so, (const char*)g_w2lo + boff, 16);\
        }                                                                          \
    }                                                                              \
} while (0)

    STAGE2(0, 0);     CP_COMMIT();
    STAGE2(64, BUF2); CP_COMMIT();

    for (int kc = 0; kc < 4; kc++) {
        uint32_t bufo = (kc & 1) ? BUF2 : 0;
        CP_WAIT1();
        __syncthreads();
#pragma unroll
        for (int j = 0; j < 4; j++) {
            uint32_t ah[4], al[4], bh[5][4], bl[5][4];
            LDSM4(ah, dynb + bufo + G2A_H + offA[j]);
            LDSM4(al, dynb + bufo + G2A_L + offA[j]);
#pragma unroll
            for (int q = 0; q < 5; q++) {
                LDSM4(bh[q], dynb + bufo + G2B_H + offB[q][j]);
                LDSM4(bl[q], dynb + bufo + G2B_L + offB[q][j]);
            }
#pragma unroll
            for (int jn = 0; jn < 10; jn++) {
                int q = jn >> 1, hsel = (jn & 1) * 2;
                uint32_t bh0 = bh[q][hsel], bh1 = bh[q][hsel + 1];
                uint32_t bl0 = bl[q][hsel], bl1 = bl[q][hsel + 1];
                mma16816(acc[jn], ah, bh0, bh1);
                mma16816(acc[jn], ah, bl0, bl1);
                mma16816(acc[jn], al, bh0, bh1);
            }
        }
        __syncthreads();
        if (kc < 2) STAGE2((kc + 2) * 64, bufo);
        CP_COMMIT();
    }
#undef STAGE2

    int r0 = bm + warp_m + (lane >> 2);
    int c0 = 2 * (lane & 3);
#pragma unroll
    for (int jn = 0; jn < 10; jn++) {
        int col = c0 + jn * 8;
#pragma unroll
        for (int half = 0; half < 2; half++) {
            int row = r0 + half * 8;
            if (row < NN) {
                float vx = acc[jn][half * 2 + 0];
                float vy = acc[jn][half * 2 + 1];
                if (col < 40) {
                    float2 v = make_float2(vx, vy);
                    *(float2*)&g_p[(size_t)row * 40 + col] = v;
                } else {
                    float2 v = make_float2(vx + b2[col - 40], vy + b2[col - 39]);
                    *(float2*)&g_r[(size_t)row * 40 + (col - 40)] = v;
                }
            }
        }
    }
}

// ---------------- layer-2 aggregation + log_softmax --------------------------
__global__ void k_agg2_lsm(float* __restrict__ out) {
    int warp = (blockIdx.x * blockDim.x + threadIdx.x) >> 5;
    if (warp >= NN) return;
    int lane = threadIdx.x & 31;
    int beg = g_offsets[warp], end = g_offsets[warp + 1];
    bool h1 = lane < 8;
    float a0 = 0.f, a1 = 0.f;
    for (int e = beg; e < end; e++) {
        int s = g_esrc[e];
        const float* ps = g_p + (size_t)s * 40;
        a0 += ps[lane];
        if (h1) a1 += ps[32 + lane];
    }
    float iv = g_invc[warp];
    float v0 = a0 * iv + g_r[(size_t)warp * 40 + lane];
    float v1 = h1 ? (a1 * iv + g_r[(size_t)warp * 40 + 32 + lane]) : -3.0e38f;

    float m = fmaxf(v0, v1);
#pragma unroll
    for (int off = 16; off; off >>= 1)
        m = fmaxf(m, __shfl_xor_sync(0xffffffffu, m, off));
    float ssum = expf(v0 - m) + (h1 ? expf(v1 - m) : 0.f);
#pragma unroll
    for (int off = 16; off; off >>= 1)
        ssum += __shfl_xor_sync(0xffffffffu, ssum, off);
    float lse = m + logf(ssum);

    out[(size_t)warp * 40 + lane] = v0 - lse;
    if (h1) out[(size_t)warp * 40 + 32 + lane] = v1 - lse;
}

// ---------------- launch -----------------------------------------------------
extern "C" void kernel_launch(void* const* d_in, const int* in_sizes, int n_in,
                              void* d_out, int out_size) {
    const float* x   = (const float*)d_in[0];
    const void*  ei  = d_in[1];
    const float* W1l = (const float*)d_in[2];
    const float* W1r = (const float*)d_in[3];
    const float* b1  = (const float*)d_in[4];
    const float* W2l = (const float*)d_in[5];
    const float* W2r = (const float*)d_in[6];
    const float* b2  = (const float*)d_in[7];
    float* out = (float*)d_out;

    cudaFuncSetAttribute(k_gemm1_mma, cudaFuncAttributeMaxDynamicSharedMemorySize,
                         DYN_SMEM1);
    cudaFuncSetAttribute(k_gemm2_mma, cudaFuncAttributeMaxDynamicSharedMemorySize,
                         DYN_SMEM2);

    k_init<<<1 + NB, 256>>>((const int*)ei);
    k_count_prep<<<CPB_X, 256>>>(ei, W1l, W1r, W2l, W2r, x);
    k_scan<<<NB, 256>>>();
    k_scatter<<<(NE + 255) / 256, 256>>>(ei);
    k_agg1<<<(NN + 7) / 8, 256>>>(x);
    dim3 g1((NN + 127) / 128, 2);
    k_gemm1_mma<<<g1, 256, DYN_SMEM1>>>(b1);
    k_gemm2_mma<<<(NN + 127) / 128, 256, DYN_SMEM2>>>(b2);
    k_agg2_lsm<<<(NN + 7) / 8, 256>>>(out);
}

// round 12
// speedup vs baseline: 1.1738x; 1.0918x over previous
#include <cuda_runtime.h>
#include <cuda_bf16.h>
#include <math.h>
#include <cstdint>

#define NN   50000
#define NE   800000
#define IND  128
#define HID  256
#define OUTD 40
#define NB   ((NN + 255) / 256)   // 196 scan blocks

// ---------------- scratch ----------------------------------------------------
__device__ int   g_is64;
__device__ int   g_counts[NN];
__device__ int   g_offsets[NN + 1];
__device__ int   g_rank[NE];
__device__ int   g_esrc[NE];
__device__ float g_invc[NN];
__device__ int   g_bsum[NB];
__device__ int   g_done1 = 0;
__device__ int   g_done2 = 0;
__device__ __align__(16) __nv_bfloat16 g_a_hi[(size_t)NN * HID];  // [agg|x] hi
__device__ __align__(16) __nv_bfloat16 g_a_lo[(size_t)NN * HID];  // [agg|x] lo
__device__ __align__(16) __nv_bfloat16 g_w1hi[(size_t)HID * HID]; // W1^T hi [n][k]
__device__ __align__(16) __nv_bfloat16 g_w1lo[(size_t)HID * HID]; // W1^T lo [n][k]
__device__ __align__(16) __nv_bfloat16 g_w2hi[(size_t)80 * HID];  // W2^T hi [80][256]
__device__ __align__(16) __nv_bfloat16 g_w2lo[(size_t)80 * HID];  // W2^T lo
__device__ __align__(16) float g_p[(size_t)NN * OUTD];
__device__ __align__(16) float g_r[(size_t)NN * OUTD];

// ---------------- helpers ----------------------------------------------------
__device__ __forceinline__ uint32_t smem_u32(const void* p) {
    uint32_t a;
    asm("{ .reg .u64 t; cvta.to.shared.u64 t, %1; cvt.u32.u64 %0, t; }"
        : "=r"(a) : "l"(p));
    return a;
}

#define SW128(o) ((o) ^ (((o) >> 3) & 0x70))

#define LDSM4(R, ADDR)                                                           \
    asm volatile("ldmatrix.sync.aligned.m8n8.x4.shared.b16 {%0,%1,%2,%3}, [%4];" \
        : "=r"((R)[0]), "=r"((R)[1]), "=r"((R)[2]), "=r"((R)[3]) : "r"(ADDR))

__device__ __forceinline__ void mma16816(float* c, const uint32_t* a,
                                         uint32_t b0, uint32_t b1) {
    asm volatile(
        "mma.sync.aligned.m16n8k16.row.col.f32.bf16.bf16.f32 "
        "{%0,%1,%2,%3}, {%4,%5,%6,%7}, {%8,%9}, {%0,%1,%2,%3};"
        : "+f"(c[0]), "+f"(c[1]), "+f"(c[2]), "+f"(c[3])
        : "r"(a[0]), "r"(a[1]), "r"(a[2]), "r"(a[3]), "r"(b0), "r"(b1));
}

__device__ __forceinline__ void cp_async16(uint32_t dst, const void* src, int srcsz) {
    asm volatile("cp.async.cg.shared.global [%0], [%1], 16, %2;"
                 :: "r"(dst), "l"(src), "r"(srcsz) : "memory");
}
#define CP_COMMIT() asm volatile("cp.async.commit_group;" ::: "memory")
#define CP_WAIT1()  asm volatile("cp.async.wait_group 1;" ::: "memory")
#define CP_WAIT0()  asm volatile("cp.async.wait_group 0;" ::: "memory")

__device__ __forceinline__ int edge_at(const void* ei, int idx) {
    if (g_is64) return (int)((const long long*)ei)[idx];
    return ((const int*)ei)[idx];
}

// ---------------- bf16 split helpers -----------------------------------------
__device__ __forceinline__ void split4(float4 v, uint2& hi, uint2& lo) {
    __nv_bfloat16 h0 = __float2bfloat16(v.x);
    __nv_bfloat16 h1 = __float2bfloat16(v.y);
    __nv_bfloat16 h2 = __float2bfloat16(v.z);
    __nv_bfloat16 h3 = __float2bfloat16(v.w);
    __nv_bfloat16 l0 = __float2bfloat16(v.x - __bfloat162float(h0));
    __nv_bfloat16 l1 = __float2bfloat16(v.y - __bfloat162float(h1));
    __nv_bfloat16 l2 = __float2bfloat16(v.z - __bfloat162float(h2));
    __nv_bfloat16 l3 = __float2bfloat16(v.w - __bfloat162float(h3));
    hi.x = (uint32_t)__bfloat16_as_ushort(h0) | ((uint32_t)__bfloat16_as_ushort(h1) << 16);
    hi.y = (uint32_t)__bfloat16_as_ushort(h2) | ((uint32_t)__bfloat16_as_ushort(h3) << 16);
    lo.x = (uint32_t)__bfloat16_as_ushort(l0) | ((uint32_t)__bfloat16_as_ushort(l1) << 16);
    lo.y = (uint32_t)__bfloat16_as_ushort(l2) | ((uint32_t)__bfloat16_as_ushort(l3) << 16);
}

__device__ __forceinline__ void split2(float x, float y, uint32_t& hi, uint32_t& lo) {
    __nv_bfloat16 hx = __float2bfloat16(x), hy = __float2bfloat16(y);
    __nv_bfloat16 lx = __float2bfloat16(x - __bfloat162float(hx));
    __nv_bfloat16 ly = __float2bfloat16(y - __bfloat162float(hy));
    hi = (uint32_t)__bfloat16_as_ushort(hx) | ((uint32_t)__bfloat16_as_ushort(hy) << 16);
    lo = (uint32_t)__bfloat16_as_ushort(lx) | ((uint32_t)__bfloat16_as_ushort(ly) << 16);
}

// ---------------- k_init: detect (block 0) + zero counts ---------------------
__global__ void k_init(const int* __restrict__ ei32) {
    int b = blockIdx.x;
    int tid = threadIdx.x;
    if (b == 0) {
        __shared__ int bad;
        if (tid == 0) bad = 0;
        __syncthreads();
        if (ei32[2 * tid + 1] != 0) atomicOr(&bad, 1);
        __syncthreads();
        if (tid == 0) g_is64 = bad ? 0 : 1;
    } else {
        int i = (b - 1) * 256 + tid;
        if (i < NN) g_counts[i] = 0;
    }
}

// ---------------- k_count_prep: edge count+rank ∥ W1/W2/x bf16-split ---------
#define CPB_COUNT 3125
#define CPB_W1    (CPB_COUNT + 256)
#define CPB_W2    (CPB_W1 + 80)
#define CPB_X     (CPB_W2 + 6250)

__global__ void k_count_prep(const void* __restrict__ ei,
                             const float* __restrict__ W1l, const float* __restrict__ W1r,
                             const float* __restrict__ W2l, const float* __restrict__ W2r,
                             const float* __restrict__ x) {
    int b = blockIdx.x;
    int tid = threadIdx.x;
    if (b < CPB_COUNT) {
        int e = b * 256 + tid;
        if (e < NE) {
            int d = edge_at(ei, NE + e);
            g_rank[e] = atomicAdd(&g_counts[d], 1);
        }
    } else if (b < CPB_W1) {
        int idx = (b - CPB_COUNT) * 256 + tid;
        int n = idx >> 8, k = idx & 255;
        float w = (k < 128) ? W1l[(size_t)k * 256 + n]
                            : W1r[(size_t)(k - 128) * 256 + n];
        __nv_bfloat16 h = __float2bfloat16(w);
        __nv_bfloat16 l = __float2bfloat16(w - __bfloat162float(h));
        g_w1hi[(size_t)n * 256 + k] = h;
        g_w1lo[(size_t)n * 256 + k] = l;
    } else if (b < CPB_W2) {
        int idx = (b - CPB_W1) * 256 + tid;
        int n = idx >> 8, k = idx & 255;
        float w = (n < 40) ? W2l[(size_t)k * 40 + n]
                           : W2r[(size_t)k * 40 + (n - 40)];
        __nv_bfloat16 h = __float2bfloat16(w);
        __nv_bfloat16 l = __float2bfloat16(w - __bfloat162float(h));
        g_w2hi[(size_t)n * 256 + k] = h;
        g_w2lo[(size_t)n * 256 + k] = l;
    } else {
        int idx = (b - CPB_W2) * 256 + tid;
        if (idx >= NN * 32) return;
        int row = idx >> 5, c4 = idx & 31;
        float4 v = ((const float4*)x)[(size_t)row * 32 + c4];
        uint2 hi, lo;
        split4(v, hi, lo);
        *(uint2*)&g_a_hi[(size_t)row * 256 + 128 + c4 * 4] = hi;
        *(uint2*)&g_a_lo[(size_t)row * 256 + 128 + c4 * 4] = lo;
    }
}

// ---------------- k_scan: fused hierarchical scan ----------------------------
__device__ __forceinline__ int block_excl_scan(int c, int t) {
    int lane = t & 31, w = t >> 5;
    int v = c;
#pragma unroll
    for (int off = 1; off < 32; off <<= 1) {
        int n = __shfl_up_sync(0xffffffffu, v, off);
        if (lane >= off) v += n;
    }
    __shared__ int ws[8];
    if (lane == 31) ws[w] = v;
    __syncthreads();
    if (w == 0 && lane < 8) {
        int s = ws[lane];
#pragma unroll
        for (int off = 1; off < 8; off <<= 1) {
            int n = __shfl_up_sync(0x000000ffu, s, off);
            if (lane >= off) s += n;
        }
        ws[lane] = s;
    }
    __syncthreads();
    return v - c + (w > 0 ? ws[w - 1] : 0);
}

__global__ void k_scan() {
    int b = blockIdx.x, tid = threadIdx.x;
    int i = b * 256 + tid;
    int c = (i < NN) ? g_counts[i] : 0;
    int e = block_excl_scan(c, tid);

    if (tid == 255) {
        g_bsum[b] = e + c;
        __threadfence();
        atomicAdd(&g_done1, 1);
    }
    if (tid == 0) {
        while (*(volatile int*)&g_done1 < NB) {}
    }
    __syncthreads();
    __threadfence();

    int v = (tid < b) ? g_bsum[tid] : 0;
    int lane = tid & 31, w = tid >> 5;
#pragma unroll
    for (int off = 16; off; off >>= 1) v += __shfl_xor_sync(0xffffffffu, v, off);
    __shared__ int rs[8];
    if (lane == 0) rs[w] = v;
    __syncthreads();
    __shared__ int pre;
    if (tid == 0) {
        int s = 0;
#pragma unroll
        for (int k = 0; k < 8; k++) s += rs[k];
        pre = s;
    }
    __syncthreads();

    if (i < NN) {
        g_offsets[i] = pre + e;
        g_invc[i]    = 1.0f / (float)(c > 1 ? c : 1);
    }
    if (b == NB - 1 && tid == 255) g_offsets[NN] = NE;

    if (tid == 0) {
        int t2 = atomicAdd(&g_done2, 1);
        if (t2 == NB - 1) { g_done1 = 0; g_done2 = 0; }
    }
}

// ---------------- k_scatter: atomic-free via precomputed rank ----------------
__global__ void k_scatter(const void* __restrict__ ei) {
    int e = blockIdx.x * blockDim.x + threadIdx.x;
    if (e < NE) {
        int s = edge_at(ei, e);
        int d = edge_at(ei, NE + e);
        g_esrc[g_offsets[d] + g_rank[e]] = s;
    }
}

// ---------------- layer-1 aggregation (bf16 hi/lo cols 0..127) ---------------
__global__ void k_agg1(const float* __restrict__ x) {
    int warp = (blockIdx.x * blockDim.x + threadIdx.x) >> 5;
    if (warp >= NN) return;
    int lane = threadIdx.x & 31;
    int beg = g_offsets[warp], end = g_offsets[warp + 1];
    const float4* __restrict__ x4 = (const float4*)x;
    float4 acc = make_float4(0.f, 0.f, 0.f, 0.f);
    int e = beg;
    for (; e + 1 < end; e += 2) {
        int s0 = g_esrc[e];
        int s1 = g_esrc[e + 1];
        float4 v0 = x4[(size_t)s0 * 32 + lane];
        float4 v1 = x4[(size_t)s1 * 32 + lane];
        acc.x += v0.x + v1.x; acc.y += v0.y + v1.y;
        acc.z += v0.z + v1.z; acc.w += v0.w + v1.w;
    }
    if (e < end) {
        int s0 = g_esrc[e];
        float4 v0 = x4[(size_t)s0 * 32 + lane];
        acc.x += v0.x; acc.y += v0.y; acc.z += v0.z; acc.w += v0.w;
    }
    float iv = g_invc[warp];
    float4 o = make_float4(acc.x * iv, acc.y * iv, acc.z * iv, acc.w * iv);
    uint2 hi, lo;
    split4(o, hi, lo);
    *(uint2*)&g_a_hi[(size_t)warp * 256 + lane * 4] = hi;
    *(uint2*)&g_a_lo[(size_t)warp * 256 + lane * 4] = lo;
}

// ---------------- MEGA kernel: gemm1 (BN=256) + gemm2 fused ------------------
// 512 threads, grid 391. Phase 1: h = relu(A@W1^T+b1) -> smem (bf16 hi/lo).
// Phase 2: [p|r] = h @ W2^T from smem.
// gemm1 smem: 2 bufs x (A 32KB + B 64KB) = 192KB
// gemm2 smem: h 128KB + W2 (88-row pad, 4 chunks) 88KB = 216KB
#define MB_A_HI 0
#define MB_A_LO 16384
#define MB_B_HI 32768
#define MB_B_LO 65536
#define MBUF    98304
#define MH_HI   0
#define MH_LO   65536
#define MB2_HI  131072
#define MB2_CH  11264          // 88 rows * 128B per chunk
#define MB2_LO  (MB2_HI + 4 * MB2_CH)   // 176128
#define DYN_SMEMM (MB2_LO + 4 * MB2_CH) // 221184

__global__ void __launch_bounds__(512, 1) k_mega(const float* __restrict__ b1,
                                                 const float* __restrict__ b2) {
    extern __shared__ char dsm[];
    int tid = threadIdx.x;
    int wid = tid >> 5;          // 0..15
    int lane = tid & 31;
    int bm = blockIdx.x * 128;
    uint32_t dynb = smem_u32(dsm);

    // ===== phase 1: gemm1, warp tile 32x64, 4x4 warps over 128x256 =====
    int warp_m = (wid & 3) * 32;
    int warp_n = (wid >> 2) * 64;

    uint32_t offA[2][4], offB[4][4];
    {
        int mat = lane >> 3, rr = lane & 7;
#pragma unroll
        for (int i = 0; i < 2; i++)
#pragma unroll
            for (int j = 0; j < 4; j++) {
                int row = warp_m + i * 16 + ((mat & 1) << 3) + rr;
                int kb  = j * 16 + ((mat >> 1) << 3);
                offA[i][j] = SW128(row * 128 + kb * 2);
            }
#pragma unroll
        for (int q = 0; q < 4; q++)
#pragma unroll
            for (int j = 0; j < 4; j++) {
                int n  = warp_n + q * 16 + ((mat & 2) << 2) + rr;
                int kb = j * 16 + ((mat & 1) << 3);
                offB[q][j] = SW128(n * 128 + kb * 2);
            }
    }

    float acc[2][8][4];
#pragma unroll
    for (int i = 0; i < 2; i++)
#pragma unroll
        for (int jn = 0; jn < 8; jn++)
#pragma unroll
            for (int t = 0; t < 4; t++) acc[i][jn][t] = 0.f;

#define STAGEM(K0, BUFO) do {                                                      \
    _Pragma("unroll")                                                              \
    for (int it = 0; it < 2; it++) {                                               \
        int idx = tid + it * 512;                                                  \
        int row = idx >> 3, seg = idx & 7;                                         \
        int grow = bm + row;                                                       \
        int cl = grow < NN ? grow : (NN - 1);                                      \
        int sz = grow < NN ? 16 : 0;                                               \
        size_t boff = ((size_t)cl * 256 + (K0) + seg * 8) * 2;                     \
        int so = SW128(row * 128 + seg * 16);                                      \
        cp_async16(dynb + (BUFO) + MB_A_HI + so, (const char*)g_a_hi + boff, sz);  \
        cp_async16(dynb + (BUFO) + MB_A_LO + so, (const char*)g_a_lo + boff, sz);  \
    }                                                                              \
    _Pragma("unroll")                                                              \
    for (int it = 0; it < 4; it++) {                                               \
        int idx = tid + it * 512;                                                  \
        int row = idx >> 3, seg = idx & 7;                                         \
        size_t boff = ((size_t)row * 256 + (K0) + seg * 8) * 2;                    \
        int so = SW128(row * 128 + seg * 16);                                      \
        cp_async16(dynb + (BUFO) + MB_B_HI + so, (const char*)g_w1hi + boff, 16);  \
        cp_async16(dynb + (BUFO) + MB_B_LO + so, (const char*)g_w1lo + boff, 16);  \
    }                                                                              \
} while (0)

    STAGEM(0, 0);     CP_COMMIT();
    STAGEM(64, MBUF); CP_COMMIT();

    for (int kc = 0; kc < 4; kc++) {
        uint32_t bufo = (kc & 1) ? MBUF : 0;
        CP_WAIT1();
        __syncthreads();
#pragma unroll
        for (int j = 0; j < 4; j++) {
            uint32_t ah[2][4], al[2][4];
#pragma unroll
            for (int i = 0; i < 2; i++) {
                LDSM4(ah[i], dynb + bufo + MB_A_HI + offA[i][j]);
                LDSM4(al[i], dynb + bufo + MB_A_LO + offA[i][j]);
            }
#pragma unroll
            for (int q = 0; q < 4; q++) {
                uint32_t bh[4], bl[4];
                LDSM4(bh, dynb + bufo + MB_B_HI + offB[q][j]);
                LDSM4(bl, dynb + bufo + MB_B_LO + offB[q][j]);
#pragma unroll
                for (int i = 0; i < 2; i++)
#pragma unroll
                    for (int hsel = 0; hsel < 2; hsel++) {
                        int jn = q * 2 + hsel;
                        uint32_t b0 = bh[hsel * 2], b1v = bh[hsel * 2 + 1];
                        uint32_t c0v = bl[hsel * 2], c1v = bl[hsel * 2 + 1];
                        mma16816(acc[i][jn], ah[i], b0, b1v);
                        mma16816(acc[i][jn], ah[i], c0v, c1v);
                        mma16816(acc[i][jn], al[i], b0, b1v);
                    }
            }
        }
        __syncthreads();
        if (kc < 2) STAGEM((kc + 2) * 64, bufo);
        CP_COMMIT();
    }
#undef STAGEM

    // ===== phase 1 epilogue: h -> smem (bf16 hi/lo, 4 swizzled k-chunks) =====
    // also stage W2 (B2) concurrently + zero its 8 pad rows per chunk
    {
        // zero pad rows 80..87 of each chunk/split: 4*2*1024B = 512 uint4
        int sp = tid >> 8, rem = tid & 255;
        int kcz = rem >> 6, q4 = rem & 63;
        uint32_t base = sp ? MB2_LO : MB2_HI;
        *(uint4*)(dsm + base + kcz * MB2_CH + 80 * 128 + q4 * 16) =
            make_uint4(0, 0, 0, 0);
        // stage 80 rows x 8 segs x 4 chunks x 2 splits = 5120 segs
#pragma unroll
        for (int it = 0; it < 10; it++) {
            int idx = tid + it * 512;
            int split = idx / 2560;
            int rem2 = idx - split * 2560;
            int kc2 = rem2 / 640;
            int rr2 = rem2 - kc2 * 640;
            int row = rr2 >> 3, seg = rr2 & 7;
            const char* src = (split ? (const char*)g_w2lo : (const char*)g_w2hi)
                              + ((size_t)row * 256 + kc2 * 64 + seg * 8) * 2;
            uint32_t dst = dynb + (split ? MB2_LO : MB2_HI) + kc2 * MB2_CH
                           + SW128(row * 128 + seg * 16);
            cp_async16(dst, src, 16);
        }
        CP_COMMIT();
    }

    {
        int r0l = warp_m + (lane >> 2);
        int c0l = warp_n + 2 * (lane & 3);
#pragma unroll
        for (int i = 0; i < 2; i++) {
#pragma unroll
            for (int jn = 0; jn < 8; jn++) {
                int col = c0l + jn * 8;
                int kc = col >> 6, kin = col & 63;
                float bx = b1[col], by = b1[col + 1];
                {
                    int r = r0l + i * 16;
                    float vx = acc[i][jn][0] + bx; vx = vx > 0.f ? vx : 0.f;
                    float vy = acc[i][jn][1] + by; vy = vy > 0.f ? vy : 0.f;
                    uint32_t hi, lo;
                    split2(vx, vy, hi, lo);
                    int so = kc * 16384 + SW128(r * 128 + kin * 2);
                    *(uint32_t*)(dsm + MH_HI + so) = hi;
                    *(uint32_t*)(dsm + MH_LO + so) = lo;
                }
                {
                    int r = r0l + i * 16 + 8;
                    float vx = acc[i][jn][2] + bx; vx = vx > 0.f ? vx : 0.f;
                    float vy = acc[i][jn][3] + by; vy = vy > 0.f ? vy : 0.f;
                    uint32_t hi, lo;
                    split2(vx, vy, hi, lo);
                    int so = kc * 16384 + SW128(r * 128 + kin * 2);
                    *(uint32_t*)(dsm + MH_HI + so) = hi;
                    *(uint32_t*)(dsm + MH_LO + so) = lo;
                }
            }
        }
    }
    CP_WAIT0();
    __syncthreads();

    // ===== phase 2: gemm2 from smem. warp tile 16x40, 8x2 warps ==============
    int warp_m2 = (wid & 7) * 16;
    int warp_n2 = (wid >> 3) * 40;

    uint32_t offA2[4], offB2[3][4];
    {
        int mat = lane >> 3, rr = lane & 7;
#pragma unroll
        for (int jj = 0; jj < 4; jj++) {
            int row = warp_m2 + ((mat & 1) << 3) + rr;
            int kb  = jj * 16 + ((mat >> 1) << 3);
            offA2[jj] = SW128(row * 128 + kb * 2);
        }
#pragma unroll
        for (int q = 0; q < 3; q++)
#pragma unroll
            for (int jj = 0; jj < 4; jj++) {
                int n  = warp_n2 + q * 16 + ((mat & 2) << 2) + rr;
                int kb = jj * 16 + ((mat & 1) << 3);
                offB2[q][jj] = SW128(n * 128 + kb * 2);
            }
    }

    float acc2[5][4];
#pragma unroll
    for (int jn = 0; jn < 5; jn++)
#pragma unroll
        for (int t = 0; t < 4; t++) acc2[jn][t] = 0.f;

#pragma unroll
    for (int j = 0; j < 16; j++) {
        int kc = j >> 2, jj = j & 3;
        uint32_t ah[4], al[4];
        LDSM4(ah, dynb + MH_HI + kc * 16384 + offA2[jj]);
        LDSM4(al, dynb + MH_LO + kc * 16384 + offA2[jj]);
#pragma unroll
        for (int q = 0; q < 3; q++) {
            uint32_t bh[4], bl[4];
            LDSM4(bh, dynb + MB2_HI + kc * MB2_CH + offB2[q][jj]);
            LDSM4(bl, dynb + MB2_LO + kc * MB2_CH + offB2[q][jj]);
#pragma unroll
            for (int h2 = 0; h2 < 2; h2++) {
                int jn = q * 2 + h2;
                if (jn < 5) {
                    uint32_t b0 = bh[h2 * 2], b1v = bh[h2 * 2 + 1];
                    uint32_t c0v = bl[h2 * 2], c1v = bl[h2 * 2 + 1];
                    mma16816(acc2[jn], ah, b0, b1v);
                    mma16816(acc2[jn], ah, c0v, c1v);
                    mma16816(acc2[jn], al, b0, b1v);
                }
            }
        }
    }

    // epilogue: cols<40 -> p (no bias), cols>=40 -> r (+b2)
    int r0 = bm + warp_m2 + (lane >> 2);
    int c0 = warp_n2 + 2 * (lane & 3);
#pragma unroll
    for (int jn = 0; jn < 5; jn++) {
        int col = c0 + jn * 8;
#pragma unroll
        for (int half = 0; half < 2; half++) {
            int row = r0 + half * 8;
            if (row < NN) {
                float vx = acc2[jn][half * 2 + 0];
                float vy = acc2[jn][half * 2 + 1];
                if (col < 40) {
                    *(float2*)&g_p[(size_t)row * 40 + col] = make_float2(vx, vy);
                } else {
                    float2 v = make_float2(vx + b2[col - 40], vy + b2[col - 39]);
                    *(float2*)&g_r[(size_t)row * 40 + (col - 40)] = v;
                }
            }
        }
    }
}

// ---------------- layer-2 aggregation + log_softmax --------------------------
__global__ void k_agg2_lsm(float* __restrict__ out) {
    int warp = (blockIdx.x * blockDim.x + threadIdx.x) >> 5;
    if (warp >= NN) return;
    int lane = threadIdx.x & 31;
    int beg = g_offsets[warp], end = g_offsets[warp + 1];
    bool h1 = lane < 8;
    float a0 = 0.f, a1 = 0.f;
    for (int e = beg; e < end; e++) {
        int s = g_esrc[e];
        const float* ps = g_p + (size_t)s * 40;
        a0 += ps[lane];
        if (h1) a1 += ps[32 + lane];
    }
    float iv = g_invc[warp];
    float v0 = a0 * iv + g_r[(size_t)warp * 40 + lane];
    float v1 = h1 ? (a1 * iv + g_r[(size_t)warp * 40 + 32 + lane]) : -3.0e38f;

    float m = fmaxf(v0, v1);
#pragma unroll
    for (int off = 16; off; off >>= 1)
        m = fmaxf(m, __shfl_xor_sync(0xffffffffu, m, off));
    float ssum = expf(v0 - m) + (h1 ? expf(v1 - m) : 0.f);
#pragma unroll
    for (int off = 16; off; off >>= 1)
        ssum += __shfl_xor_sync(0xffffffffu, ssum, off);
    float lse = m + logf(ssum);

    out[(size_t)warp * 40 + lane] = v0 - lse;
    if (h1) out[(size_t)warp * 40 + 32 + lane] = v1 - lse;
}

// ---------------- launch -----------------------------------------------------
extern "C" void kernel_launch(void* const* d_in, const int* in_sizes, int n_in,
                              void* d_out, int out_size) {
    const float* x   = (const float*)d_in[0];
    const void*  ei  = d_in[1];
    const float* W1l = (const float*)d_in[2];
    const float* W1r = (const float*)d_in[3];
    const float* b1  = (const float*)d_in[4];
    const float* W2l = (const float*)d_in[5];
    const float* W2r = (const float*)d_in[6];
    const float* b2  = (const float*)d_in[7];
    float* out = (float*)d_out;

    cudaFuncSetAttribute(k_mega, cudaFuncAttributeMaxDynamicSharedMemorySize,
                         DYN_SMEMM);

    k_init<<<1 + NB, 256>>>((const int*)ei);
    k_count_prep<<<CPB_X, 256>>>(ei, W1l, W1r, W2l, W2r, x);
    k_scan<<<NB, 256>>>();
    k_scatter<<<(NE + 255) / 256, 256>>>(ei);
    k_agg1<<<(NN + 7) / 8, 256>>>(x);
    k_mega<<<(NN + 127) / 128, 512, DYN_SMEMM>>>(b1, b2);
    k_agg2_lsm<<<(NN + 7) / 8, 256>>>(out);
}

// round 13
// speedup vs baseline: 1.3898x; 1.1840x over previous
#include <cuda_runtime.h>
#include <cuda_fp16.h>
#include <math.h>
#include <cstdint>

#define NN   50000
#define NE   800000
#define IND  128
#define HID  256
#define OUTD 40
#define NB   ((NN + 255) / 256)   // 196 scan blocks

// ---------------- scratch ----------------------------------------------------
__device__ int   g_counts[NN];          // zero at load; re-zeroed by agg2 tail
__device__ int   g_offsets[NN + 1];
__device__ int   g_rank[NE];
__device__ int   g_esrc[NE];
__device__ float g_invc[NN];
__device__ int   g_bsum[NB];
__device__ int   g_done1 = 0;
__device__ int   g_done2 = 0;
__device__ __align__(16) __half g_a_hi[(size_t)NN * HID];  // [agg|x] hi (fp16)
__device__ __align__(16) __half g_a_lo[(size_t)NN * HID];  // [agg|x] lo (fp16)
__device__ __align__(16) __half g_w1hi[(size_t)HID * HID]; // W1^T fp16 [n][k]
__device__ __align__(16) __half g_w2hi[(size_t)80 * HID];  // W2^T fp16 [80][256]
__device__ __align__(16) float g_p[(size_t)NN * OUTD];
__device__ __align__(16) float g_r[(size_t)NN * OUTD];

// ---------------- helpers ----------------------------------------------------
__device__ __forceinline__ uint32_t smem_u32(const void* p) {
    uint32_t a;
    asm("{ .reg .u64 t; cvta.to.shared.u64 t, %1; cvt.u32.u64 %0, t; }"
        : "=r"(a) : "l"(p));
    return a;
}

#define SW128(o) ((o) ^ (((o) >> 3) & 0x70))

#define LDSM4(R, ADDR)                                                           \
    asm volatile("ldmatrix.sync.aligned.m8n8.x4.shared.b16 {%0,%1,%2,%3}, [%4];" \
        : "=r"((R)[0]), "=r"((R)[1]), "=r"((R)[2]), "=r"((R)[3]) : "r"(ADDR))

__device__ __forceinline__ void mma16816(float* c, const uint32_t* a,
                                         uint32_t b0, uint32_t b1) {
    asm volatile(
        "mma.sync.aligned.m16n8k16.row.col.f32.f16.f16.f32 "
        "{%0,%1,%2,%3}, {%4,%5,%6,%7}, {%8,%9}, {%0,%1,%2,%3};"
        : "+f"(c[0]), "+f"(c[1]), "+f"(c[2]), "+f"(c[3])
        : "r"(a[0]), "r"(a[1]), "r"(a[2]), "r"(a[3]), "r"(b0), "r"(b1));
}

__device__ __forceinline__ void cp_async16(uint32_t dst, const void* src, int srcsz) {
    asm volatile("cp.async.cg.shared.global [%0], [%1], 16, %2;"
                 :: "r"(dst), "l"(src), "r"(srcsz) : "memory");
}
#define CP_COMMIT() asm volatile("cp.async.commit_group;" ::: "memory")
#define CP_WAIT1()  asm volatile("cp.async.wait_group 1;" ::: "memory")
#define CP_WAIT0()  asm volatile("cp.async.wait_group 0;" ::: "memory")

// per-block edge dtype detection: odd 32-bit words all zero over 32 samples
// <=> int64 (values < 50000 => high halves zero; int32 odd words are random
// src values, P(all 32 == 0) ~ (2e-5)^32).
__device__ __forceinline__ int detect_is64(const int* __restrict__ ei32) {
    __shared__ int s_is64;
    if (threadIdx.x < 32) {
        int v = ei32[2 * threadIdx.x + 1];
        unsigned b = __ballot_sync(0xffffffffu, v != 0);
        if (threadIdx.x == 0) s_is64 = (b == 0) ? 1 : 0;
    }
    __syncthreads();
    return s_is64;
}

__device__ __forceinline__ int edge_at(const void* ei, int idx, int is64) {
    if (is64) return (int)((const long long*)ei)[idx];
    return ((const int*)ei)[idx];
}

// ---------------- fp16 split helpers -----------------------------------------
__device__ __forceinline__ void split4h(float4 v, uint2& hi, uint2& lo) {
    __half h0 = __float2half_rn(v.x);
    __half h1 = __float2half_rn(v.y);
    __half h2 = __float2half_rn(v.z);
    __half h3 = __float2half_rn(v.w);
    __half l0 = __float2half_rn(v.x - __half2float(h0));
    __half l1 = __float2half_rn(v.y - __half2float(h1));
    __half l2 = __float2half_rn(v.z - __half2float(h2));
    __half l3 = __float2half_rn(v.w - __half2float(h3));
    hi.x = (uint32_t)__half_as_ushort(h0) | ((uint32_t)__half_as_ushort(h1) << 16);
    hi.y = (uint32_t)__half_as_ushort(h2) | ((uint32_t)__half_as_ushort(h3) << 16);
    lo.x = (uint32_t)__half_as_ushort(l0) | ((uint32_t)__half_as_ushort(l1) << 16);
    lo.y = (uint32_t)__half_as_ushort(l2) | ((uint32_t)__half_as_ushort(l3) << 16);
}

__device__ __forceinline__ void split2h(float x, float y, uint32_t& hi, uint32_t& lo) {
    __half hx = __float2half_rn(x), hy = __float2half_rn(y);
    __half lx = __float2half_rn(x - __half2float(hx));
    __half ly = __float2half_rn(y - __half2float(hy));
    hi = (uint32_t)__half_as_ushort(hx) | ((uint32_t)__half_as_ushort(hy) << 16);
    lo = (uint32_t)__half_as_ushort(lx) | ((uint32_t)__half_as_ushort(ly) << 16);
}

// ---------------- k_count_prep: edge count+rank ∥ W1/W2/x fp16 prep ----------
#define CPB_COUNT 3125
#define CPB_W1    (CPB_COUNT + 256)
#define CPB_W2    (CPB_W1 + 80)
#define CPB_X     (CPB_W2 + 6250)

__global__ void k_count_prep(const void* __restrict__ ei,
                             const float* __restrict__ W1l, const float* __restrict__ W1r,
                             const float* __restrict__ W2l, const float* __restrict__ W2r,
                             const float* __restrict__ x) {
    int b = blockIdx.x;
    int tid = threadIdx.x;
    if (b < CPB_COUNT) {
        int is64 = detect_is64((const int*)ei);
        int e = b * 256 + tid;
        if (e < NE) {
            int d = edge_at(ei, NE + e, is64);
            g_rank[e] = atomicAdd(&g_counts[d], 1);
        }
    } else if (b < CPB_W1) {
        int idx = (b - CPB_COUNT) * 256 + tid;
        int n = idx >> 8, k = idx & 255;
        float w = (k < 128) ? W1l[(size_t)k * 256 + n]
                            : W1r[(size_t)(k - 128) * 256 + n];
        g_w1hi[(size_t)n * 256 + k] = __float2half_rn(w);
    } else if (b < CPB_W2) {
        int idx = (b - CPB_W1) * 256 + tid;
        int n = idx >> 8, k = idx & 255;
        float w = (n < 40) ? W2l[(size_t)k * 40 + n]
                           : W2r[(size_t)k * 40 + (n - 40)];
        g_w2hi[(size_t)n * 256 + k] = __float2half_rn(w);
    } else {
        int idx = (b - CPB_W2) * 256 + tid;
        if (idx >= NN * 32) return;
        int row = idx >> 5, c4 = idx & 31;
        float4 v = ((const float4*)x)[(size_t)row * 32 + c4];
        uint2 hi, lo;
        split4h(v, hi, lo);
        *(uint2*)&g_a_hi[(size_t)row * 256 + 128 + c4 * 4] = hi;
        *(uint2*)&g_a_lo[(size_t)row * 256 + 128 + c4 * 4] = lo;
    }
}

// ---------------- k_scan: fused hierarchical scan ----------------------------
__device__ __forceinline__ int block_excl_scan(int c, int t) {
    int lane = t & 31, w = t >> 5;
    int v = c;
#pragma unroll
    for (int off = 1; off < 32; off <<= 1) {
        int n = __shfl_up_sync(0xffffffffu, v, off);
        if (lane >= off) v += n;
    }
    __shared__ int ws[8];
    if (lane == 31) ws[w] = v;
    __syncthreads();
    if (w == 0 && lane < 8) {
        int s = ws[lane];
#pragma unroll
        for (int off = 1; off < 8; off <<= 1) {
            int n = __shfl_up_sync(0x000000ffu, s, off);
            if (lane >= off) s += n;
        }
        ws[lane] = s;
    }
    __syncthreads();
    return v - c + (w > 0 ? ws[w - 1] : 0);
}

__global__ void k_scan() {
    int b = blockIdx.x, tid = threadIdx.x;
    int i = b * 256 + tid;
    int c = (i < NN) ? g_counts[i] : 0;
    int e = block_excl_scan(c, tid);

    if (tid == 255) {
        g_bsum[b] = e + c;
        __threadfence();
        atomicAdd(&g_done1, 1);
    }
    if (tid == 0) {
        while (*(volatile int*)&g_done1 < NB) {}
    }
    __syncthreads();
    __threadfence();

    int v = (tid < b) ? g_bsum[tid] : 0;
    int lane = tid & 31, w = tid >> 5;
#pragma unroll
    for (int off = 16; off; off >>= 1) v += __shfl_xor_sync(0xffffffffu, v, off);
    __shared__ int rs[8];
    if (lane == 0) rs[w] = v;
    __syncthreads();
    __shared__ int pre;
    if (tid == 0) {
        int s = 0;
#pragma unroll
        for (int k = 0; k < 8; k++) s += rs[k];
        pre = s;
    }
    __syncthreads();

    if (i < NN) {
        g_offsets[i] = pre + e;
        g_invc[i]    = 1.0f / (float)(c > 1 ? c : 1);
    }
    if (b == NB - 1 && tid == 255) g_offsets[NN] = NE;

    if (tid == 0) {
        int t2 = atomicAdd(&g_done2, 1);
        if (t2 == NB - 1) { g_done1 = 0; g_done2 = 0; }
    }
}

// ---------------- k_scatter: atomic-free via precomputed rank ----------------
__global__ void k_scatter(const void* __restrict__ ei) {
    int is64 = detect_is64((const int*)ei);
    int e = blockIdx.x * blockDim.x + threadIdx.x;
    if (e < NE) {
        int s = edge_at(ei, e, is64);
        int d = edge_at(ei, NE + e, is64);
        g_esrc[g_offsets[d] + g_rank[e]] = s;
    }
}

// ---------------- layer-1 aggregation (fp16 hi/lo cols 0..127) ---------------
__global__ void k_agg1(const float* __restrict__ x) {
    int warp = (blockIdx.x * blockDim.x + threadIdx.x) >> 5;
    if (warp >= NN) return;
    int lane = threadIdx.x & 31;
    int beg = g_offsets[warp], end = g_offsets[warp + 1];
    const float4* __restrict__ x4 = (const float4*)x;
    float4 acc = make_float4(0.f, 0.f, 0.f, 0.f);
    int e = beg;
    for (; e + 1 < end; e += 2) {
        int s0 = g_esrc[e];
        int s1 = g_esrc[e + 1];
        float4 v0 = x4[(size_t)s0 * 32 + lane];
        float4 v1 = x4[(size_t)s1 * 32 + lane];
        acc.x += v0.x + v1.x; acc.y += v0.y + v1.y;
        acc.z += v0.z + v1.z; acc.w += v0.w + v1.w;
    }
    if (e < end) {
        int s0 = g_esrc[e];
        float4 v0 = x4[(size_t)s0 * 32 + lane];
        acc.x += v0.x; acc.y += v0.y; acc.z += v0.z; acc.w += v0.w;
    }
    float iv = g_invc[warp];
    float4 o = make_float4(acc.x * iv, acc.y * iv, acc.z * iv, acc.w * iv);
    uint2 hi, lo;
    split4h(o, hi, lo);
    *(uint2*)&g_a_hi[(size_t)warp * 256 + lane * 4] = hi;
    *(uint2*)&g_a_lo[(size_t)warp * 256 + lane * 4] = lo;
}

// ---------------- MEGA kernel: gemm1 (BN=256) + gemm2 fused, fp16 2-pass -----
// 512 threads, grid 391. Phase 1: h = relu(A@W1h^T + b1) -> smem (fp16 hi/lo).
// Phase 2: [p|r] = h @ W2h^T from smem.  A exact (hi+lo), B fp16-rounded.
// phase1 smem: 2 bufs x (A_hi 16K + A_lo 16K + B_hi 32K) = 128KB
// phase2 smem: h 128KB (reuse) + W2h (88-row pad, 4 chunks) 45KB -> 176128 total
#define MB_A_HI 0
#define MB_A_LO 16384
#define MB_B_HI 32768
#define MBUF    65536
#define MH_HI   0
#define MH_LO   65536
#define MB2_HI  131072
#define MB2_CH  11264          // 88 rows * 128B per chunk
#define DYN_SMEMM (MB2_HI + 4 * MB2_CH)   // 176128

__global__ void __launch_bounds__(512, 1) k_mega(const float* __restrict__ b1,
                                                 const float* __restrict__ b2) {
    extern __shared__ char dsm[];
    int tid = threadIdx.x;
    int wid = tid >> 5;          // 0..15
    int lane = tid & 31;
    int bm = blockIdx.x * 128;
    uint32_t dynb = smem_u32(dsm);

    // ===== phase 1: gemm1, warp tile 32x64, 4x4 warps over 128x256 =====
    int warp_m = (wid & 3) * 32;
    int warp_n = (wid >> 2) * 64;

    uint32_t offA[2][4], offB[4][4];
    {
        int mat = lane >> 3, rr = lane & 7;
#pragma unroll
        for (int i = 0; i < 2; i++)
#pragma unroll
            for (int j = 0; j < 4; j++) {
                int row = warp_m + i * 16 + ((mat & 1) << 3) + rr;
                int kb  = j * 16 + ((mat >> 1) << 3);
                offA[i][j] = SW128(row * 128 + kb * 2);
            }
#pragma unroll
        for (int q = 0; q < 4; q++)
#pragma unroll
            for (int j = 0; j < 4; j++) {
                int n  = warp_n + q * 16 + ((mat & 2) << 2) + rr;
                int kb = j * 16 + ((mat & 1) << 3);
                offB[q][j] = SW128(n * 128 + kb * 2);
            }
    }

    float acc[2][8][4];
#pragma unroll
    for (int i = 0; i < 2; i++)
#pragma unroll
        for (int jn = 0; jn < 8; jn++)
#pragma unroll
            for (int t = 0; t < 4; t++) acc[i][jn][t] = 0.f;

#define STAGEM(K0, BUFO) do {                                                      \
    _Pragma("unroll")                                                              \
    for (int it = 0; it < 2; it++) {                                               \
        int idx = tid + it * 512;                                                  \
        int row = idx >> 3, seg = idx & 7;                                         \
        int grow = bm + row;                                                       \
        int cl = grow < NN ? grow : (NN - 1);                                      \
        int sz = grow < NN ? 16 : 0;                                               \
        size_t boff = ((size_t)cl * 256 + (K0) + seg * 8) * 2;                     \
        int so = SW128(row * 128 + seg * 16);                                      \
        cp_async16(dynb + (BUFO) + MB_A_HI + so, (const char*)g_a_hi + boff, sz);  \
        cp_async16(dynb + (BUFO) + MB_A_LO + so, (const char*)g_a_lo + boff, sz);  \
    }                                                                              \
    _Pragma("unroll")                                                              \
    for (int it = 0; it < 4; it++) {                                               \
        int idx = tid + it * 512;                                                  \
        int row = idx >> 3, seg = idx & 7;                                         \
        size_t boff = ((size_t)row * 256 + (K0) + seg * 8) * 2;                    \
        int so = SW128(row * 128 + seg * 16);                                      \
        cp_async16(dynb + (BUFO) + MB_B_HI + so, (const char*)g_w1hi + boff, 16);  \
    }                                                                              \
} while (0)

    STAGEM(0, 0);     CP_COMMIT();
    STAGEM(64, MBUF); CP_COMMIT();

    for (int kc = 0; kc < 4; kc++) {
        uint32_t bufo = (kc & 1) ? MBUF : 0;
        CP_WAIT1();
        __syncthreads();
#pragma unroll
        for (int j = 0; j < 4; j++) {
            uint32_t ah[2][4], al[2][4];
#pragma unroll
            for (int i = 0; i < 2; i++) {
                LDSM4(ah[i], dynb + bufo + MB_A_HI + offA[i][j]);
                LDSM4(al[i], dynb + bufo + MB_A_LO + offA[i][j]);
            }
#pragma unroll
            for (int q = 0; q < 4; q++) {
                uint32_t bh[4];
                LDSM4(bh, dynb + bufo + MB_B_HI + offB[q][j]);
#pragma unroll
                for (int i = 0; i < 2; i++)
#pragma unroll
                    for (int hsel = 0; hsel < 2; hsel++) {
                        int jn = q * 2 + hsel;
                        uint32_t b0 = bh[hsel * 2], b1v = bh[hsel * 2 + 1];
                        mma16816(acc[i][jn], ah[i], b0, b1v);
                        mma16816(acc[i][jn], al[i], b0, b1v);
                    }
            }
        }
        __syncthreads();
        if (kc < 2) STAGEM((kc + 2) * 64, bufo);
        CP_COMMIT();
    }
#undef STAGEM

    // ===== phase 1 epilogue: h -> smem (fp16 hi/lo), stage W2h concurrently ==
    {
        // zero pad rows 80..87 of each chunk: 4*1024B = 256 uint4
        if (tid < 256) {
            int kcz = tid >> 6, q4 = tid & 63;
            *(uint4*)(dsm + MB2_HI + kcz * MB2_CH + 80 * 128 + q4 * 16) =
                make_uint4(0, 0, 0, 0);
        }
        // stage 80 rows x 8 segs x 4 chunks = 2560 segs, 512 thr -> 5 iters
#pragma unroll
        for (int it = 0; it < 5; it++) {
            int idx = tid + it * 512;
            int kc2 = idx / 640;
            int rr2 = idx - kc2 * 640;
            int row = rr2 >> 3, seg = rr2 & 7;
            const char* src = (const char*)g_w2hi
                              + ((size_t)row * 256 + kc2 * 64 + seg * 8) * 2;
            uint32_t dst = dynb + MB2_HI + kc2 * MB2_CH
                           + SW128(row * 128 + seg * 16);
            cp_async16(dst, src, 16);
        }
        CP_COMMIT();
    }

    {
        int r0l = warp_m + (lane >> 2);
        int c0l = warp_n + 2 * (lane & 3);
#pragma unroll
        for (int i = 0; i < 2; i++) {
#pragma unroll
            for (int jn = 0; jn < 8; jn++) {
                int col = c0l + jn * 8;
                int kc = col >> 6, kin = col & 63;
                float bx = b1[col], by = b1[col + 1];
                {
                    int r = r0l + i * 16;
                    float vx = acc[i][jn][0] + bx; vx = vx > 0.f ? vx : 0.f;
                    float vy = acc[i][jn][1] + by; vy = vy > 0.f ? vy : 0.f;
                    uint32_t hi, lo;
                    split2h(vx, vy, hi, lo);
                    int so = kc * 16384 + SW128(r * 128 + kin * 2);
                    *(uint32_t*)(dsm + MH_HI + so) = hi;
                    *(uint32_t*)(dsm + MH_LO + so) = lo;
                }
                {
                    int r = r0l + i * 16 + 8;
                    float vx = acc[i][jn][2] + bx; vx = vx > 0.f ? vx : 0.f;
                    float vy = acc[i][jn][3] + by; vy = vy > 0.f ? vy : 0.f;
                    uint32_t hi, lo;
                    split2h(vx, vy, hi, lo);
                    int so = kc * 16384 + SW128(r * 128 + kin * 2);
                    *(uint32_t*)(dsm + MH_HI + so) = hi;
                    *(uint32_t*)(dsm + MH_LO + so) = lo;
                }
            }
        }
    }
    CP_WAIT0();
    __syncthreads();

    // ===== phase 2: gemm2 from smem. warp tile 16x40, 8x2 warps ==============
    int warp_m2 = (wid & 7) * 16;
    int warp_n2 = (wid >> 3) * 40;

    uint32_t offA2[4], offB2[3][4];
    {
        int mat = lane >> 3, rr = lane & 7;
#pragma unroll
        for (int jj = 0; jj < 4; jj++) {
            int row = warp_m2 + ((mat & 1) << 3) + rr;
            int kb  = jj * 16 + ((mat >> 1) << 3);
            offA2[jj] = SW128(row * 128 + kb * 2);
        }
#pragma unroll
        for (int q = 0; q < 3; q++)
#pragma unroll
            for (int jj = 0; jj < 4; jj++) {
                int n  = warp_n2 + q * 16 + ((mat & 2) << 2) + rr;
                int kb = jj * 16 + ((mat & 1) << 3);
                offB2[q][jj] = SW128(n * 128 + kb * 2);
            }
    }

    float acc2[5][4];
#pragma unroll
    for (int jn = 0; jn < 5; jn++)
#pragma unroll
        for (int t = 0; t < 4; t++) acc2[jn][t] = 0.f;

#pragma unroll
    for (int j = 0; j < 16; j++) {
        int kc = j >> 2, jj = j & 3;
        uint32_t ah[4], al[4];
        LDSM4(ah, dynb + MH_HI + kc * 16384 + offA2[jj]);
        LDSM4(al, dynb + MH_LO + kc * 16384 + offA2[jj]);
#pragma unroll
        for (int q = 0; q < 3; q++) {
            uint32_t bh[4];
            LDSM4(bh, dynb + MB2_HI + kc * MB2_CH + offB2[q][jj]);
#pragma unroll
            for (int h2 = 0; h2 < 2; h2++) {
                int jn = q * 2 + h2;
                if (jn < 5) {
                    uint32_t b0 = bh[h2 * 2], b1v = bh[h2 * 2 + 1];
                    mma16816(acc2[jn], ah, b0, b1v);
                    mma16816(acc2[jn], al, b0, b1v);
                }
            }
        }
    }

    // epilogue: cols<40 -> p (no bias), cols>=40 -> r (+b2)
    int r0 = bm + warp_m2 + (lane >> 2);
    int c0 = warp_n2 + 2 * (lane & 3);
#pragma unroll
    for (int jn = 0; jn < 5; jn++) {
        int col = c0 + jn * 8;
#pragma unroll
        for (int half = 0; half < 2; half++) {
            int row = r0 + half * 8;
            if (row < NN) {
                float vx = acc2[jn][half * 2 + 0];
                float vy = acc2[jn][half * 2 + 1];
                if (col < 40) {
                    *(float2*)&g_p[(size_t)row * 40 + col] = make_float2(vx, vy);
                } else {
                    float2 v = make_float2(vx + b2[col - 40], vy + b2[col - 39]);
                    *(float2*)&g_r[(size_t)row * 40 + (col - 40)] = v;
                }
            }
        }
    }
}

// ---------------- layer-2 aggregation + log_softmax + counts reset -----------
__global__ void k_agg2_lsm(float* __restrict__ out) {
    // reset counts for next execution (graph-replay invariant; zero at load)
    if (blockIdx.x < NB) {
        int ci = blockIdx.x * 256 + threadIdx.x;
        if (ci < NN) g_counts[ci] = 0;
    }

    int warp = (blockIdx.x * blockDim.x + threadIdx.x) >> 5;
    if (warp >= NN) return;
    int lane = threadIdx.x & 31;
    int beg = g_offsets[warp], end = g_offsets[warp + 1];
    bool h1 = lane < 8;
    float a0 = 0.f, a1 = 0.f;
    for (int e = beg; e < end; e++) {
        int s = g_esrc[e];
        const float* ps = g_p + (size_t)s * 40;
        a0 += ps[lane];
        if (h1) a1 += ps[32 + lane];
    }
    float iv = g_invc[warp];
    float v0 = a0 * iv + g_r[(size_t)warp * 40 + lane];
    float v1 = h1 ? (a1 * iv + g_r[(size_t)warp * 40 + 32 + lane]) : -3.0e38f;

    float m = fmaxf(v0, v1);
#pragma unroll
    for (int off = 16; off; off >>= 1)
        m = fmaxf(m, __shfl_xor_sync(0xffffffffu, m, off));
    float ssum = expf(v0 - m) + (h1 ? expf(v1 - m) : 0.f);
#pragma unroll
    for (int off = 16; off; off >>= 1)
        ssum += __shfl_xor_sync(0xffffffffu, ssum, off);
    float lse = m + logf(ssum);

    out[(size_t)warp * 40 + lane] = v0 - lse;
    if (h1) out[(size_t)warp * 40 + 32 + lane] = v1 - lse;
}

// ---------------- launch -----------------------------------------------------
extern "C" void kernel_launch(void* const* d_in, const int* in_sizes, int n_in,
                              void* d_out, int out_size) {
    const float* x   = (const float*)d_in[0];
    const void*  ei  = d_in[1];
    const float* W1l = (const float*)d_in[2];
    const float* W1r = (const float*)d_in[3];
    const float* b1  = (const float*)d_in[4];
    const float* W2l = (const float*)d_in[5];
    const float* W2r = (const float*)d_in[6];
    const float* b2  = (const float*)d_in[7];
    float* out = (float*)d_out;

    cudaFuncSetAttribute(k_mega, cudaFuncAttributeMaxDynamicSharedMemorySize,
                         DYN_SMEMM);

    k_count_prep<<<CPB_X, 256>>>(ei, W1l, W1r, W2l, W2r, x);
    k_scan<<<NB, 256>>>();
    k_scatter<<<(NE + 255) / 256, 256>>>(ei);
    k_agg1<<<(NN + 7) / 8, 256>>>(x);
    k_mega<<<(NN + 127) / 128, 512, DYN_SMEMM>>>(b1, b2);
    k_agg2_lsm<<<(NN + 7) / 8, 256>>>(out);
}

// round 14
// speedup vs baseline: 1.4154x; 1.0184x over previous
#include <cuda_runtime.h>
#include <cuda_fp16.h>
#include <math.h>
#include <cstdint>

#define NN   50000
#define NE   800000
#define IND  128
#define HID  256
#define OUTD 40
#define NB   ((NN + 255) / 256)   // 196 scan blocks

// ---------------- scratch ----------------------------------------------------
__device__ int   g_counts[NN];          // zero at load; re-zeroed by agg2 tail
__device__ int   g_offsets[NN + 1];
__device__ int   g_rank[NE];
__device__ int   g_esrc[NE];
__device__ float g_invc[NN];
__device__ int   g_bsum[NB];
__device__ int   g_done1 = 0;
__device__ int   g_done2 = 0;
__device__ __align__(16) __half g_a_hi[(size_t)NN * HID];  // [agg|x] hi (fp16)
__device__ __align__(16) __half g_a_lo[(size_t)NN * HID];  // [agg|x] lo (fp16)
__device__ __align__(16) __half g_w1hi[(size_t)HID * HID]; // W1^T fp16 [n][k]
__device__ __align__(16) __half g_w2hi[(size_t)80 * HID];  // W2^T fp16 [80][256]
__device__ __align__(16) __half g_p[(size_t)NN * OUTD];    // p fp16 [NN][40]
__device__ __align__(16) float g_r[(size_t)NN * OUTD];

// ---------------- helpers ----------------------------------------------------
__device__ __forceinline__ uint32_t smem_u32(const void* p) {
    uint32_t a;
    asm("{ .reg .u64 t; cvta.to.shared.u64 t, %1; cvt.u32.u64 %0, t; }"
        : "=r"(a) : "l"(p));
    return a;
}

#define SW128(o) ((o) ^ (((o) >> 3) & 0x70))

#define LDSM4(R, ADDR)                                                           \
    asm volatile("ldmatrix.sync.aligned.m8n8.x4.shared.b16 {%0,%1,%2,%3}, [%4];" \
        : "=r"((R)[0]), "=r"((R)[1]), "=r"((R)[2]), "=r"((R)[3]) : "r"(ADDR))

__device__ __forceinline__ void mma16816(float* c, const uint32_t* a,
                                         uint32_t b0, uint32_t b1) {
    asm volatile(
        "mma.sync.aligned.m16n8k16.row.col.f32.f16.f16.f32 "
        "{%0,%1,%2,%3}, {%4,%5,%6,%7}, {%8,%9}, {%0,%1,%2,%3};"
        : "+f"(c[0]), "+f"(c[1]), "+f"(c[2]), "+f"(c[3])
        : "r"(a[0]), "r"(a[1]), "r"(a[2]), "r"(a[3]), "r"(b0), "r"(b1));
}

__device__ __forceinline__ void cp_async16(uint32_t dst, const void* src, int srcsz) {
    asm volatile("cp.async.cg.shared.global [%0], [%1], 16, %2;"
                 :: "r"(dst), "l"(src), "r"(srcsz) : "memory");
}
#define CP_COMMIT() asm volatile("cp.async.commit_group;" ::: "memory")
#define CP_WAIT1()  asm volatile("cp.async.wait_group 1;" ::: "memory")
#define CP_WAIT0()  asm volatile("cp.async.wait_group 0;" ::: "memory")

// per-block edge dtype detection (odd words all zero over 32 samples <=> int64)
__device__ __forceinline__ int detect_is64(const int* __restrict__ ei32) {
    __shared__ int s_is64;
    if (threadIdx.x < 32) {
        int v = ei32[2 * threadIdx.x + 1];
        unsigned b = __ballot_sync(0xffffffffu, v != 0);
        if (threadIdx.x == 0) s_is64 = (b == 0) ? 1 : 0;
    }
    __syncthreads();
    return s_is64;
}

__device__ __forceinline__ int edge_at(const void* ei, int idx, int is64) {
    if (is64) return (int)((const long long*)ei)[idx];
    return ((const int*)ei)[idx];
}

// ---------------- fp16 split helpers -----------------------------------------
__device__ __forceinline__ void split4h(float4 v, uint2& hi, uint2& lo) {
    __half h0 = __float2half_rn(v.x);
    __half h1 = __float2half_rn(v.y);
    __half h2 = __float2half_rn(v.z);
    __half h3 = __float2half_rn(v.w);
    __half l0 = __float2half_rn(v.x - __half2float(h0));
    __half l1 = __float2half_rn(v.y - __half2float(h1));
    __half l2 = __float2half_rn(v.z - __half2float(h2));
    __half l3 = __float2half_rn(v.w - __half2float(h3));
    hi.x = (uint32_t)__half_as_ushort(h0) | ((uint32_t)__half_as_ushort(h1) << 16);
    hi.y = (uint32_t)__half_as_ushort(h2) | ((uint32_t)__half_as_ushort(h3) << 16);
    lo.x = (uint32_t)__half_as_ushort(l0) | ((uint32_t)__half_as_ushort(l1) << 16);
    lo.y = (uint32_t)__half_as_ushort(l2) | ((uint32_t)__half_as_ushort(l3) << 16);
}

__device__ __forceinline__ void split2h(float x, float y, uint32_t& hi, uint32_t& lo) {
    __half hx = __float2half_rn(x), hy = __float2half_rn(y);
    __half lx = __float2half_rn(x - __half2float(hx));
    __half ly = __float2half_rn(y - __half2float(hy));
    hi = (uint32_t)__half_as_ushort(hx) | ((uint32_t)__half_as_ushort(hy) << 16);
    lo = (uint32_t)__half_as_ushort(lx) | ((uint32_t)__half_as_ushort(ly) << 16);
}

// ---------------- k_count_prep: edge count+rank ∥ W1/W2/x fp16 prep ----------
#define CPB_COUNT 3125
#define CPB_W1    (CPB_COUNT + 256)
#define CPB_W2    (CPB_W1 + 80)
#define CPB_X     (CPB_W2 + 6250)

__global__ void k_count_prep(const void* __restrict__ ei,
                             const float* __restrict__ W1l, const float* __restrict__ W1r,
                             const float* __restrict__ W2l, const float* __restrict__ W2r,
                             const float* __restrict__ x) {
    int b = blockIdx.x;
    int tid = threadIdx.x;
    if (b < CPB_COUNT) {
        int is64 = detect_is64((const int*)ei);
        int e = b * 256 + tid;
        if (e < NE) {
            int d = edge_at(ei, NE + e, is64);
            g_rank[e] = atomicAdd(&g_counts[d], 1);
        }
    } else if (b < CPB_W1) {
        int idx = (b - CPB_COUNT) * 256 + tid;
        int n = idx >> 8, k = idx & 255;
        float w = (k < 128) ? W1l[(size_t)k * 256 + n]
                            : W1r[(size_t)(k - 128) * 256 + n];
        g_w1hi[(size_t)n * 256 + k] = __float2half_rn(w);
    } else if (b < CPB_W2) {
        int idx = (b - CPB_W1) * 256 + tid;
        int n = idx >> 8, k = idx & 255;
        float w = (n < 40) ? W2l[(size_t)k * 40 + n]
                           : W2r[(size_t)k * 40 + (n - 40)];
        g_w2hi[(size_t)n * 256 + k] = __float2half_rn(w);
    } else {
        int idx = (b - CPB_W2) * 256 + tid;
        if (idx >= NN * 32) return;
        int row = idx >> 5, c4 = idx & 31;
        float4 v = ((const float4*)x)[(size_t)row * 32 + c4];
        uint2 hi, lo;
        split4h(v, hi, lo);
        *(uint2*)&g_a_hi[(size_t)row * 256 + 128 + c4 * 4] = hi;
        *(uint2*)&g_a_lo[(size_t)row * 256 + 128 + c4 * 4] = lo;
    }
}

// ---------------- k_scan: fused hierarchical scan ----------------------------
__device__ __forceinline__ int block_excl_scan(int c, int t) {
    int lane = t & 31, w = t >> 5;
    int v = c;
#pragma unroll
    for (int off = 1; off < 32; off <<= 1) {
        int n = __shfl_up_sync(0xffffffffu, v, off);
        if (lane >= off) v += n;
    }
    __shared__ int ws[8];
    if (lane == 31) ws[w] = v;
    __syncthreads();
    if (w == 0 && lane < 8) {
        int s = ws[lane];
#pragma unroll
        for (int off = 1; off < 8; off <<= 1) {
            int n = __shfl_up_sync(0x000000ffu, s, off);
            if (lane >= off) s += n;
        }
        ws[lane] = s;
    }
    __syncthreads();
    return v - c + (w > 0 ? ws[w - 1] : 0);
}

__global__ void k_scan() {
    int b = blockIdx.x, tid = threadIdx.x;
    int i = b * 256 + tid;
    int c = (i < NN) ? g_counts[i] : 0;
    int e = block_excl_scan(c, tid);

    if (tid == 255) {
        g_bsum[b] = e + c;
        __threadfence();
        atomicAdd(&g_done1, 1);
    }
    if (tid == 0) {
        while (*(volatile int*)&g_done1 < NB) {}
    }
    __syncthreads();
    __threadfence();

    int v = (tid < b) ? g_bsum[tid] : 0;
    int lane = tid & 31, w = tid >> 5;
#pragma unroll
    for (int off = 16; off; off >>= 1) v += __shfl_xor_sync(0xffffffffu, v, off);
    __shared__ int rs[8];
    if (lane == 0) rs[w] = v;
    __syncthreads();
    __shared__ int pre;
    if (tid == 0) {
        int s = 0;
#pragma unroll
        for (int k = 0; k < 8; k++) s += rs[k];
        pre = s;
    }
    __syncthreads();

    if (i < NN) {
        g_offsets[i] = pre + e;
        g_invc[i]    = 1.0f / (float)(c > 1 ? c : 1);
    }
    if (b == NB - 1 && tid == 255) g_offsets[NN] = NE;

    if (tid == 0) {
        int t2 = atomicAdd(&g_done2, 1);
        if (t2 == NB - 1) { g_done1 = 0; g_done2 = 0; }
    }
}

// ---------------- k_scatter: atomic-free via precomputed rank ----------------
__global__ void k_scatter(const void* __restrict__ ei) {
    int is64 = detect_is64((const int*)ei);
    int e = blockIdx.x * blockDim.x + threadIdx.x;
    if (e < NE) {
        int s = edge_at(ei, e, is64);
        int d = edge_at(ei, NE + e, is64);
        g_esrc[g_offsets[d] + g_rank[e]] = s;
    }
}

// ---------------- layer-1 aggregation: gather x_hi (fp16) --------------------
// x_hi lives in g_a_hi cols 128..255 (written by count_prep). 256B/edge.
__global__ void k_agg1() {
    int warp = (blockIdx.x * blockDim.x + threadIdx.x) >> 5;
    if (warp >= NN) return;
    int lane = threadIdx.x & 31;
    int beg = g_offsets[warp], end = g_offsets[warp + 1];
    float4 acc = make_float4(0.f, 0.f, 0.f, 0.f);
    int e = beg;
    for (; e + 1 < end; e += 2) {
        int s0 = g_esrc[e];
        int s1 = g_esrc[e + 1];
        uint2 u0 = *(const uint2*)&g_a_hi[(size_t)s0 * 256 + 128 + lane * 4];
        uint2 u1 = *(const uint2*)&g_a_hi[(size_t)s1 * 256 + 128 + lane * 4];
        float2 f0a = __half22float2(*(__half2*)&u0.x);
        float2 f0b = __half22float2(*(__half2*)&u0.y);
        float2 f1a = __half22float2(*(__half2*)&u1.x);
        float2 f1b = __half22float2(*(__half2*)&u1.y);
        acc.x += f0a.x + f1a.x; acc.y += f0a.y + f1a.y;
        acc.z += f0b.x + f1b.x; acc.w += f0b.y + f1b.y;
    }
    if (e < end) {
        int s0 = g_esrc[e];
        uint2 u0 = *(const uint2*)&g_a_hi[(size_t)s0 * 256 + 128 + lane * 4];
        float2 f0a = __half22float2(*(__half2*)&u0.x);
        float2 f0b = __half22float2(*(__half2*)&u0.y);
        acc.x += f0a.x; acc.y += f0a.y; acc.z += f0b.x; acc.w += f0b.y;
    }
    float iv = g_invc[warp];
    float4 o = make_float4(acc.x * iv, acc.y * iv, acc.z * iv, acc.w * iv);
    uint2 hi, lo;
    split4h(o, hi, lo);
    *(uint2*)&g_a_hi[(size_t)warp * 256 + lane * 4] = hi;
    *(uint2*)&g_a_lo[(size_t)warp * 256 + lane * 4] = lo;
}

// ---------------- MEGA kernel: gemm1 (BN=256) + gemm2 fused, fp16 2-pass -----
#define MB_A_HI 0
#define MB_A_LO 16384
#define MB_B_HI 32768
#define MBUF    65536
#define MH_HI   0
#define MH_LO   65536
#define MB2_HI  131072
#define MB2_CH  11264          // 88 rows * 128B per chunk
#define DYN_SMEMM (MB2_HI + 4 * MB2_CH)   // 176128

__global__ void __launch_bounds__(512, 1) k_mega(const float* __restrict__ b1,
                                                 const float* __restrict__ b2) {
    extern __shared__ char dsm[];
    int tid = threadIdx.x;
    int wid = tid >> 5;          // 0..15
    int lane = tid & 31;
    int bm = blockIdx.x * 128;
    uint32_t dynb = smem_u32(dsm);

    // ===== phase 1: gemm1, warp tile 32x64, 4x4 warps over 128x256 =====
    int warp_m = (wid & 3) * 32;
    int warp_n = (wid >> 2) * 64;

    uint32_t offA[2][4], offB[4][4];
    {
        int mat = lane >> 3, rr = lane & 7;
#pragma unroll
        for (int i = 0; i < 2; i++)
#pragma unroll
            for (int j = 0; j < 4; j++) {
                int row = warp_m + i * 16 + ((mat & 1) << 3) + rr;
                int kb  = j * 16 + ((mat >> 1) << 3);
                offA[i][j] = SW128(row * 128 + kb * 2);
            }
#pragma unroll
        for (int q = 0; q < 4; q++)
#pragma unroll
            for (int j = 0; j < 4; j++) {
                int n  = warp_n + q * 16 + ((mat & 2) << 2) + rr;
                int kb = j * 16 + ((mat & 1) << 3);
                offB[q][j] = SW128(n * 128 + kb * 2);
            }
    }

    float acc[2][8][4];
#pragma unroll
    for (int i = 0; i < 2; i++)
#pragma unroll
        for (int jn = 0; jn < 8; jn++)
#pragma unroll
            for (int t = 0; t < 4; t++) acc[i][jn][t] = 0.f;

#define STAGEM(K0, BUFO) do {                                                      \
    _Pragma("unroll")                                                              \
    for (int it = 0; it < 2; it++) {                                               \
        int idx = tid + it * 512;                                                  \
        int row = idx >> 3, seg = idx & 7;                                         \
        int grow = bm + row;                                                       \
        int cl = grow < NN ? grow : (NN - 1);                                      \
        int sz = grow < NN ? 16 : 0;                                               \
        size_t boff = ((size_t)cl * 256 + (K0) + seg * 8) * 2;                     \
        int so = SW128(row * 128 + seg * 16);                                      \
        cp_async16(dynb + (BUFO) + MB_A_HI + so, (const char*)g_a_hi + boff, sz);  \
        cp_async16(dynb + (BUFO) + MB_A_LO + so, (const char*)g_a_lo + boff, sz);  \
    }                                                                              \
    _Pragma("unroll")                                                              \
    for (int it = 0; it < 4; it++) {                                               \
        int idx = tid + it * 512;                                                  \
        int row = idx >> 3, seg = idx & 7;                                         \
        size_t boff = ((size_t)row * 256 + (K0) + seg * 8) * 2;                    \
        int so = SW128(row * 128 + seg * 16);                                      \
        cp_async16(dynb + (BUFO) + MB_B_HI + so, (const char*)g_w1hi + boff, 16);  \
    }                                                                              \
} while (0)

    STAGEM(0, 0);     CP_COMMIT();
    STAGEM(64, MBUF); CP_COMMIT();

    for (int kc = 0; kc < 4; kc++) {
        uint32_t bufo = (kc & 1) ? MBUF : 0;
        CP_WAIT1();
        __syncthreads();
#pragma unroll
        for (int j = 0; j < 4; j++) {
            uint32_t ah[2][4], al[2][4];
#pragma unroll
            for (int i = 0; i < 2; i++) {
                LDSM4(ah[i], dynb + bufo + MB_A_HI + offA[i][j]);
                LDSM4(al[i], dynb + bufo + MB_A_LO + offA[i][j]);
            }
#pragma unroll
            for (int q = 0; q < 4; q++) {
                uint32_t bh[4];
                LDSM4(bh, dynb + bufo + MB_B_HI + offB[q][j]);
#pragma unroll
                for (int i = 0; i < 2; i++)
#pragma unroll
                    for (int hsel = 0; hsel < 2; hsel++) {
                        int jn = q * 2 + hsel;
                        uint32_t b0 = bh[hsel * 2], b1v = bh[hsel * 2 + 1];
                        mma16816(acc[i][jn], ah[i], b0, b1v);
                        mma16816(acc[i][jn], al[i], b0, b1v);
                    }
            }
        }
        __syncthreads();
        if (kc < 2) STAGEM((kc + 2) * 64, bufo);
        CP_COMMIT();
    }
#undef STAGEM

    // ===== phase 1 epilogue: h -> smem (fp16 hi/lo), stage W2h concurrently ==
    {
        if (tid < 256) {
            int kcz = tid >> 6, q4 = tid & 63;
            *(uint4*)(dsm + MB2_HI + kcz * MB2_CH + 80 * 128 + q4 * 16) =
                make_uint4(0, 0, 0, 0);
        }
#pragma unroll
        for (int it = 0; it < 5; it++) {
            int idx = tid + it * 512;
            int kc2 = idx / 640;
            int rr2 = idx - kc2 * 640;
            int row = rr2 >> 3, seg = rr2 & 7;
            const char* src = (const char*)g_w2hi
                              + ((size_t)row * 256 + kc2 * 64 + seg * 8) * 2;
            uint32_t dst = dynb + MB2_HI + kc2 * MB2_CH
                           + SW128(row * 128 + seg * 16);
            cp_async16(dst, src, 16);
        }
        CP_COMMIT();
    }

    {
        int r0l = warp_m + (lane >> 2);
        int c0l = warp_n + 2 * (lane & 3);
#pragma unroll
        for (int i = 0; i < 2; i++) {
#pragma unroll
            for (int jn = 0; jn < 8; jn++) {
                int col = c0l + jn * 8;
                int kc = col >> 6, kin = col & 63;
                float bx = b1[col], by = b1[col + 1];
                {
                    int r = r0l + i * 16;
                    float vx = acc[i][jn][0] + bx; vx = vx > 0.f ? vx : 0.f;
                    float vy = acc[i][jn][1] + by; vy = vy > 0.f ? vy : 0.f;
                    uint32_t hi, lo;
                    split2h(vx, vy, hi, lo);
                    int so = kc * 16384 + SW128(r * 128 + kin * 2);
                    *(uint32_t*)(dsm + MH_HI + so) = hi;
                    *(uint32_t*)(dsm + MH_LO + so) = lo;
                }
                {
                    int r = r0l + i * 16 + 8;
                    float vx = acc[i][jn][2] + bx; vx = vx > 0.f ? vx : 0.f;
                    float vy = acc[i][jn][3] + by; vy = vy > 0.f ? vy : 0.f;
                    uint32_t hi, lo;
                    split2h(vx, vy, hi, lo);
                    int so = kc * 16384 + SW128(r * 128 + kin * 2);
                    *(uint32_t*)(dsm + MH_HI + so) = hi;
                    *(uint32_t*)(dsm + MH_LO + so) = lo;
                }
            }
        }
    }
    CP_WAIT0();
    __syncthreads();

    // ===== phase 2: gemm2 from smem. warp tile 16x40, 8x2 warps ==============
    int warp_m2 = (wid & 7) * 16;
    int warp_n2 = (wid >> 3) * 40;

    uint32_t offA2[4], offB2[3][4];
    {
        int mat = lane >> 3, rr = lane & 7;
#pragma unroll
        for (int jj = 0; jj < 4; jj++) {
            int row = warp_m2 + ((mat & 1) << 3) + rr;
            int kb  = jj * 16 + ((mat >> 1) << 3);
            offA2[jj] = SW128(row * 128 + kb * 2);
        }
#pragma unroll
        for (int q = 0; q < 3; q++)
#pragma unroll
            for (int jj = 0; jj < 4; jj++) {
                int n  = warp_n2 + q * 16 + ((mat & 2) << 2) + rr;
                int kb = jj * 16 + ((mat & 1) << 3);
                offB2[q][jj] = SW128(n * 128 + kb * 2);
            }
    }

    float acc2[5][4];
#pragma unroll
    for (int jn = 0; jn < 5; jn++)
#pragma unroll
        for (int t = 0; t < 4; t++) acc2[jn][t] = 0.f;

#pragma unroll
    for (int j = 0; j < 16; j++) {
        int kc = j >> 2, jj = j & 3;
        uint32_t ah[4], al[4];
        LDSM4(ah, dynb + MH_HI + kc * 16384 + offA2[jj]);
        LDSM4(al, dynb + MH_LO + kc * 16384 + offA2[jj]);
#pragma unroll
        for (int q = 0; q < 3; q++) {
            uint32_t bh[4];
            LDSM4(bh, dynb + MB2_HI + kc * MB2_CH + offB2[q][jj]);
#pragma unroll
            for (int h2 = 0; h2 < 2; h2++) {
                int jn = q * 2 + h2;
                if (jn < 5) {
                    uint32_t b0 = bh[h2 * 2], b1v = bh[h2 * 2 + 1];
                    mma16816(acc2[jn], ah, b0, b1v);
                    mma16816(acc2[jn], al, b0, b1v);
                }
            }
        }
    }

    // epilogue: cols<40 -> p (fp16, no bias), cols>=40 -> r (fp32, +b2)
    int r0 = bm + warp_m2 + (lane >> 2);
    int c0 = warp_n2 + 2 * (lane & 3);
#pragma unroll
    for (int jn = 0; jn < 5; jn++) {
        int col = c0 + jn * 8;
#pragma unroll
        for (int half = 0; half < 2; half++) {
            int row = r0 + half * 8;
            if (row < NN) {
                float vx = acc2[jn][half * 2 + 0];
                float vy = acc2[jn][half * 2 + 1];
                if (col < 40) {
                    __half2 hp = __floats2half2_rn(vx, vy);
                    *(__half2*)&g_p[(size_t)row * 40 + col] = hp;
                } else {
                    float2 v = make_float2(vx + b2[col - 40], vy + b2[col - 39]);
                    *(float2*)&g_r[(size_t)row * 40 + (col - 40)] = v;
                }
            }
        }
    }
}

// ---------------- layer-2 aggregation + log_softmax + counts reset -----------
__global__ void k_agg2_lsm(float* __restrict__ out) {
    if (blockIdx.x < NB) {
        int ci = blockIdx.x * 256 + threadIdx.x;
        if (ci < NN) g_counts[ci] = 0;
    }

    int warp = (blockIdx.x * blockDim.x + threadIdx.x) >> 5;
    if (warp >= NN) return;
    int lane = threadIdx.x & 31;
    int beg = g_offsets[warp], end = g_offsets[warp + 1];
    bool h1 = lane < 8;
    float a0 = 0.f, a1 = 0.f;
    for (int e = beg; e < end; e++) {
        int s = g_esrc[e];
        const __half* ps = g_p + (size_t)s * 40;
        a0 += __half2float(ps[lane]);
        if (h1) a1 += __half2float(ps[32 + lane]);
    }
    float iv = g_invc[warp];
    float v0 = a0 * iv + g_r[(size_t)warp * 40 + lane];
    float v1 = h1 ? (a1 * iv + g_r[(size_t)warp * 40 + 32 + lane]) : -3.0e38f;

    float m = fmaxf(v0, v1);
#pragma unroll
    for (int off = 16; off; off >>= 1)
        m = fmaxf(m, __shfl_xor_sync(0xffffffffu, m, off));
    float ssum = expf(v0 - m) + (h1 ? expf(v1 - m) : 0.f);
#pragma unroll
    for (int off = 16; off; off >>= 1)
        ssum += __shfl_xor_sync(0xffffffffu, ssum, off);
    float lse = m + logf(ssum);

    out[(size_t)warp * 40 + lane] = v0 - lse;
    if (h1) out[(size_t)warp * 40 + 32 + lane] = v1 - lse;
}

// ---------------- launch -----------------------------------------------------
extern "C" void kernel_launch(void* const* d_in, const int* in_sizes, int n_in,
                              void* d_out, int out_size) {
    const void*  ei  = d_in[1];
    const float* x   = (const float*)d_in[0];
    const float* W1l = (const float*)d_in[2];
    const float* W1r = (const float*)d_in[3];
    const float* b1  = (const float*)d_in[4];
    const float* W2l = (const float*)d_in[5];
    const float* W2r = (const float*)d_in[6];
    const float* b2  = (const float*)d_in[7];
    float* out = (float*)d_out;

    cudaFuncSetAttribute(k_mega, cudaFuncAttributeMaxDynamicSharedMemorySize,
                         DYN_SMEMM);

    k_count_prep<<<CPB_X, 256>>>(ei, W1l, W1r, W2l, W2r, x);
    k_scan<<<NB, 256>>>();
    k_scatter<<<(NE + 255) / 256, 256>>>(ei);
    k_agg1<<<(NN + 7) / 8, 256>>>();
    k_mega<<<(NN + 127) / 128, 512, DYN_SMEMM>>>(b1, b2);
    k_agg2_lsm<<<(NN + 7) / 8, 256>>>(out);
}

// round 15
// speedup vs baseline: 1.7540x; 1.2393x over previous
#include <cuda_runtime.h>
#include <cuda_fp16.h>
#include <math.h>
#include <cstdint>

#define NN   50000
#define NE   800000
#define IND  128
#define HID  256
#define OUTD 40
#define NB   ((NN + 255) / 256)   // 196 scan blocks

// ---------------- scratch ----------------------------------------------------
__device__ int   g_counts[NN];          // zero at load; re-zeroed by agg2 tail
__device__ int   g_offsets[NN + 1];
__device__ int   g_rank[NE];
__device__ int   g_esrc[NE];
__device__ float g_invc[NN];
__device__ int   g_bsum[NB];
__device__ int   g_done1 = 0;
__device__ int   g_done2 = 0;
__device__ __align__(16) __half g_a_hi[(size_t)NN * HID];  // [agg|x] fp16
__device__ __align__(16) __half g_w1hi[(size_t)HID * HID]; // W1^T fp16 [n][k]
__device__ __align__(16) __half g_w2hi[(size_t)80 * HID];  // W2^T fp16 [80][256]
__device__ __align__(16) __half g_p[(size_t)NN * OUTD];    // p fp16 [NN][40]
__device__ __align__(16) float g_r[(size_t)NN * OUTD];

// ---------------- helpers ----------------------------------------------------
__device__ __forceinline__ uint32_t smem_u32(const void* p) {
    uint32_t a;
    asm("{ .reg .u64 t; cvta.to.shared.u64 t, %1; cvt.u32.u64 %0, t; }"
        : "=r"(a) : "l"(p));
    return a;
}

#define SW128(o) ((o) ^ (((o) >> 3) & 0x70))

#define LDSM4(R, ADDR)                                                           \
    asm volatile("ldmatrix.sync.aligned.m8n8.x4.shared.b16 {%0,%1,%2,%3}, [%4];" \
        : "=r"((R)[0]), "=r"((R)[1]), "=r"((R)[2]), "=r"((R)[3]) : "r"(ADDR))

__device__ __forceinline__ void mma16816(float* c, const uint32_t* a,
                                         uint32_t b0, uint32_t b1) {
    asm volatile(
        "mma.sync.aligned.m16n8k16.row.col.f32.f16.f16.f32 "
        "{%0,%1,%2,%3}, {%4,%5,%6,%7}, {%8,%9}, {%0,%1,%2,%3};"
        : "+f"(c[0]), "+f"(c[1]), "+f"(c[2]), "+f"(c[3])
        : "r"(a[0]), "r"(a[1]), "r"(a[2]), "r"(a[3]), "r"(b0), "r"(b1));
}

__device__ __forceinline__ void cp_async16(uint32_t dst, const void* src, int srcsz) {
    asm volatile("cp.async.cg.shared.global [%0], [%1], 16, %2;"
                 :: "r"(dst), "l"(src), "r"(srcsz) : "memory");
}
#define CP_COMMIT() asm volatile("cp.async.commit_group;" ::: "memory")
#define CP_WAIT1()  asm volatile("cp.async.wait_group 1;" ::: "memory")
#define CP_WAIT0()  asm volatile("cp.async.wait_group 0;" ::: "memory")

// per-block edge dtype detection (odd words all zero over 32 samples <=> int64)
__device__ __forceinline__ int detect_is64(const int* __restrict__ ei32) {
    __shared__ int s_is64;
    if (threadIdx.x < 32) {
        int v = ei32[2 * threadIdx.x + 1];
        unsigned b = __ballot_sync(0xffffffffu, v != 0);
        if (threadIdx.x == 0) s_is64 = (b == 0) ? 1 : 0;
    }
    __syncthreads();
    return s_is64;
}

__device__ __forceinline__ int edge_at(const void* ei, int idx, int is64) {
    if (is64) return (int)((const long long*)ei)[idx];
    return ((const int*)ei)[idx];
}

// ---------------- k_count_prep: edge count+rank ∥ W1/W2/x fp16 prep ----------
#define CPB_COUNT 3125
#define CPB_W1    (CPB_COUNT + 256)
#define CPB_W2    (CPB_W1 + 80)
#define CPB_X     (CPB_W2 + 6250)

__global__ void k_count_prep(const void* __restrict__ ei,
                             const float* __restrict__ W1l, const float* __restrict__ W1r,
                             const float* __restrict__ W2l, const float* __restrict__ W2r,
                             const float* __restrict__ x) {
    int b = blockIdx.x;
    int tid = threadIdx.x;
    if (b < CPB_COUNT) {
        int is64 = detect_is64((const int*)ei);
        int e = b * 256 + tid;
        if (e < NE) {
            int d = edge_at(ei, NE + e, is64);
            g_rank[e] = atomicAdd(&g_counts[d], 1);
        }
    } else if (b < CPB_W1) {
        int idx = (b - CPB_COUNT) * 256 + tid;
        int n = idx >> 8, k = idx & 255;
        float w = (k < 128) ? W1l[(size_t)k * 256 + n]
                            : W1r[(size_t)(k - 128) * 256 + n];
        g_w1hi[(size_t)n * 256 + k] = __float2half_rn(w);
    } else if (b < CPB_W2) {
        int idx = (b - CPB_W1) * 256 + tid;
        int n = idx >> 8, k = idx & 255;
        float w = (n < 40) ? W2l[(size_t)k * 40 + n]
                           : W2r[(size_t)k * 40 + (n - 40)];
        g_w2hi[(size_t)n * 256 + k] = __float2half_rn(w);
    } else {
        int idx = (b - CPB_W2) * 256 + tid;
        if (idx >= NN * 32) return;
        int row = idx >> 5, c4 = idx & 31;
        float4 v = ((const float4*)x)[(size_t)row * 32 + c4];
        __half2 h0 = __floats2half2_rn(v.x, v.y);
        __half2 h1 = __floats2half2_rn(v.z, v.w);
        uint2 hi;
        hi.x = *(uint32_t*)&h0;
        hi.y = *(uint32_t*)&h1;
        *(uint2*)&g_a_hi[(size_t)row * 256 + 128 + c4 * 4] = hi;
    }
}

// ---------------- k_scan: fused hierarchical scan ----------------------------
__device__ __forceinline__ int block_excl_scan(int c, int t) {
    int lane = t & 31, w = t >> 5;
    int v = c;
#pragma unroll
    for (int off = 1; off < 32; off <<= 1) {
        int n = __shfl_up_sync(0xffffffffu, v, off);
        if (lane >= off) v += n;
    }
    __shared__ int ws[8];
    if (lane == 31) ws[w] = v;
    __syncthreads();
    if (w == 0 && lane < 8) {
        int s = ws[lane];
#pragma unroll
        for (int off = 1; off < 8; off <<= 1) {
            int n = __shfl_up_sync(0x000000ffu, s, off);
            if (lane >= off) s += n;
        }
        ws[lane] = s;
    }
    __syncthreads();
    return v - c + (w > 0 ? ws[w - 1] : 0);
}

__global__ void k_scan() {
    int b = blockIdx.x, tid = threadIdx.x;
    int i = b * 256 + tid;
    int c = (i < NN) ? g_counts[i] : 0;
    int e = block_excl_scan(c, tid);

    if (tid == 255) {
        g_bsum[b] = e + c;
        __threadfence();
        atomicAdd(&g_done1, 1);
    }
    if (tid == 0) {
        while (*(volatile int*)&g_done1 < NB) {}
    }
    __syncthreads();
    __threadfence();

    int v = (tid < b) ? g_bsum[tid] : 0;
    int lane = tid & 31, w = tid >> 5;
#pragma unroll
    for (int off = 16; off; off >>= 1) v += __shfl_xor_sync(0xffffffffu, v, off);
    __shared__ int rs[8];
    if (lane == 0) rs[w] = v;
    __syncthreads();
    __shared__ int pre;
    if (tid == 0) {
        int s = 0;
#pragma unroll
        for (int k = 0; k < 8; k++) s += rs[k];
        pre = s;
    }
    __syncthreads();

    if (i < NN) {
        g_offsets[i] = pre + e;
        g_invc[i]    = 1.0f / (float)(c > 1 ? c : 1);
    }
    if (b == NB - 1 && tid == 255) g_offsets[NN] = NE;

    if (tid == 0) {
        int t2 = atomicAdd(&g_done2, 1);
        if (t2 == NB - 1) { g_done1 = 0; g_done2 = 0; }
    }
}

// ---------------- k_scatter: atomic-free via precomputed rank ----------------
__global__ void k_scatter(const void* __restrict__ ei) {
    int is64 = detect_is64((const int*)ei);
    int e = blockIdx.x * blockDim.x + threadIdx.x;
    if (e < NE) {
        int s = edge_at(ei, e, is64);
        int d = edge_at(ei, NE + e, is64);
        g_esrc[g_offsets[d] + g_rank[e]] = s;
    }
}

// ---------------- layer-1 aggregation: pairwise HADD2 gather of x_hi ---------
__global__ void k_agg1() {
    int warp = (blockIdx.x * blockDim.x + threadIdx.x) >> 5;
    if (warp >= NN) return;
    int lane = threadIdx.x & 31;
    int beg = g_offsets[warp], end = g_offsets[warp + 1];
    float4 acc = make_float4(0.f, 0.f, 0.f, 0.f);
    int e = beg;
    for (; e + 1 < end; e += 2) {
        int s0 = g_esrc[e];
        int s1 = g_esrc[e + 1];
        uint2 u0 = *(const uint2*)&g_a_hi[(size_t)s0 * 256 + 128 + lane * 4];
        uint2 u1 = *(const uint2*)&g_a_hi[(size_t)s1 * 256 + 128 + lane * 4];
        __half2 p0 = __hadd2(*(__half2*)&u0.x, *(__half2*)&u1.x);
        __half2 p1 = __hadd2(*(__half2*)&u0.y, *(__half2*)&u1.y);
        float2 f0 = __half22float2(p0);
        float2 f1 = __half22float2(p1);
        acc.x += f0.x; acc.y += f0.y; acc.z += f1.x; acc.w += f1.y;
    }
    if (e < end) {
        int s0 = g_esrc[e];
        uint2 u0 = *(const uint2*)&g_a_hi[(size_t)s0 * 256 + 128 + lane * 4];
        float2 f0 = __half22float2(*(__half2*)&u0.x);
        float2 f1 = __half22float2(*(__half2*)&u0.y);
        acc.x += f0.x; acc.y += f0.y; acc.z += f1.x; acc.w += f1.y;
    }
    float iv = g_invc[warp];
    __half2 h0 = __floats2half2_rn(acc.x * iv, acc.y * iv);
    __half2 h1 = __floats2half2_rn(acc.z * iv, acc.w * iv);
    uint2 hi;
    hi.x = *(uint32_t*)&h0;
    hi.y = *(uint32_t*)&h1;
    *(uint2*)&g_a_hi[(size_t)warp * 256 + lane * 4] = hi;
}

// ---------------- MEGA kernel: gemm1 (BN=256) + gemm2 fused, pure fp16 -------
// 512 threads, grid 391.
// Phase1 staging: 2 bufs x (A 16KB + B 32KB) at MSTG.  h -> MH (64KB, 4 chunks).
// Phase2: W2 chunks reuse dead staging area.
#define MH_HI   0
#define MB_A_HI 0
#define MB_B_HI 16384
#define MSTG    65536
#define MBUFSZ  49152
#define MB2_HI  65536
#define MB2_CH  11264          // 88 rows * 128B per chunk
#define DYN_SMEMM 163840

__global__ void __launch_bounds__(512, 1) k_mega(const float* __restrict__ b1,
                                                 const float* __restrict__ b2) {
    extern __shared__ char dsm[];
    int tid = threadIdx.x;
    int wid = tid >> 5;          // 0..15
    int lane = tid & 31;
    int bm = blockIdx.x * 128;
    uint32_t dynb = smem_u32(dsm);

    // ===== phase 1: gemm1, warp tile 32x64, 4x4 warps over 128x256 =====
    int warp_m = (wid & 3) * 32;
    int warp_n = (wid >> 2) * 64;

    uint32_t offA[2][4], offB[4][4];
    {
        int mat = lane >> 3, rr = lane & 7;
#pragma unroll
        for (int i = 0; i < 2; i++)
#pragma unroll
            for (int j = 0; j < 4; j++) {
                int row = warp_m + i * 16 + ((mat & 1) << 3) + rr;
                int kb  = j * 16 + ((mat >> 1) << 3);
                offA[i][j] = SW128(row * 128 + kb * 2);
            }
#pragma unroll
        for (int q = 0; q < 4; q++)
#pragma unroll
            for (int j = 0; j < 4; j++) {
                int n  = warp_n + q * 16 + ((mat & 2) << 2) + rr;
                int kb = j * 16 + ((mat & 1) << 3);
                offB[q][j] = SW128(n * 128 + kb * 2);
            }
    }

    float acc[2][8][4];
#pragma unroll
    for (int i = 0; i < 2; i++)
#pragma unroll
        for (int jn = 0; jn < 8; jn++)
#pragma unroll
            for (int t = 0; t < 4; t++) acc[i][jn][t] = 0.f;

#define STAGEM(K0, BUFO) do {                                                      \
    _Pragma("unroll")                                                              \
    for (int it = 0; it < 2; it++) {                                               \
        int idx = tid + it * 512;                                                  \
        int row = idx >> 3, seg = idx & 7;                                         \
        int grow = bm + row;                                                       \
        int cl = grow < NN ? grow : (NN - 1);                                      \
        int sz = grow < NN ? 16 : 0;                                               \
        size_t boff = ((size_t)cl * 256 + (K0) + seg * 8) * 2;                     \
        int so = SW128(row * 128 + seg * 16);                                      \
        cp_async16(dynb + (BUFO) + MB_A_HI + so, (const char*)g_a_hi + boff, sz);  \
    }                                                                              \
    _Pragma("unroll")                                                              \
    for (int it = 0; it < 4; it++) {                                               \
        int idx = tid + it * 512;                                                  \
        int row = idx >> 3, seg = idx & 7;                                         \
        size_t boff = ((size_t)row * 256 + (K0) + seg * 8) * 2;                    \
        int so = SW128(row * 128 + seg * 16);                                      \
        cp_async16(dynb + (BUFO) + MB_B_HI + so, (const char*)g_w1hi + boff, 16);  \
    }                                                                              \
} while (0)

    STAGEM(0, MSTG);            CP_COMMIT();
    STAGEM(64, MSTG + MBUFSZ);  CP_COMMIT();

    for (int kc = 0; kc < 4; kc++) {
        uint32_t bufo = MSTG + ((kc & 1) ? MBUFSZ : 0);
        CP_WAIT1();
        __syncthreads();
#pragma unroll
        for (int j = 0; j < 4; j++) {
            uint32_t ah[2][4];
#pragma unroll
            for (int i = 0; i < 2; i++)
                LDSM4(ah[i], dynb + bufo + MB_A_HI + offA[i][j]);
#pragma unroll
            for (int q = 0; q < 4; q++) {
                uint32_t bh[4];
                LDSM4(bh, dynb + bufo + MB_B_HI + offB[q][j]);
#pragma unroll
                for (int i = 0; i < 2; i++)
#pragma unroll
                    for (int hsel = 0; hsel < 2; hsel++) {
                        int jn = q * 2 + hsel;
                        mma16816(acc[i][jn], ah[i], bh[hsel * 2], bh[hsel * 2 + 1]);
                    }
            }
        }
        __syncthreads();
        if (kc < 2) STAGEM((kc + 2) * 64, bufo);
        CP_COMMIT();
    }
#undef STAGEM

    // ===== phase 1 epilogue: h -> smem fp16, stage W2 into dead staging area =
    {
        if (tid < 256) {
            int kcz = tid >> 6, q4 = tid & 63;
            *(uint4*)(dsm + MB2_HI + kcz * MB2_CH + 80 * 128 + q4 * 16) =
                make_uint4(0, 0, 0, 0);
        }
#pragma unroll
        for (int it = 0; it < 5; it++) {
            int idx = tid + it * 512;
            int kc2 = idx / 640;
            int rr2 = idx - kc2 * 640;
            int row = rr2 >> 3, seg = rr2 & 7;
            const char* src = (const char*)g_w2hi
                              + ((size_t)row * 256 + kc2 * 64 + seg * 8) * 2;
            uint32_t dst = dynb + MB2_HI + kc2 * MB2_CH
                           + SW128(row * 128 + seg * 16);
            cp_async16(dst, src, 16);
        }
        CP_COMMIT();
    }

    {
        int r0l = warp_m + (lane >> 2);
        int c0l = warp_n + 2 * (lane & 3);
#pragma unroll
        for (int i = 0; i < 2; i++) {
#pragma unroll
            for (int jn = 0; jn < 8; jn++) {
                int col = c0l + jn * 8;
                int kc = col >> 6, kin = col & 63;
                float bx = b1[col], by = b1[col + 1];
                {
                    int r = r0l + i * 16;
                    float vx = acc[i][jn][0] + bx; vx = vx > 0.f ? vx : 0.f;
                    float vy = acc[i][jn][1] + by; vy = vy > 0.f ? vy : 0.f;
                    __half2 h = __floats2half2_rn(vx, vy);
                    int so = kc * 16384 + SW128(r * 128 + kin * 2);
                    *(uint32_t*)(dsm + MH_HI + so) = *(uint32_t*)&h;
                }
                {
                    int r = r0l + i * 16 + 8;
                    float vx = acc[i][jn][2] + bx; vx = vx > 0.f ? vx : 0.f;
                    float vy = acc[i][jn][3] + by; vy = vy > 0.f ? vy : 0.f;
                    __half2 h = __floats2half2_rn(vx, vy);
                    int so = kc * 16384 + SW128(r * 128 + kin * 2);
                    *(uint32_t*)(dsm + MH_HI + so) = *(uint32_t*)&h;
                }
            }
        }
    }
    CP_WAIT0();
    __syncthreads();

    // ===== phase 2: gemm2 from smem. warp tile 16x40, 8x2 warps ==============
    int warp_m2 = (wid & 7) * 16;
    int warp_n2 = (wid >> 3) * 40;

    uint32_t offA2[4], offB2[3][4];
    {
        int mat = lane >> 3, rr = lane & 7;
#pragma unroll
        for (int jj = 0; jj < 4; jj++) {
            int row = warp_m2 + ((mat & 1) << 3) + rr;
            int kb  = jj * 16 + ((mat >> 1) << 3);
            offA2[jj] = SW128(row * 128 + kb * 2);
        }
#pragma unroll
        for (int q = 0; q < 3; q++)
#pragma unroll
            for (int jj = 0; jj < 4; jj++) {
                int n  = warp_n2 + q * 16 + ((mat & 2) << 2) + rr;
                int kb = jj * 16 + ((mat & 1) << 3);
                offB2[q][jj] = SW128(n * 128 + kb * 2);
            }
    }

    float acc2[5][4];
#pragma unroll
    for (int jn = 0; jn < 5; jn++)
#pragma unroll
        for (int t = 0; t < 4; t++) acc2[jn][t] = 0.f;

#pragma unroll
    for (int j = 0; j < 16; j++) {
        int kc = j >> 2, jj = j & 3;
        uint32_t ah[4];
        LDSM4(ah, dynb + MH_HI + kc * 16384 + offA2[jj]);
#pragma unroll
        for (int q = 0; q < 3; q++) {
            uint32_t bh[4];
            LDSM4(bh, dynb + MB2_HI + kc * MB2_CH + offB2[q][jj]);
#pragma unroll
            for (int h2 = 0; h2 < 2; h2++) {
                int jn = q * 2 + h2;
                if (jn < 5)
                    mma16816(acc2[jn], ah, bh[h2 * 2], bh[h2 * 2 + 1]);
            }
        }
    }

    // epilogue: cols<40 -> p (fp16, no bias), cols>=40 -> r (fp32, +b2)
    int r0 = bm + warp_m2 + (lane >> 2);
    int c0 = warp_n2 + 2 * (lane & 3);
#pragma unroll
    for (int jn = 0; jn < 5; jn++) {
        int col = c0 + jn * 8;
#pragma unroll
        for (int half = 0; half < 2; half++) {
            int row = r0 + half * 8;
            if (row < NN) {
                float vx = acc2[jn][half * 2 + 0];
                float vy = acc2[jn][half * 2 + 1];
                if (col < 40) {
                    __half2 hp = __floats2half2_rn(vx, vy);
                    *(__half2*)&g_p[(size_t)row * 40 + col] = hp;
                } else {
                    float2 v = make_float2(vx + b2[col - 40], vy + b2[col - 39]);
                    *(float2*)&g_r[(size_t)row * 40 + (col - 40)] = v;
                }
            }
        }
    }
}

// ---------------- layer-2 aggregation + log_softmax + counts reset -----------
__global__ void k_agg2_lsm(float* __restrict__ out) {
    if (blockIdx.x < NB) {
        int ci = blockIdx.x * 256 + threadIdx.x;
        if (ci < NN) g_counts[ci] = 0;
    }

    int warp = (blockIdx.x * blockDim.x + threadIdx.x) >> 5;
    if (warp >= NN) return;
    int lane = threadIdx.x & 31;
    int beg = g_offsets[warp], end = g_offsets[warp + 1];
    bool h1 = lane < 8;
    float a0 = 0.f, a1 = 0.f;
    for (int e = beg; e < end; e++) {
        int s = g_esrc[e];
        const __half* ps = g_p + (size_t)s * 40;
        a0 += __half2float(ps[lane]);
        if (h1) a1 += __half2float(ps[32 + lane]);
    }
    float iv = g_invc[warp];
    float v0 = a0 * iv + g_r[(size_t)warp * 40 + lane];
    float v1 = h1 ? (a1 * iv + g_r[(size_t)warp * 40 + 32 + lane]) : -3.0e38f;

    float m = fmaxf(v0, v1);
#pragma unroll
    for (int off = 16; off; off >>= 1)
        m = fmaxf(m, __shfl_xor_sync(0xffffffffu, m, off));
    float ssum = expf(v0 - m) + (h1 ? expf(v1 - m) : 0.f);
#pragma unroll
    for (int off = 16; off; off >>= 1)
        ssum += __shfl_xor_sync(0xffffffffu, ssum, off);
    float lse = m + logf(ssum);

    out[(size_t)warp * 40 + lane] = v0 - lse;
    if (h1) out[(size_t)warp * 40 + 32 + lane] = v1 - lse;
}

// ---------------- launch -----------------------------------------------------
extern "C" void kernel_launch(void* const* d_in, const int* in_sizes, int n_in,
                              void* d_out, int out_size) {
    const float* x   = (const float*)d_in[0];
    const void*  ei  = d_in[1];
    const float* W1l = (const float*)d_in[2];
    const float* W1r = (const float*)d_in[3];
    const float* b1  = (const float*)d_in[4];
    const float* W2l = (const float*)d_in[5];
    const float* W2r = (const float*)d_in[6];
    const float* b2  = (const float*)d_in[7];
    float* out = (float*)d_out;

    cudaFuncSetAttribute(k_mega, cudaFuncAttributeMaxDynamicSharedMemorySize,
                         DYN_SMEMM);

    k_count_prep<<<CPB_X, 256>>>(ei, W1l, W1r, W2l, W2r, x);
    k_scan<<<NB, 256>>>();
    k_scatter<<<(NE + 255) / 256, 256>>>(ei);
    k_agg1<<<(NN + 7) / 8, 256>>>();
    k_mega<<<(NN + 127) / 128, 512, DYN_SMEMM>>>(b1, b2);
    k_agg2_lsm<<<(NN + 7) / 8, 256>>>(out);
}

// round 16
// speedup vs baseline: 1.7711x; 1.0097x over previous
#include <cuda_runtime.h>
#include <cuda_fp16.h>
#include <math.h>
#include <cstdint>

#define NN   50000
#define NE   800000
#define IND  128
#define HID  256
#define OUTD 40
#define NB   ((NN + 255) / 256)   // 196 scan blocks

// ---------------- scratch ----------------------------------------------------
__device__ int   g_counts[NN];          // zero at load; re-zeroed by agg2 tail
__device__ int   g_offsets[NN + 1];
__device__ int   g_rank[NE];
__device__ int   g_esrc[NE];
__device__ float g_invc[NN];
__device__ int   g_bsum[NB];
__device__ int   g_done1 = 0;
__device__ int   g_done2 = 0;
__device__ __align__(16) __half g_a_hi[(size_t)NN * HID];  // [agg|x] fp16
__device__ __align__(16) __half g_w1hi[(size_t)HID * HID]; // W1^T fp16 [n][k]
__device__ __align__(16) __half g_w2hi[(size_t)80 * HID];  // W2^T fp16 [80][256]
__device__ __align__(16) __half g_p[(size_t)NN * OUTD];    // p fp16 [NN][40]
__device__ __align__(16) float g_r[(size_t)NN * OUTD];

// ---------------- helpers ----------------------------------------------------
__device__ __forceinline__ uint32_t smem_u32(const void* p) {
    uint32_t a;
    asm("{ .reg .u64 t; cvta.to.shared.u64 t, %1; cvt.u32.u64 %0, t; }"
        : "=r"(a) : "l"(p));
    return a;
}

#define SW128(o) ((o) ^ (((o) >> 3) & 0x70))

#define LDSM4(R, ADDR)                                                           \
    asm volatile("ldmatrix.sync.aligned.m8n8.x4.shared.b16 {%0,%1,%2,%3}, [%4];" \
        : "=r"((R)[0]), "=r"((R)[1]), "=r"((R)[2]), "=r"((R)[3]) : "r"(ADDR))

__device__ __forceinline__ void mma16816(float* c, const uint32_t* a,
                                         uint32_t b0, uint32_t b1) {
    asm volatile(
        "mma.sync.aligned.m16n8k16.row.col.f32.f16.f16.f32 "
        "{%0,%1,%2,%3}, {%4,%5,%6,%7}, {%8,%9}, {%0,%1,%2,%3};"
        : "+f"(c[0]), "+f"(c[1]), "+f"(c[2]), "+f"(c[3])
        : "r"(a[0]), "r"(a[1]), "r"(a[2]), "r"(a[3]), "r"(b0), "r"(b1));
}

__device__ __forceinline__ void cp_async16(uint32_t dst, const void* src, int srcsz) {
    asm volatile("cp.async.cg.shared.global [%0], [%1], 16, %2;"
                 :: "r"(dst), "l"(src), "r"(srcsz) : "memory");
}
#define CP_COMMIT() asm volatile("cp.async.commit_group;" ::: "memory")
#define CP_WAIT1()  asm volatile("cp.async.wait_group 1;" ::: "memory")
#define CP_WAIT0()  asm volatile("cp.async.wait_group 0;" ::: "memory")

// per-block edge dtype detection (odd words all zero over 32 samples <=> int64)
__device__ __forceinline__ int detect_is64(const int* __restrict__ ei32) {
    __shared__ int s_is64;
    if (threadIdx.x < 32) {
        int v = ei32[2 * threadIdx.x + 1];
        unsigned b = __ballot_sync(0xffffffffu, v != 0);
        if (threadIdx.x == 0) s_is64 = (b == 0) ? 1 : 0;
    }
    __syncthreads();
    return s_is64;
}

__device__ __forceinline__ int edge_at(const void* ei, int idx, int is64) {
    if (is64) return (int)((const long long*)ei)[idx];
    return ((const int*)ei)[idx];
}

// ---------------- k_count_prep: edge count+rank ∥ W1/W2/x fp16 prep ----------
#define CPB_COUNT 3125
#define CPB_W1    (CPB_COUNT + 256)
#define CPB_W2    (CPB_W1 + 80)
#define CPB_X     (CPB_W2 + 6250)

__global__ void k_count_prep(const void* __restrict__ ei,
                             const float* __restrict__ W1l, const float* __restrict__ W1r,
                             const float* __restrict__ W2l, const float* __restrict__ W2r,
                             const float* __restrict__ x) {
    int b = blockIdx.x;
    int tid = threadIdx.x;
    if (b < CPB_COUNT) {
        int is64 = detect_is64((const int*)ei);
        int e = b * 256 + tid;
        if (e < NE) {
            int d = edge_at(ei, NE + e, is64);
            g_rank[e] = atomicAdd(&g_counts[d], 1);
        }
    } else if (b < CPB_W1) {
        int idx = (b - CPB_COUNT) * 256 + tid;
        int n = idx >> 8, k = idx & 255;
        float w = (k < 128) ? W1l[(size_t)k * 256 + n]
                            : W1r[(size_t)(k - 128) * 256 + n];
        g_w1hi[(size_t)n * 256 + k] = __float2half_rn(w);
    } else if (b < CPB_W2) {
        int idx = (b - CPB_W1) * 256 + tid;
        int n = idx >> 8, k = idx & 255;
        float w = (n < 40) ? W2l[(size_t)k * 40 + n]
                           : W2r[(size_t)k * 40 + (n - 40)];
        g_w2hi[(size_t)n * 256 + k] = __float2half_rn(w);
    } else {
        int idx = (b - CPB_W2) * 256 + tid;
        if (idx >= NN * 32) return;
        int row = idx >> 5, c4 = idx & 31;
        float4 v = ((const float4*)x)[(size_t)row * 32 + c4];
        __half2 h0 = __floats2half2_rn(v.x, v.y);
        __half2 h1 = __floats2half2_rn(v.z, v.w);
        uint2 hi;
        hi.x = *(uint32_t*)&h0;
        hi.y = *(uint32_t*)&h1;
        *(uint2*)&g_a_hi[(size_t)row * 256 + 128 + c4 * 4] = hi;
    }
}

// ---------------- k_scan: fused hierarchical scan ----------------------------
__device__ __forceinline__ int block_excl_scan(int c, int t) {
    int lane = t & 31, w = t >> 5;
    int v = c;
#pragma unroll
    for (int off = 1; off < 32; off <<= 1) {
        int n = __shfl_up_sync(0xffffffffu, v, off);
        if (lane >= off) v += n;
    }
    __shared__ int ws[8];
    if (lane == 31) ws[w] = v;
    __syncthreads();
    if (w == 0 && lane < 8) {
        int s = ws[lane];
#pragma unroll
        for (int off = 1; off < 8; off <<= 1) {
            int n = __shfl_up_sync(0x000000ffu, s, off);
            if (lane >= off) s += n;
        }
        ws[lane] = s;
    }
    __syncthreads();
    return v - c + (w > 0 ? ws[w - 1] : 0);
}

__global__ void k_scan() {
    int b = blockIdx.x, tid = threadIdx.x;
    int i = b * 256 + tid;
    int c = (i < NN) ? g_counts[i] : 0;
    int e = block_excl_scan(c, tid);

    if (tid == 255) {
        g_bsum[b] = e + c;
        __threadfence();
        atomicAdd(&g_done1, 1);
    }
    if (tid == 0) {
        while (*(volatile int*)&g_done1 < NB) {}
    }
    __syncthreads();
    __threadfence();

    int v = (tid < b) ? g_bsum[tid] : 0;
    int lane = tid & 31, w = tid >> 5;
#pragma unroll
    for (int off = 16; off; off >>= 1) v += __shfl_xor_sync(0xffffffffu, v, off);
    __shared__ int rs[8];
    if (lane == 0) rs[w] = v;
    __syncthreads();
    __shared__ int pre;
    if (tid == 0) {
        int s = 0;
#pragma unroll
        for (int k = 0; k < 8; k++) s += rs[k];
        pre = s;
    }
    __syncthreads();

    if (i < NN) {
        g_offsets[i] = pre + e;
        g_invc[i]    = 1.0f / (float)(c > 1 ? c : 1);
    }
    if (b == NB - 1 && tid == 255) g_offsets[NN] = NE;

    if (tid == 0) {
        int t2 = atomicAdd(&g_done2, 1);
        if (t2 == NB - 1) { g_done1 = 0; g_done2 = 0; }
    }
}

// ---------------- k_scatter: atomic-free via precomputed rank ----------------
__global__ void k_scatter(const void* __restrict__ ei) {
    int is64 = detect_is64((const int*)ei);
    int e = blockIdx.x * blockDim.x + threadIdx.x;
    if (e < NE) {
        int s = edge_at(ei, e, is64);
        int d = edge_at(ei, NE + e, is64);
        g_esrc[g_offsets[d] + g_rank[e]] = s;
    }
}

// ---------------- layer-1 aggregation: unroll-4 depth-2 HADD2 tree -----------
__global__ void k_agg1() {
    int warp = (blockIdx.x * blockDim.x + threadIdx.x) >> 5;
    if (warp >= NN) return;
    int lane = threadIdx.x & 31;
    int beg = g_offsets[warp], end = g_offsets[warp + 1];
    float4 acc = make_float4(0.f, 0.f, 0.f, 0.f);
    size_t lo = 128 + lane * 4;
    int e = beg;
    for (; e + 3 < end; e += 4) {
        int s0 = g_esrc[e];
        int s1 = g_esrc[e + 1];
        int s2 = g_esrc[e + 2];
        int s3 = g_esrc[e + 3];
        uint2 u0 = *(const uint2*)&g_a_hi[(size_t)s0 * 256 + lo];
        uint2 u1 = *(const uint2*)&g_a_hi[(size_t)s1 * 256 + lo];
        uint2 u2 = *(const uint2*)&g_a_hi[(size_t)s2 * 256 + lo];
        uint2 u3 = *(const uint2*)&g_a_hi[(size_t)s3 * 256 + lo];
        __half2 a01 = __hadd2(*(__half2*)&u0.x, *(__half2*)&u1.x);
        __half2 b01 = __hadd2(*(__half2*)&u0.y, *(__half2*)&u1.y);
        __half2 a23 = __hadd2(*(__half2*)&u2.x, *(__half2*)&u3.x);
        __half2 b23 = __hadd2(*(__half2*)&u2.y, *(__half2*)&u3.y);
        float2 f0 = __half22float2(__hadd2(a01, a23));
        float2 f1 = __half22float2(__hadd2(b01, b23));
        acc.x += f0.x; acc.y += f0.y; acc.z += f1.x; acc.w += f1.y;
    }
    for (; e < end; e++) {
        int s0 = g_esrc[e];
        uint2 u0 = *(const uint2*)&g_a_hi[(size_t)s0 * 256 + lo];
        float2 f0 = __half22float2(*(__half2*)&u0.x);
        float2 f1 = __half22float2(*(__half2*)&u0.y);
        acc.x += f0.x; acc.y += f0.y; acc.z += f1.x; acc.w += f1.y;
    }
    float iv = g_invc[warp];
    __half2 h0 = __floats2half2_rn(acc.x * iv, acc.y * iv);
    __half2 h1 = __floats2half2_rn(acc.z * iv, acc.w * iv);
    uint2 hi;
    hi.x = *(uint32_t*)&h0;
    hi.y = *(uint32_t*)&h1;
    *(uint2*)&g_a_hi[(size_t)warp * 256 + lane * 4] = hi;
}

// ---------------- MEGA kernel: gemm1 (BN=256) + gemm2 fused, pure fp16 -------
#define MH_HI   0
#define MB_A_HI 0
#define MB_B_HI 16384
#define MSTG    65536
#define MBUFSZ  49152
#define MB2_HI  65536
#define MB2_CH  11264          // 88 rows * 128B per chunk
#define DYN_SMEMM 163840

__global__ void __launch_bounds__(512, 1) k_mega(const float* __restrict__ b1,
                                                 const float* __restrict__ b2) {
    extern __shared__ char dsm[];
    int tid = threadIdx.x;
    int wid = tid >> 5;          // 0..15
    int lane = tid & 31;
    int bm = blockIdx.x * 128;
    uint32_t dynb = smem_u32(dsm);

    int warp_m = (wid & 3) * 32;
    int warp_n = (wid >> 2) * 64;

    uint32_t offA[2][4], offB[4][4];
    {
        int mat = lane >> 3, rr = lane & 7;
#pragma unroll
        for (int i = 0; i < 2; i++)
#pragma unroll
            for (int j = 0; j < 4; j++) {
                int row = warp_m + i * 16 + ((mat & 1) << 3) + rr;
                int kb  = j * 16 + ((mat >> 1) << 3);
                offA[i][j] = SW128(row * 128 + kb * 2);
            }
#pragma unroll
        for (int q = 0; q < 4; q++)
#pragma unroll
            for (int j = 0; j < 4; j++) {
                int n  = warp_n + q * 16 + ((mat & 2) << 2) + rr;
                int kb = j * 16 + ((mat & 1) << 3);
                offB[q][j] = SW128(n * 128 + kb * 2);
            }
    }

    float acc[2][8][4];
#pragma unroll
    for (int i = 0; i < 2; i++)
#pragma unroll
        for (int jn = 0; jn < 8; jn++)
#pragma unroll
            for (int t = 0; t < 4; t++) acc[i][jn][t] = 0.f;

#define STAGEM(K0, BUFO) do {                                                      \
    _Pragma("unroll")                                                              \
    for (int it = 0; it < 2; it++) {                                               \
        int idx = tid + it * 512;                                                  \
        int row = idx >> 3, seg = idx & 7;                                         \
        int grow = bm + row;                                                       \
        int cl = grow < NN ? grow : (NN - 1);                                      \
        int sz = grow < NN ? 16 : 0;                                               \
        size_t boff = ((size_t)cl * 256 + (K0) + seg * 8) * 2;                     \
        int so = SW128(row * 128 + seg * 16);                                      \
        cp_async16(dynb + (BUFO) + MB_A_HI + so, (const char*)g_a_hi + boff, sz);  \
    }                                                                              \
    _Pragma("unroll")                                                              \
    for (int it = 0; it < 4; it++) {                                               \
        int idx = tid + it * 512;                                                  \
        int row = idx >> 3, seg = idx & 7;                                         \
        size_t boff = ((size_t)row * 256 + (K0) + seg * 8) * 2;                    \
        int so = SW128(row * 128 + seg * 16);                                      \
        cp_async16(dynb + (BUFO) + MB_B_HI + so, (const char*)g_w1hi + boff, 16);  \
    }                                                                              \
} while (0)

    STAGEM(0, MSTG);            CP_COMMIT();
    STAGEM(64, MSTG + MBUFSZ);  CP_COMMIT();

    for (int kc = 0; kc < 4; kc++) {
        uint32_t bufo = MSTG + ((kc & 1) ? MBUFSZ : 0);
        CP_WAIT1();
        __syncthreads();
#pragma unroll
        for (int j = 0; j < 4; j++) {
            uint32_t ah[2][4];
#pragma unroll
            for (int i = 0; i < 2; i++)
                LDSM4(ah[i], dynb + bufo + MB_A_HI + offA[i][j]);
#pragma unroll
            for (int q = 0; q < 4; q++) {
                uint32_t bh[4];
                LDSM4(bh, dynb + bufo + MB_B_HI + offB[q][j]);
#pragma unroll
                for (int i = 0; i < 2; i++)
#pragma unroll
                    for (int hsel = 0; hsel < 2; hsel++) {
                        int jn = q * 2 + hsel;
                        mma16816(acc[i][jn], ah[i], bh[hsel * 2], bh[hsel * 2 + 1]);
                    }
            }
        }
        __syncthreads();
        if (kc < 2) STAGEM((kc + 2) * 64, bufo);
        CP_COMMIT();
    }
#undef STAGEM

    // ===== phase 1 epilogue: h -> smem fp16, stage W2 into dead staging area =
    {
        if (tid < 256) {
            int kcz = tid >> 6, q4 = tid & 63;
            *(uint4*)(dsm + MB2_HI + kcz * MB2_CH + 80 * 128 + q4 * 16) =
                make_uint4(0, 0, 0, 0);
        }
#pragma unroll
        for (int it = 0; it < 5; it++) {
            int idx = tid + it * 512;
            int kc2 = idx / 640;
            int rr2 = idx - kc2 * 640;
            int row = rr2 >> 3, seg = rr2 & 7;
            const char* src = (const char*)g_w2hi
                              + ((size_t)row * 256 + kc2 * 64 + seg * 8) * 2;
            uint32_t dst = dynb + MB2_HI + kc2 * MB2_CH
                           + SW128(row * 128 + seg * 16);
            cp_async16(dst, src, 16);
        }
        CP_COMMIT();
    }

    {
        int r0l = warp_m + (lane >> 2);
        int c0l = warp_n + 2 * (lane & 3);
#pragma unroll
        for (int i = 0; i < 2; i++) {
#pragma unroll
            for (int jn = 0; jn < 8; jn++) {
                int col = c0l + jn * 8;
                int kc = col >> 6, kin = col & 63;
                float bx = b1[col], by = b1[col + 1];
                {
                    int r = r0l + i * 16;
                    float vx = acc[i][jn][0] + bx; vx = vx > 0.f ? vx : 0.f;
                    float vy = acc[i][jn][1] + by; vy = vy > 0.f ? vy : 0.f;
                    __half2 h = __floats2half2_rn(vx, vy);
                    int so = kc * 16384 + SW128(r * 128 + kin * 2);
                    *(uint32_t*)(dsm + MH_HI + so) = *(uint32_t*)&h;
                }
                {
                    int r = r0l + i * 16 + 8;
                    float vx = acc[i][jn][2] + bx; vx = vx > 0.f ? vx : 0.f;
                    float vy = acc[i][jn][3] + by; vy = vy > 0.f ? vy : 0.f;
                    __half2 h = __floats2half2_rn(vx, vy);
                    int so = kc * 16384 + SW128(r * 128 + kin * 2);
                    *(uint32_t*)(dsm + MH_HI + so) = *(uint32_t*)&h;
                }
            }
        }
    }
    CP_WAIT0();
    __syncthreads();

    // ===== phase 2: gemm2 from smem. warp tile 16x40, 8x2 warps ==============
    int warp_m2 = (wid & 7) * 16;
    int warp_n2 = (wid >> 3) * 40;

    uint32_t offA2[4], offB2[3][4];
    {
        int mat = lane >> 3, rr = lane & 7;
#pragma unroll
        for (int jj = 0; jj < 4; jj++) {
            int row = warp_m2 + ((mat & 1) << 3) + rr;
            int kb  = jj * 16 + ((mat >> 1) << 3);
            offA2[jj] = SW128(row * 128 + kb * 2);
        }
#pragma unroll
        for (int q = 0; q < 3; q++)
#pragma unroll
            for (int jj = 0; jj < 4; jj++) {
                int n  = warp_n2 + q * 16 + ((mat & 2) << 2) + rr;
                int kb = jj * 16 + ((mat & 1) << 3);
                offB2[q][jj] = SW128(n * 128 + kb * 2);
            }
    }

    float acc2[5][4];
#pragma unroll
    for (int jn = 0; jn < 5; jn++)
#pragma unroll
        for (int t = 0; t < 4; t++) acc2[jn][t] = 0.f;

#pragma unroll
    for (int j = 0; j < 16; j++) {
        int kc = j >> 2, jj = j & 3;
        uint32_t ah[4];
        LDSM4(ah, dynb + MH_HI + kc * 16384 + offA2[jj]);
#pragma unroll
        for (int q = 0; q < 3; q++) {
            uint32_t bh[4];
            LDSM4(bh, dynb + MB2_HI + kc * MB2_CH + offB2[q][jj]);
#pragma unroll
            for (int h2 = 0; h2 < 2; h2++) {
                int jn = q * 2 + h2;
                if (jn < 5)
                    mma16816(acc2[jn], ah, bh[h2 * 2], bh[h2 * 2 + 1]);
            }
        }
    }

    // epilogue: cols<40 -> p (fp16, no bias), cols>=40 -> r (fp32, +b2)
    int r0 = bm + warp_m2 + (lane >> 2);
    int c0 = warp_n2 + 2 * (lane & 3);
#pragma unroll
    for (int jn = 0; jn < 5; jn++) {
        int col = c0 + jn * 8;
#pragma unroll
        for (int half = 0; half < 2; half++) {
            int row = r0 + half * 8;
            if (row < NN) {
                float vx = acc2[jn][half * 2 + 0];
                float vy = acc2[jn][half * 2 + 1];
                if (col < 40) {
                    __half2 hp = __floats2half2_rn(vx, vy);
                    *(__half2*)&g_p[(size_t)row * 40 + col] = hp;
                } else {
                    float2 v = make_float2(vx + b2[col - 40], vy + b2[col - 39]);
                    *(float2*)&g_r[(size_t)row * 40 + (col - 40)] = v;
                }
            }
        }
    }
}

// ---------------- layer-2 aggregation + log_softmax + counts reset -----------
__global__ void k_agg2_lsm(float* __restrict__ out) {
    if (blockIdx.x < NB) {
        int ci = blockIdx.x * 256 + threadIdx.x;
        if (ci < NN) g_counts[ci] = 0;
    }

    int warp = (blockIdx.x * blockDim.x + threadIdx.x) >> 5;
    if (warp >= NN) return;
    int lane = threadIdx.x & 31;
    int beg = g_offsets[warp], end = g_offsets[warp + 1];
    bool h1 = lane < 8;
    float a0 = 0.f, a1 = 0.f;
    int e = beg;
    for (; e + 1 < end; e += 2) {
        int s0 = g_esrc[e];
        int s1 = g_esrc[e + 1];
        const __half* p0 = g_p + (size_t)s0 * 40;
        const __half* p1 = g_p + (size_t)s1 * 40;
        float v00 = __half2float(p0[lane]);
        float v01 = __half2float(p1[lane]);
        a0 += v00 + v01;
        if (h1) {
            float v10 = __half2float(p0[32 + lane]);
            float v11 = __half2float(p1[32 + lane]);
            a1 += v10 + v11;
        }
    }
    if (e < end) {
        int s0 = g_esrc[e];
        const __half* ps = g_p + (size_t)s0 * 40;
        a0 += __half2float(ps[lane]);
        if (h1) a1 += __half2float(ps[32 + lane]);
    }
    float iv = g_invc[warp];
    float v0 = a0 * iv + g_r[(size_t)warp * 40 + lane];
    float v1 = h1 ? (a1 * iv + g_r[(size_t)warp * 40 + 32 + lane]) : -3.0e38f;

    float m = fmaxf(v0, v1);
#pragma unroll
    for (int off = 16; off; off >>= 1)
        m = fmaxf(m, __shfl_xor_sync(0xffffffffu, m, off));
    float ssum = expf(v0 - m) + (h1 ? expf(v1 - m) : 0.f);
#pragma unroll
    for (int off = 16; off; off >>= 1)
        ssum += __shfl_xor_sync(0xffffffffu, ssum, off);
    float lse = m + logf(ssum);

    out[(size_t)warp * 40 + lane] = v0 - lse;
    if (h1) out[(size_t)warp * 40 + 32 + lane] = v1 - lse;
}

// ---------------- launch -----------------------------------------------------
extern "C" void kernel_launch(void* const* d_in, const int* in_sizes, int n_in,
                              void* d_out, int out_size) {
    const float* x   = (const float*)d_in[0];
    const void*  ei  = d_in[1];
    const float* W1l = (const float*)d_in[2];
    const float* W1r = (const float*)d_in[3];
    const float* b1  = (const float*)d_in[4];
    const float* W2l = (const float*)d_in[5];
    const float* W2r = (const float*)d_in[6];
    const float* b2  = (const float*)d_in[7];
    float* out = (float*)d_out;

    cudaFuncSetAttribute(k_mega, cudaFuncAttributeMaxDynamicSharedMemorySize,
                         DYN_SMEMM);

    k_count_prep<<<CPB_X, 256>>>(ei, W1l, W1r, W2l, W2r, x);
    k_scan<<<NB, 256>>>();
    k_scatter<<<(NE + 255) / 256, 256>>>(ei);
    k_agg1<<<(NN + 7) / 8, 256>>>();
    k_mega<<<(NN + 127) / 128, 512, DYN_SMEMM>>>(b1, b2);
    k_agg2_lsm<<<(NN + 7) / 8, 256>>>(out);
}